// round 1
// baseline (speedup 1.0000x reference)
#include <cuda_runtime.h>
#include <math.h>

// ---------------------------------------------------------------------------
// Problem constants (fixed by the dataset)
// ---------------------------------------------------------------------------
#define NNODE 100000
#define EDGES 800000
#define DIN   128
#define HDIM  256

// ---------------------------------------------------------------------------
// Scratch: __device__ globals (no allocation allowed in kernel_launch)
// ---------------------------------------------------------------------------
__device__ float g_hu [(size_t)NNODE * HDIM];
__device__ float g_hi [(size_t)NNODE * HDIM];
__device__ float g_tu [(size_t)NNODE * HDIM];
__device__ float g_ti [(size_t)NNODE * HDIM];
__device__ float g_agg[(size_t)NNODE * HDIM];
__device__ float g_invu[NNODE];
__device__ float g_invi[NNODE];
__device__ int   g_degu[NNODE];
__device__ int   g_degi[NNODE];

// ---------------------------------------------------------------------------
// Small helpers
// ---------------------------------------------------------------------------
__device__ __forceinline__ float gelu_f(float x) {
    // exact (erf) GELU, matching jax.nn.gelu(approximate=False)
    return 0.5f * x * (1.0f + erff(x * 0.70710678118654752f));
}

// ---------------------------------------------------------------------------
// Degree / inverse-degree kernels
// ---------------------------------------------------------------------------
__global__ void deg_kernel(const int* __restrict__ dst, int* __restrict__ deg, int nE) {
    int i = blockIdx.x * blockDim.x + threadIdx.x;
    if (i < nE) atomicAdd(&deg[dst[i]], 1);
}

__global__ void inv_kernel(const int* __restrict__ deg, float* __restrict__ inv, int n) {
    int i = blockIdx.x * blockDim.x + threadIdx.x;
    if (i < n) inv[i] = 1.0f / fmaxf((float)deg[i], 1.0f);
}

// ---------------------------------------------------------------------------
// Edge scatter: agg[dst] += h[src]   (one warp per edge, float4 reductions)
// ---------------------------------------------------------------------------
__global__ void __launch_bounds__(256)
scatter_kernel(const float* __restrict__ h, const int* __restrict__ src,
               const int* __restrict__ dst, float* __restrict__ agg, int nE)
{
    int gid  = blockIdx.x * blockDim.x + threadIdx.x;
    int e    = gid >> 5;
    int lane = gid & 31;
    if (e >= nE) return;
    int s = __ldg(&src[e]);
    int d = __ldg(&dst[e]);
    const float4* hp = reinterpret_cast<const float4*>(h + (size_t)s * HDIM) + lane * 2;
    float4*       ap = reinterpret_cast<float4*>(agg + (size_t)d * HDIM) + lane * 2;
    float4 v0 = hp[0];
    float4 v1 = hp[1];
    asm volatile("red.global.add.v4.f32 [%0], {%1,%2,%3,%4};"
                 :: "l"(ap), "f"(v0.x), "f"(v0.y), "f"(v0.z), "f"(v0.w) : "memory");
    asm volatile("red.global.add.v4.f32 [%0], {%1,%2,%3,%4};"
                 :: "l"(ap + 1), "f"(v1.x), "f"(v1.y), "f"(v1.z), "f"(v1.w) : "memory");
}

// ---------------------------------------------------------------------------
// Fused GEMM:
//   C[M,256] = EPI( A1(*scale1)@W1 (+ A2@W2) + bias )
//   EPI = 0 : exact GELU
//   EPI = 1 : LayerNorm(., lng, lnb), eps=1e-5
// Block tile: 64 rows x 256 cols (full width), 256 threads, KT=16.
// Thread (tx = tid&15, ty = tid>>4) owns rows ty*4..+3, cols {tx*4 + j*64}.
// ---------------------------------------------------------------------------
constexpr int TM = 64;
constexpr int KT = 16;

template<int K, bool HAS_A2, bool SCALE1, int EPI>
__global__ void __launch_bounds__(256, 2)
gemm_kernel(const float* __restrict__ A1, const float* __restrict__ scale1,
            const float* __restrict__ A2,
            const float* __restrict__ W1, const float* __restrict__ W2,
            const float* __restrict__ bias,
            const float* __restrict__ lng, const float* __restrict__ lnb,
            float* __restrict__ C, int M)
{
    __shared__ float a_s[KT][TM];
    __shared__ float w_s[KT][HDIM];

    const int tid  = threadIdx.x;
    const int tx   = tid & 15;
    const int ty   = tid >> 4;
    const int row0 = blockIdx.x * TM;

    float4 acc[4][4];
    #pragma unroll
    for (int i = 0; i < 4; i++)
        #pragma unroll
        for (int j = 0; j < 4; j++)
            acc[i][j] = make_float4(0.f, 0.f, 0.f, 0.f);

    const int ldr = tid >> 2;         // A-tile row 0..63
    const int ldk = (tid & 3) << 2;   // A-tile k   0,4,8,12

    #pragma unroll
    for (int ph = 0; ph < (HAS_A2 ? 2 : 1); ph++) {
        const float* __restrict__ A = (ph == 0) ? A1 : A2;
        const float* __restrict__ W = (ph == 0) ? W1 : W2;
        for (int k0 = 0; k0 < K; k0 += KT) {
            __syncthreads();
            // ---- A tile (64 x 16), stored transposed [k][row]
            {
                int gr = row0 + ldr;
                float4 v = make_float4(0.f, 0.f, 0.f, 0.f);
                if (gr < M) {
                    v = *reinterpret_cast<const float4*>(A + (size_t)gr * K + k0 + ldk);
                    if (SCALE1 && ph == 0) {
                        float s = scale1[gr];
                        v.x *= s; v.y *= s; v.z *= s; v.w *= s;
                    }
                }
                a_s[ldk + 0][ldr] = v.x;
                a_s[ldk + 1][ldr] = v.y;
                a_s[ldk + 2][ldr] = v.z;
                a_s[ldk + 3][ldr] = v.w;
            }
            // ---- W tile (16 x 256) = 1024 float4, 4 per thread
            #pragma unroll
            for (int t = 0; t < 4; t++) {
                int idx = tid + t * 256;
                int wr  = idx >> 6;
                int wc  = (idx & 63) << 2;
                *reinterpret_cast<float4*>(&w_s[wr][wc]) =
                    *reinterpret_cast<const float4*>(W + (size_t)(k0 + wr) * HDIM + wc);
            }
            __syncthreads();
            // ---- compute
            #pragma unroll
            for (int kk = 0; kk < KT; kk++) {
                float4 av = *reinterpret_cast<const float4*>(&a_s[kk][ty << 2]);
                float ar[4] = {av.x, av.y, av.z, av.w};
                #pragma unroll
                for (int j = 0; j < 4; j++) {
                    float4 wv = *reinterpret_cast<const float4*>(&w_s[kk][(tx << 2) + j * 64]);
                    #pragma unroll
                    for (int i = 0; i < 4; i++) {
                        acc[i][j].x = fmaf(ar[i], wv.x, acc[i][j].x);
                        acc[i][j].y = fmaf(ar[i], wv.y, acc[i][j].y);
                        acc[i][j].z = fmaf(ar[i], wv.z, acc[i][j].z);
                        acc[i][j].w = fmaf(ar[i], wv.w, acc[i][j].w);
                    }
                }
            }
        }
    }

    // ---- bias
    #pragma unroll
    for (int j = 0; j < 4; j++) {
        float4 b = *reinterpret_cast<const float4*>(bias + (tx << 2) + j * 64);
        #pragma unroll
        for (int i = 0; i < 4; i++) {
            acc[i][j].x += b.x; acc[i][j].y += b.y;
            acc[i][j].z += b.z; acc[i][j].w += b.w;
        }
    }

    if (EPI == 0) {
        // ---- GELU epilogue
        #pragma unroll
        for (int i = 0; i < 4; i++) {
            int gr = row0 + (ty << 2) + i;
            if (gr < M) {
                #pragma unroll
                for (int j = 0; j < 4; j++) {
                    float4 v = acc[i][j];
                    v.x = gelu_f(v.x); v.y = gelu_f(v.y);
                    v.z = gelu_f(v.z); v.w = gelu_f(v.w);
                    *reinterpret_cast<float4*>(C + (size_t)gr * HDIM + (tx << 2) + j * 64) = v;
                }
            }
        }
    } else {
        // ---- LayerNorm epilogue (16 lanes per row; lanes with same ty share gr)
        #pragma unroll
        for (int i = 0; i < 4; i++) {
            int gr = row0 + (ty << 2) + i;
            float s = 0.f;
            #pragma unroll
            for (int j = 0; j < 4; j++)
                s += acc[i][j].x + acc[i][j].y + acc[i][j].z + acc[i][j].w;
            #pragma unroll
            for (int m = 8; m > 0; m >>= 1) s += __shfl_xor_sync(0xffffffffu, s, m);
            float mu = s * (1.0f / 256.0f);

            float vs = 0.f;
            #pragma unroll
            for (int j = 0; j < 4; j++) {
                float dx = acc[i][j].x - mu, dy = acc[i][j].y - mu;
                float dz = acc[i][j].z - mu, dw = acc[i][j].w - mu;
                vs += dx * dx + dy * dy + dz * dz + dw * dw;
            }
            #pragma unroll
            for (int m = 8; m > 0; m >>= 1) vs += __shfl_xor_sync(0xffffffffu, vs, m);
            float rstd = rsqrtf(vs * (1.0f / 256.0f) + 1e-5f);

            if (gr < M) {
                #pragma unroll
                for (int j = 0; j < 4; j++) {
                    int c = (tx << 2) + j * 64;
                    float4 g  = *reinterpret_cast<const float4*>(lng + c);
                    float4 b2 = *reinterpret_cast<const float4*>(lnb + c);
                    float4 v;
                    v.x = (acc[i][j].x - mu) * rstd * g.x + b2.x;
                    v.y = (acc[i][j].y - mu) * rstd * g.y + b2.y;
                    v.z = (acc[i][j].z - mu) * rstd * g.z + b2.z;
                    v.w = (acc[i][j].w - mu) * rstd * g.w + b2.w;
                    *reinterpret_cast<float4*>(C + (size_t)gr * HDIM + c) = v;
                }
            }
        }
    }
}

// ---------------------------------------------------------------------------
// kernel_launch
// ---------------------------------------------------------------------------
extern "C" void kernel_launch(void* const* d_in, const int* in_sizes, int n_in,
                              void* d_out, int out_size)
{
    const float* x_user    = (const float*)d_in[0];
    const float* x_item    = (const float*)d_in[1];
    const int*   ei_ui_src = (const int*)  d_in[2];
    const int*   ei_ui_dst = (const int*)  d_in[3];
    const int*   ei_iu_src = (const int*)  d_in[4];
    const int*   ei_iu_dst = (const int*)  d_in[5];
    const float* lin_user_W = (const float*)d_in[6];
    const float* lin_user_b = (const float*)d_in[7];
    const float* lin_item_W = (const float*)d_in[8];
    const float* lin_item_b = (const float*)d_in[9];
    const float* c0_ui_Wl = (const float*)d_in[10];
    const float* c0_ui_bl = (const float*)d_in[11];
    const float* c0_ui_Wr = (const float*)d_in[12];
    const float* c0_iu_Wl = (const float*)d_in[13];
    const float* c0_iu_bl = (const float*)d_in[14];
    const float* c0_iu_Wr = (const float*)d_in[15];
    const float* c1_ui_Wl = (const float*)d_in[16];
    const float* c1_ui_bl = (const float*)d_in[17];
    const float* c1_ui_Wr = (const float*)d_in[18];
    const float* c1_iu_Wl = (const float*)d_in[19];
    const float* c1_iu_bl = (const float*)d_in[20];
    const float* c1_iu_Wr = (const float*)d_in[21];
    const float* out_user_W = (const float*)d_in[22];
    const float* out_user_b = (const float*)d_in[23];
    const float* out_item_W = (const float*)d_in[24];
    const float* out_item_b = (const float*)d_in[25];
    const float* ln_user_g  = (const float*)d_in[26];
    const float* ln_user_b2 = (const float*)d_in[27];
    const float* ln_item_g  = (const float*)d_in[28];
    const float* ln_item_b2 = (const float*)d_in[29];

    float* out = (float*)d_out;

    const int nE = in_sizes[2];        // 800000
    const int M  = NNODE;              // both node sets are 100000

    float *hu, *hi, *tu, *ti, *agg, *invu, *invi;
    int *degu, *degi;
    cudaGetSymbolAddress((void**)&hu,   g_hu);
    cudaGetSymbolAddress((void**)&hi,   g_hi);
    cudaGetSymbolAddress((void**)&tu,   g_tu);
    cudaGetSymbolAddress((void**)&ti,   g_ti);
    cudaGetSymbolAddress((void**)&agg,  g_agg);
    cudaGetSymbolAddress((void**)&invu, g_invu);
    cudaGetSymbolAddress((void**)&invi, g_invi);
    cudaGetSymbolAddress((void**)&degu, g_degu);
    cudaGetSymbolAddress((void**)&degi, g_degi);

    const size_t HB = (size_t)M * HDIM * sizeof(float);

    dim3 blk(256);
    dim3 grid_gemm((M + TM - 1) / TM);
    dim3 grid_edge((nE + 255) / 256);
    dim3 grid_node((M + 255) / 256);
    dim3 grid_scat(((size_t)nE * 32 + 255) / 256);

    // -- degrees (depend only on edge lists; recomputed every call) --
    cudaMemsetAsync(degu, 0, M * sizeof(int));
    cudaMemsetAsync(degi, 0, M * sizeof(int));
    deg_kernel<<<grid_edge, blk>>>(ei_ui_dst, degi, nE);
    deg_kernel<<<grid_edge, blk>>>(ei_iu_dst, degu, nE);
    inv_kernel<<<grid_node, blk>>>(degi, invi, M);
    inv_kernel<<<grid_node, blk>>>(degu, invu, M);

    // -- input projections + GELU --
    gemm_kernel<DIN, false, false, 0><<<grid_gemm, blk>>>(
        x_user, nullptr, nullptr, lin_user_W, nullptr, lin_user_b, nullptr, nullptr, hu, M);
    gemm_kernel<DIN, false, false, 0><<<grid_gemm, blk>>>(
        x_item, nullptr, nullptr, lin_item_W, nullptr, lin_item_b, nullptr, nullptr, hi, M);

    // -- layer 0, item dst: agg(h_u over ui edges) --
    cudaMemsetAsync(agg, 0, HB);
    scatter_kernel<<<grid_scat, blk>>>(hu, ei_ui_src, ei_ui_dst, agg, nE);
    gemm_kernel<HDIM, true, true, 0><<<grid_gemm, blk>>>(
        agg, invi, hi, c0_ui_Wl, c0_ui_Wr, c0_ui_bl, nullptr, nullptr, ti, M);

    // -- layer 0, user dst: agg(h_i over iu edges) --
    cudaMemsetAsync(agg, 0, HB);
    scatter_kernel<<<grid_scat, blk>>>(hi, ei_iu_src, ei_iu_dst, agg, nE);
    gemm_kernel<HDIM, true, true, 0><<<grid_gemm, blk>>>(
        agg, invu, hu, c0_iu_Wl, c0_iu_Wr, c0_iu_bl, nullptr, nullptr, tu, M);

    // -- layer 1, item dst (h now in tu/ti) --
    cudaMemsetAsync(agg, 0, HB);
    scatter_kernel<<<grid_scat, blk>>>(tu, ei_ui_src, ei_ui_dst, agg, nE);
    gemm_kernel<HDIM, true, true, 0><<<grid_gemm, blk>>>(
        agg, invi, ti, c1_ui_Wl, c1_ui_Wr, c1_ui_bl, nullptr, nullptr, hi, M);

    // -- layer 1, user dst --
    cudaMemsetAsync(agg, 0, HB);
    scatter_kernel<<<grid_scat, blk>>>(ti, ei_iu_src, ei_iu_dst, agg, nE);
    gemm_kernel<HDIM, true, true, 0><<<grid_gemm, blk>>>(
        agg, invu, tu, c1_iu_Wl, c1_iu_Wr, c1_iu_bl, nullptr, nullptr, hu, M);

    // -- heads: linear + LayerNorm --
    gemm_kernel<HDIM, false, false, 1><<<grid_gemm, blk>>>(
        hu, nullptr, nullptr, out_user_W, nullptr, out_user_b, ln_user_g, ln_user_b2,
        out, M);
    gemm_kernel<HDIM, false, false, 1><<<grid_gemm, blk>>>(
        hi, nullptr, nullptr, out_item_W, nullptr, out_item_b, ln_item_g, ln_item_b2,
        out + (size_t)M * HDIM, M);
}

// round 3
// speedup vs baseline: 1.1646x; 1.1646x over previous
#include <cuda_runtime.h>
#include <math.h>
#include <stdint.h>

// ---------------------------------------------------------------------------
// Problem constants (fixed by the dataset)
// ---------------------------------------------------------------------------
#define NNODE 100000
#define EDGES 800000
#define DIN   128
#define HDIM  256

// ---------------------------------------------------------------------------
// Scratch: __device__ globals (no allocation allowed in kernel_launch)
// ---------------------------------------------------------------------------
__device__ float g_hu [(size_t)NNODE * HDIM];
__device__ float g_hi [(size_t)NNODE * HDIM];
__device__ float g_tu [(size_t)NNODE * HDIM];
__device__ float g_ti [(size_t)NNODE * HDIM];
__device__ float g_agg[(size_t)NNODE * HDIM];
__device__ float g_invu[NNODE];
__device__ float g_invi[NNODE];
__device__ int   g_degu[NNODE];
__device__ int   g_degi[NNODE];

// ---------------------------------------------------------------------------
// Helpers
// ---------------------------------------------------------------------------
__device__ __forceinline__ float gelu_f(float x) {
    return 0.5f * x * (1.0f + erff(x * 0.70710678118654752f));
}

__device__ __forceinline__ float to_tf32(float x) {
    float r;
    asm("cvt.rna.tf32.f32 %0, %1;" : "=f"(r) : "f"(x));
    return r;
}

__device__ __forceinline__ void mma_tf32(float& d0, float& d1, float& d2, float& d3,
                                         uint32_t a0, uint32_t a1, uint32_t a2, uint32_t a3,
                                         uint32_t b0, uint32_t b1)
{
    asm volatile(
        "mma.sync.aligned.m16n8k8.row.col.f32.tf32.tf32.f32 "
        "{%0,%1,%2,%3}, {%4,%5,%6,%7}, {%8,%9}, {%0,%1,%2,%3};"
        : "+f"(d0), "+f"(d1), "+f"(d2), "+f"(d3)
        : "r"(a0), "r"(a1), "r"(a2), "r"(a3), "r"(b0), "r"(b1));
}

// ---------------------------------------------------------------------------
// Degree / inverse-degree kernels
// ---------------------------------------------------------------------------
__global__ void deg_kernel(const int* __restrict__ dst, int* __restrict__ deg, int nE) {
    int i = blockIdx.x * blockDim.x + threadIdx.x;
    if (i < nE) atomicAdd(&deg[dst[i]], 1);
}

__global__ void inv_kernel(const int* __restrict__ deg, float* __restrict__ inv, int n) {
    int i = blockIdx.x * blockDim.x + threadIdx.x;
    if (i < n) inv[i] = 1.0f / fmaxf((float)deg[i], 1.0f);
}

// ---------------------------------------------------------------------------
// Edge scatter: agg[dst] += h[src]   (one warp per edge, float4 reductions)
// ---------------------------------------------------------------------------
__global__ void __launch_bounds__(256)
scatter_kernel(const float* __restrict__ h, const int* __restrict__ src,
               const int* __restrict__ dst, float* __restrict__ agg, int nE)
{
    int gid  = blockIdx.x * blockDim.x + threadIdx.x;
    int e    = gid >> 5;
    int lane = gid & 31;
    if (e >= nE) return;
    int s = __ldg(&src[e]);
    int d = __ldg(&dst[e]);
    const float4* hp = reinterpret_cast<const float4*>(h + (size_t)s * HDIM) + lane * 2;
    float4*       ap = reinterpret_cast<float4*>(agg + (size_t)d * HDIM) + lane * 2;
    float4 v0 = hp[0];
    float4 v1 = hp[1];
    asm volatile("red.global.add.v4.f32 [%0], {%1,%2,%3,%4};"
                 :: "l"(ap), "f"(v0.x), "f"(v0.y), "f"(v0.z), "f"(v0.w) : "memory");
    asm volatile("red.global.add.v4.f32 [%0], {%1,%2,%3,%4};"
                 :: "l"(ap + 1), "f"(v1.x), "f"(v1.y), "f"(v1.z), "f"(v1.w) : "memory");
}

// ---------------------------------------------------------------------------
// Standalone in-place LayerNorm over 256 cols, one warp per row.
// ---------------------------------------------------------------------------
__global__ void __launch_bounds__(256)
ln_kernel(float* __restrict__ x, const float* __restrict__ g,
          const float* __restrict__ b, int M)
{
    int row  = blockIdx.x * 8 + (threadIdx.x >> 5);
    int lane = threadIdx.x & 31;
    if (row >= M) return;
    float* p = x + (size_t)row * HDIM + lane * 8;
    float4 v0 = *reinterpret_cast<const float4*>(p);
    float4 v1 = *reinterpret_cast<const float4*>(p + 4);
    float s  = v0.x + v0.y + v0.z + v0.w + v1.x + v1.y + v1.z + v1.w;
    float sq = v0.x*v0.x + v0.y*v0.y + v0.z*v0.z + v0.w*v0.w
             + v1.x*v1.x + v1.y*v1.y + v1.z*v1.z + v1.w*v1.w;
    #pragma unroll
    for (int m = 16; m > 0; m >>= 1) {
        s  += __shfl_xor_sync(0xffffffffu, s,  m);
        sq += __shfl_xor_sync(0xffffffffu, sq, m);
    }
    float mu   = s * (1.0f / 256.0f);
    float var  = sq * (1.0f / 256.0f) - mu * mu;
    float rstd = rsqrtf(var + 1e-5f);
    float4 g0 = *reinterpret_cast<const float4*>(g + lane * 8);
    float4 g1 = *reinterpret_cast<const float4*>(g + lane * 8 + 4);
    float4 b0 = *reinterpret_cast<const float4*>(b + lane * 8);
    float4 b1 = *reinterpret_cast<const float4*>(b + lane * 8 + 4);
    float4 o0, o1;
    o0.x = (v0.x - mu) * rstd * g0.x + b0.x;
    o0.y = (v0.y - mu) * rstd * g0.y + b0.y;
    o0.z = (v0.z - mu) * rstd * g0.z + b0.z;
    o0.w = (v0.w - mu) * rstd * g0.w + b0.w;
    o1.x = (v1.x - mu) * rstd * g1.x + b1.x;
    o1.y = (v1.y - mu) * rstd * g1.y + b1.y;
    o1.z = (v1.z - mu) * rstd * g1.z + b1.z;
    o1.w = (v1.w - mu) * rstd * g1.w + b1.w;
    *reinterpret_cast<float4*>(p)     = o0;
    *reinterpret_cast<float4*>(p + 4) = o1;
}

// ---------------------------------------------------------------------------
// Tensor-core tf32 GEMM:
//   C[M,256] = EPI( A1(*scale1)@W1 (+ A2@W2) + bias )
//   EPI = 0 : exact GELU       EPI = 1 : none (bias only)
//
// Block tile 128x128 (grid.y = 2 covers N=256). BK = 32. 8 warps = 2(M) x 4(N),
// warp tile 64x32 -> 4 x 4 m16n8k8 tiles.
// Smem: A [m][k] ld=36, B [k][n] ld=136 (both conflict-free for STS.128 + frag LDS).
// ---------------------------------------------------------------------------
constexpr int BM  = 128;
constexpr int BK  = 32;
constexpr int LDA = 36;
constexpr int LDB = 136;

template<int K, bool HAS_A2, bool SCALE1, int EPI>
__global__ void __launch_bounds__(256)
gemm_tc(const float* __restrict__ A1, const float* __restrict__ scale1,
        const float* __restrict__ A2,
        const float* __restrict__ W1, const float* __restrict__ W2,
        const float* __restrict__ bias,
        float* __restrict__ C, int M)
{
    __shared__ float a_s[BM * LDA];
    __shared__ float b_s[BK * LDB];

    const int tid  = threadIdx.x;
    const int lane = tid & 31;
    const int wid  = tid >> 5;
    const int wm   = wid >> 2;
    const int wn   = wid & 3;
    const int lq   = lane >> 2;
    const int lr   = lane & 3;
    const int row0 = blockIdx.x * BM;
    const int ncol0 = blockIdx.y * 128;

    float d[4][4][4];
    #pragma unroll
    for (int i = 0; i < 4; i++)
        #pragma unroll
        for (int j = 0; j < 4; j++)
            #pragma unroll
            for (int q = 0; q < 4; q++)
                d[i][j][q] = 0.f;

    #pragma unroll
    for (int ph = 0; ph < (HAS_A2 ? 2 : 1); ph++) {
        const float* __restrict__ A = (ph == 0) ? A1 : A2;
        const float* __restrict__ W = (ph == 0) ? W1 : W2;
        #pragma unroll 1
        for (int k0 = 0; k0 < K; k0 += BK) {
            __syncthreads();
            // ---- A tile: 128 x 32
            #pragma unroll
            for (int u = 0; u < 4; u++) {
                int f  = u * 256 + tid;
                int r  = f >> 3;
                int c4 = (f & 7) << 2;
                int gr = row0 + r;
                float4 v = make_float4(0.f, 0.f, 0.f, 0.f);
                if (gr < M) {
                    v = *reinterpret_cast<const float4*>(A + (size_t)gr * K + k0 + c4);
                    if (SCALE1 && ph == 0) {
                        float s = __ldg(&scale1[gr]);
                        v.x *= s; v.y *= s; v.z *= s; v.w *= s;
                    }
                    v.x = to_tf32(v.x); v.y = to_tf32(v.y);
                    v.z = to_tf32(v.z); v.w = to_tf32(v.w);
                }
                *reinterpret_cast<float4*>(&a_s[r * LDA + c4]) = v;
            }
            // ---- B tile: 32 x 128
            #pragma unroll
            for (int u = 0; u < 4; u++) {
                int f  = u * 256 + tid;
                int kr = f >> 5;
                int c4 = (f & 31) << 2;
                float4 v = *reinterpret_cast<const float4*>(
                    W + (size_t)(k0 + kr) * HDIM + ncol0 + c4);
                v.x = to_tf32(v.x); v.y = to_tf32(v.y);
                v.z = to_tf32(v.z); v.w = to_tf32(v.w);
                *reinterpret_cast<float4*>(&b_s[kr * LDB + c4]) = v;
            }
            __syncthreads();
            // ---- compute
            #pragma unroll
            for (int ks = 0; ks < 4; ks++) {
                uint32_t af[4][4];
                #pragma unroll
                for (int i = 0; i < 4; i++) {
                    int rm = wm * 64 + i * 16 + lq;
                    af[i][0] = __float_as_uint(a_s[rm * LDA + ks * 8 + lr]);
                    af[i][1] = __float_as_uint(a_s[(rm + 8) * LDA + ks * 8 + lr]);
                    af[i][2] = __float_as_uint(a_s[rm * LDA + ks * 8 + lr + 4]);
                    af[i][3] = __float_as_uint(a_s[(rm + 8) * LDA + ks * 8 + lr + 4]);
                }
                uint32_t bf[4][2];
                #pragma unroll
                for (int j = 0; j < 4; j++) {
                    int cb = wn * 32 + j * 8 + lq;
                    bf[j][0] = __float_as_uint(b_s[(ks * 8 + lr) * LDB + cb]);
                    bf[j][1] = __float_as_uint(b_s[(ks * 8 + lr + 4) * LDB + cb]);
                }
                #pragma unroll
                for (int i = 0; i < 4; i++)
                    #pragma unroll
                    for (int j = 0; j < 4; j++)
                        mma_tf32(d[i][j][0], d[i][j][1], d[i][j][2], d[i][j][3],
                                 af[i][0], af[i][1], af[i][2], af[i][3],
                                 bf[j][0], bf[j][1]);
            }
        }
    }

    // ---- bias
    #pragma unroll
    for (int j = 0; j < 4; j++) {
        float2 b = *reinterpret_cast<const float2*>(bias + ncol0 + wn * 32 + j * 8 + 2 * lr);
        #pragma unroll
        for (int i = 0; i < 4; i++) {
            d[i][j][0] += b.x; d[i][j][1] += b.y;
            d[i][j][2] += b.x; d[i][j][3] += b.y;
        }
    }

    const int cbase = ncol0 + wn * 32;

    // ---- store (optionally GELU)
    #pragma unroll
    for (int i = 0; i < 4; i++) {
        #pragma unroll
        for (int rr = 0; rr < 2; rr++) {
            int gr = row0 + wm * 64 + i * 16 + lq + rr * 8;
            if (gr < M) {
                #pragma unroll
                for (int j = 0; j < 4; j++) {
                    float2 v;
                    if (EPI == 0) {
                        v.x = gelu_f(d[i][j][rr * 2 + 0]);
                        v.y = gelu_f(d[i][j][rr * 2 + 1]);
                    } else {
                        v.x = d[i][j][rr * 2 + 0];
                        v.y = d[i][j][rr * 2 + 1];
                    }
                    *reinterpret_cast<float2*>(
                        C + (size_t)gr * HDIM + cbase + j * 8 + 2 * lr) = v;
                }
            }
        }
    }
}

// ---------------------------------------------------------------------------
// kernel_launch
// ---------------------------------------------------------------------------
extern "C" void kernel_launch(void* const* d_in, const int* in_sizes, int n_in,
                              void* d_out, int out_size)
{
    const float* x_user    = (const float*)d_in[0];
    const float* x_item    = (const float*)d_in[1];
    const int*   ei_ui_src = (const int*)  d_in[2];
    const int*   ei_ui_dst = (const int*)  d_in[3];
    const int*   ei_iu_src = (const int*)  d_in[4];
    const int*   ei_iu_dst = (const int*)  d_in[5];
    const float* lin_user_W = (const float*)d_in[6];
    const float* lin_user_b = (const float*)d_in[7];
    const float* lin_item_W = (const float*)d_in[8];
    const float* lin_item_b = (const float*)d_in[9];
    const float* c0_ui_Wl = (const float*)d_in[10];
    const float* c0_ui_bl = (const float*)d_in[11];
    const float* c0_ui_Wr = (const float*)d_in[12];
    const float* c0_iu_Wl = (const float*)d_in[13];
    const float* c0_iu_bl = (const float*)d_in[14];
    const float* c0_iu_Wr = (const float*)d_in[15];
    const float* c1_ui_Wl = (const float*)d_in[16];
    const float* c1_ui_bl = (const float*)d_in[17];
    const float* c1_ui_Wr = (const float*)d_in[18];
    const float* c1_iu_Wl = (const float*)d_in[19];
    const float* c1_iu_bl = (const float*)d_in[20];
    const float* c1_iu_Wr = (const float*)d_in[21];
    const float* out_user_W = (const float*)d_in[22];
    const float* out_user_b = (const float*)d_in[23];
    const float* out_item_W = (const float*)d_in[24];
    const float* out_item_b = (const float*)d_in[25];
    const float* ln_user_g  = (const float*)d_in[26];
    const float* ln_user_b2 = (const float*)d_in[27];
    const float* ln_item_g  = (const float*)d_in[28];
    const float* ln_item_b2 = (const float*)d_in[29];

    float* out = (float*)d_out;

    const int nE = in_sizes[2];
    const int M  = NNODE;

    float *hu, *hi, *tu, *ti, *agg, *invu, *invi;
    int *degu, *degi;
    cudaGetSymbolAddress((void**)&hu,   g_hu);
    cudaGetSymbolAddress((void**)&hi,   g_hi);
    cudaGetSymbolAddress((void**)&tu,   g_tu);
    cudaGetSymbolAddress((void**)&ti,   g_ti);
    cudaGetSymbolAddress((void**)&agg,  g_agg);
    cudaGetSymbolAddress((void**)&invu, g_invu);
    cudaGetSymbolAddress((void**)&invi, g_invi);
    cudaGetSymbolAddress((void**)&degu, g_degu);
    cudaGetSymbolAddress((void**)&degi, g_degi);

    const size_t HB = (size_t)M * HDIM * sizeof(float);

    dim3 blk(256);
    dim3 grid_gemm((M + BM - 1) / BM, 2);
    dim3 grid_edge((nE + 255) / 256);
    dim3 grid_node((M + 255) / 256);
    dim3 grid_scat(((size_t)nE * 32 + 255) / 256);
    dim3 grid_ln((M + 7) / 8);

    // -- degrees --
    cudaMemsetAsync(degu, 0, M * sizeof(int));
    cudaMemsetAsync(degi, 0, M * sizeof(int));
    deg_kernel<<<grid_edge, blk>>>(ei_ui_dst, degi, nE);
    deg_kernel<<<grid_edge, blk>>>(ei_iu_dst, degu, nE);
    inv_kernel<<<grid_node, blk>>>(degi, invi, M);
    inv_kernel<<<grid_node, blk>>>(degu, invu, M);

    // -- input projections + GELU --
    gemm_tc<DIN, false, false, 0><<<grid_gemm, blk>>>(
        x_user, nullptr, nullptr, lin_user_W, nullptr, lin_user_b, hu, M);
    gemm_tc<DIN, false, false, 0><<<grid_gemm, blk>>>(
        x_item, nullptr, nullptr, lin_item_W, nullptr, lin_item_b, hi, M);

    // -- layer 0, item dst --
    cudaMemsetAsync(agg, 0, HB);
    scatter_kernel<<<grid_scat, blk>>>(hu, ei_ui_src, ei_ui_dst, agg, nE);
    gemm_tc<HDIM, true, true, 0><<<grid_gemm, blk>>>(
        agg, invi, hi, c0_ui_Wl, c0_ui_Wr, c0_ui_bl, ti, M);

    // -- layer 0, user dst --
    cudaMemsetAsync(agg, 0, HB);
    scatter_kernel<<<grid_scat, blk>>>(hi, ei_iu_src, ei_iu_dst, agg, nE);
    gemm_tc<HDIM, true, true, 0><<<grid_gemm, blk>>>(
        agg, invu, hu, c0_iu_Wl, c0_iu_Wr, c0_iu_bl, tu, M);

    // -- layer 1, item dst --
    cudaMemsetAsync(agg, 0, HB);
    scatter_kernel<<<grid_scat, blk>>>(tu, ei_ui_src, ei_ui_dst, agg, nE);
    gemm_tc<HDIM, true, true, 0><<<grid_gemm, blk>>>(
        agg, invi, ti, c1_ui_Wl, c1_ui_Wr, c1_ui_bl, hi, M);

    // -- layer 1, user dst --
    cudaMemsetAsync(agg, 0, HB);
    scatter_kernel<<<grid_scat, blk>>>(ti, ei_iu_src, ei_iu_dst, agg, nE);
    gemm_tc<HDIM, true, true, 0><<<grid_gemm, blk>>>(
        agg, invu, tu, c1_iu_Wl, c1_iu_Wr, c1_iu_bl, hu, M);

    // -- heads: linear (raw) then in-place LayerNorm --
    gemm_tc<HDIM, false, false, 1><<<grid_gemm, blk>>>(
        hu, nullptr, nullptr, out_user_W, nullptr, out_user_b, out, M);
    gemm_tc<HDIM, false, false, 1><<<grid_gemm, blk>>>(
        hi, nullptr, nullptr, out_item_W, nullptr, out_item_b, out + (size_t)M * HDIM, M);
    ln_kernel<<<grid_ln, blk>>>(out, ln_user_g, ln_user_b2, M);
    ln_kernel<<<grid_ln, blk>>>(out + (size_t)M * HDIM, ln_item_g, ln_item_b2, M);
}

// round 4
// speedup vs baseline: 1.2856x; 1.1039x over previous
#include <cuda_runtime.h>
#include <math.h>
#include <stdint.h>

#define NNODE 100000
#define EDGES 800000
#define DIN   128
#define HDIM  256

// ---------------------------------------------------------------------------
// Scratch (__device__ globals; no allocation allowed)
// ---------------------------------------------------------------------------
__device__ float g_hu [(size_t)NNODE * HDIM];
__device__ float g_hi [(size_t)NNODE * HDIM];
__device__ float g_tu [(size_t)NNODE * HDIM];
__device__ float g_ti [(size_t)NNODE * HDIM];
__device__ float g_agg[2 * (size_t)NNODE * HDIM];  // agg0 | agg1
__device__ int   g_deg[2 * NNODE];                 // deg0 (item) | deg1 (user)

// ---------------------------------------------------------------------------
// Helpers
// ---------------------------------------------------------------------------
__device__ __forceinline__ float gelu_f(float x) {
    return 0.5f * x * (1.0f + erff(x * 0.70710678118654752f));
}
__device__ __forceinline__ float to_tf32(float x) {
    float r;
    asm("cvt.rna.tf32.f32 %0, %1;" : "=f"(r) : "f"(x));
    return r;
}
__device__ __forceinline__ void cvt4(float4& v) {
    v.x = to_tf32(v.x); v.y = to_tf32(v.y); v.z = to_tf32(v.z); v.w = to_tf32(v.w);
}
__device__ __forceinline__ void mma_tf32(float& d0, float& d1, float& d2, float& d3,
                                         uint32_t a0, uint32_t a1, uint32_t a2, uint32_t a3,
                                         uint32_t b0, uint32_t b1)
{
    asm volatile(
        "mma.sync.aligned.m16n8k8.row.col.f32.tf32.tf32.f32 "
        "{%0,%1,%2,%3}, {%4,%5,%6,%7}, {%8,%9}, {%0,%1,%2,%3};"
        : "+f"(d0), "+f"(d1), "+f"(d2), "+f"(d3)
        : "r"(a0), "r"(a1), "r"(a2), "r"(a3), "r"(b0), "r"(b1));
}

// ---------------------------------------------------------------------------
// Edge scatter: agg[dst] += h[src]; optionally counts deg[dst] (lane 0).
// One warp per edge, red.global.add.v4.f32.
// ---------------------------------------------------------------------------
template<bool COUNT>
__global__ void __launch_bounds__(256)
scatter_kernel(const float* __restrict__ h, const int* __restrict__ src,
               const int* __restrict__ dst, float* __restrict__ agg,
               int* __restrict__ deg, int nE)
{
    int gid  = blockIdx.x * blockDim.x + threadIdx.x;
    int e    = gid >> 5;
    int lane = gid & 31;
    if (e >= nE) return;
    int s = __ldg(&src[e]);
    int d = __ldg(&dst[e]);
    if (COUNT && lane == 0) atomicAdd(&deg[d], 1);
    const float4* hp = reinterpret_cast<const float4*>(h + (size_t)s * HDIM) + lane * 2;
    float4*       ap = reinterpret_cast<float4*>(agg + (size_t)d * HDIM) + lane * 2;
    float4 v0 = hp[0];
    float4 v1 = hp[1];
    asm volatile("red.global.add.v4.f32 [%0], {%1,%2,%3,%4};"
                 :: "l"(ap), "f"(v0.x), "f"(v0.y), "f"(v0.z), "f"(v0.w) : "memory");
    asm volatile("red.global.add.v4.f32 [%0], {%1,%2,%3,%4};"
                 :: "l"(ap + 1), "f"(v1.x), "f"(v1.y), "f"(v1.z), "f"(v1.w) : "memory");
}

// ---------------------------------------------------------------------------
// In-place LayerNorm over 256 cols, one warp per row.
// ---------------------------------------------------------------------------
__global__ void __launch_bounds__(256)
ln_kernel(float* __restrict__ x, const float* __restrict__ g,
          const float* __restrict__ b, int M)
{
    int row  = blockIdx.x * 8 + (threadIdx.x >> 5);
    int lane = threadIdx.x & 31;
    if (row >= M) return;
    float* p = x + (size_t)row * HDIM + lane * 8;
    float4 v0 = *reinterpret_cast<const float4*>(p);
    float4 v1 = *reinterpret_cast<const float4*>(p + 4);
    float s  = v0.x + v0.y + v0.z + v0.w + v1.x + v1.y + v1.z + v1.w;
    float sq = v0.x*v0.x + v0.y*v0.y + v0.z*v0.z + v0.w*v0.w
             + v1.x*v1.x + v1.y*v1.y + v1.z*v1.z + v1.w*v1.w;
    #pragma unroll
    for (int m = 16; m > 0; m >>= 1) {
        s  += __shfl_xor_sync(0xffffffffu, s,  m);
        sq += __shfl_xor_sync(0xffffffffu, sq, m);
    }
    float mu   = s * (1.0f / 256.0f);
    float var  = sq * (1.0f / 256.0f) - mu * mu;
    float rstd = rsqrtf(var + 1e-5f);
    float4 g0 = *reinterpret_cast<const float4*>(g + lane * 8);
    float4 g1 = *reinterpret_cast<const float4*>(g + lane * 8 + 4);
    float4 b0 = *reinterpret_cast<const float4*>(b + lane * 8);
    float4 b1 = *reinterpret_cast<const float4*>(b + lane * 8 + 4);
    float4 o0, o1;
    o0.x = (v0.x - mu) * rstd * g0.x + b0.x;
    o0.y = (v0.y - mu) * rstd * g0.y + b0.y;
    o0.z = (v0.z - mu) * rstd * g0.z + b0.z;
    o0.w = (v0.w - mu) * rstd * g0.w + b0.w;
    o1.x = (v1.x - mu) * rstd * g1.x + b1.x;
    o1.y = (v1.y - mu) * rstd * g1.y + b1.y;
    o1.z = (v1.z - mu) * rstd * g1.z + b1.z;
    o1.w = (v1.w - mu) * rstd * g1.w + b1.w;
    *reinterpret_cast<float4*>(p)     = o0;
    *reinterpret_cast<float4*>(p + 4) = o1;
}

// ---------------------------------------------------------------------------
// Double-buffered tensor-core tf32 GEMM:
//   C[M,256] = EPI( A1(*1/max(deg,1))@W1 (+ A2@W2) + bias )
//   EPI=0: exact GELU   EPI=1: none
// Block 128x128 (grid.y=2), BK=32, 8 warps 2x4, warp tile 64x32.
// 2-stage smem pipeline with register prefetch; 1 sync per k-iter.
// ---------------------------------------------------------------------------
constexpr int BM  = 128;
constexpr int BK  = 32;
constexpr int LDA = 36;
constexpr int LDB = 136;

template<int K, bool HAS_A2, bool SCALE1, int EPI>
__global__ void __launch_bounds__(256)
gemm_tc(const float* __restrict__ A1, const int* __restrict__ deg,
        const float* __restrict__ A2,
        const float* __restrict__ W1, const float* __restrict__ W2,
        const float* __restrict__ bias,
        float* __restrict__ C, int M)
{
    __shared__ float a_s[2][BM * LDA];
    __shared__ float b_s[2][BK * LDB];

    constexpr int NIT = (HAS_A2 ? 2 : 1) * K / BK;

    const int tid  = threadIdx.x;
    const int lane = tid & 31;
    const int wid  = tid >> 5;
    const int wm   = wid >> 2;
    const int wn   = wid & 3;
    const int lq   = lane >> 2;
    const int lr   = lane & 3;
    const int row0 = blockIdx.x * BM;
    const int ncol0 = blockIdx.y * 128;

    // Per-thread load coordinates (u = 0..3 strided by 256 threads)
    const int ar  = tid >> 3;          // + u*32 : A row 0..127
    const int ac4 = (tid & 7) << 2;    // A col (float index)
    const int bkr = tid >> 5;          // + u*8  : B k-row 0..31
    const int bc4 = (tid & 31) << 2;   // B col

    float d[4][4][4];
    #pragma unroll
    for (int i = 0; i < 4; i++)
        #pragma unroll
        for (int j = 0; j < 4; j++)
            #pragma unroll
            for (int q = 0; q < 4; q++)
                d[i][j][q] = 0.f;

    float4 va[4], vb[4];

    auto load_tile = [&](int kt) {
        int kk = kt * BK;
        const float* __restrict__ A = (HAS_A2 && kk >= K) ? A2 : A1;
        const float* __restrict__ W = (HAS_A2 && kk >= K) ? W2 : W1;
        const bool ph0 = !(HAS_A2 && kk >= K);
        const int k0 = HAS_A2 ? (kk & (K - 1)) : kk;
        #pragma unroll
        for (int u = 0; u < 4; u++) {
            int r  = ar + u * 32;
            int gr = row0 + r;
            float4 v = make_float4(0.f, 0.f, 0.f, 0.f);
            if (gr < M) {
                v = *reinterpret_cast<const float4*>(A + (size_t)gr * K + k0 + ac4);
                if (SCALE1 && ph0) {
                    float s = 1.0f / fmaxf((float)__ldg(&deg[gr]), 1.0f);
                    v.x *= s; v.y *= s; v.z *= s; v.w *= s;
                }
                cvt4(v);
            }
            va[u] = v;
            float4 w = *reinterpret_cast<const float4*>(
                W + (size_t)(k0 + bkr + u * 8) * HDIM + ncol0 + bc4);
            cvt4(w);
            vb[u] = w;
        }
    };
    auto store_tile = [&](int buf) {
        #pragma unroll
        for (int u = 0; u < 4; u++) {
            *reinterpret_cast<float4*>(&a_s[buf][(ar + u * 32) * LDA + ac4]) = va[u];
            *reinterpret_cast<float4*>(&b_s[buf][(bkr + u * 8) * LDB + bc4]) = vb[u];
        }
    };

    load_tile(0);
    store_tile(0);
    __syncthreads();

    #pragma unroll 1
    for (int kt = 0; kt < NIT; kt++) {
        const int buf = kt & 1;
        if (kt + 1 < NIT) load_tile(kt + 1);

        const float* __restrict__ as = a_s[buf];
        const float* __restrict__ bs = b_s[buf];
        #pragma unroll
        for (int ks = 0; ks < 4; ks++) {
            uint32_t af[4][4];
            #pragma unroll
            for (int i = 0; i < 4; i++) {
                int rm = wm * 64 + i * 16 + lq;
                af[i][0] = __float_as_uint(as[rm * LDA + ks * 8 + lr]);
                af[i][1] = __float_as_uint(as[(rm + 8) * LDA + ks * 8 + lr]);
                af[i][2] = __float_as_uint(as[rm * LDA + ks * 8 + lr + 4]);
                af[i][3] = __float_as_uint(as[(rm + 8) * LDA + ks * 8 + lr + 4]);
            }
            uint32_t bf[4][2];
            #pragma unroll
            for (int j = 0; j < 4; j++) {
                int cb = wn * 32 + j * 8 + lq;
                bf[j][0] = __float_as_uint(bs[(ks * 8 + lr) * LDB + cb]);
                bf[j][1] = __float_as_uint(bs[(ks * 8 + lr + 4) * LDB + cb]);
            }
            #pragma unroll
            for (int i = 0; i < 4; i++)
                #pragma unroll
                for (int j = 0; j < 4; j++)
                    mma_tf32(d[i][j][0], d[i][j][1], d[i][j][2], d[i][j][3],
                             af[i][0], af[i][1], af[i][2], af[i][3],
                             bf[j][0], bf[j][1]);
        }
        if (kt + 1 < NIT) {
            store_tile(buf ^ 1);
            __syncthreads();
        }
    }

    // ---- bias
    #pragma unroll
    for (int j = 0; j < 4; j++) {
        float2 b = *reinterpret_cast<const float2*>(bias + ncol0 + wn * 32 + j * 8 + 2 * lr);
        #pragma unroll
        for (int i = 0; i < 4; i++) {
            d[i][j][0] += b.x; d[i][j][1] += b.y;
            d[i][j][2] += b.x; d[i][j][3] += b.y;
        }
    }

    const int cbase = ncol0 + wn * 32;
    #pragma unroll
    for (int i = 0; i < 4; i++) {
        #pragma unroll
        for (int rr = 0; rr < 2; rr++) {
            int gr = row0 + wm * 64 + i * 16 + lq + rr * 8;
            if (gr < M) {
                #pragma unroll
                for (int j = 0; j < 4; j++) {
                    float2 v;
                    if (EPI == 0) {
                        v.x = gelu_f(d[i][j][rr * 2 + 0]);
                        v.y = gelu_f(d[i][j][rr * 2 + 1]);
                    } else {
                        v.x = d[i][j][rr * 2 + 0];
                        v.y = d[i][j][rr * 2 + 1];
                    }
                    *reinterpret_cast<float2*>(
                        C + (size_t)gr * HDIM + cbase + j * 8 + 2 * lr) = v;
                }
            }
        }
    }
}

// ---------------------------------------------------------------------------
// kernel_launch
// ---------------------------------------------------------------------------
extern "C" void kernel_launch(void* const* d_in, const int* in_sizes, int n_in,
                              void* d_out, int out_size)
{
    const float* x_user    = (const float*)d_in[0];
    const float* x_item    = (const float*)d_in[1];
    const int*   ei_ui_src = (const int*)  d_in[2];
    const int*   ei_ui_dst = (const int*)  d_in[3];
    const int*   ei_iu_src = (const int*)  d_in[4];
    const int*   ei_iu_dst = (const int*)  d_in[5];
    const float* lin_user_W = (const float*)d_in[6];
    const float* lin_user_b = (const float*)d_in[7];
    const float* lin_item_W = (const float*)d_in[8];
    const float* lin_item_b = (const float*)d_in[9];
    const float* c0_ui_Wl = (const float*)d_in[10];
    const float* c0_ui_bl = (const float*)d_in[11];
    const float* c0_ui_Wr = (const float*)d_in[12];
    const float* c0_iu_Wl = (const float*)d_in[13];
    const float* c0_iu_bl = (const float*)d_in[14];
    const float* c0_iu_Wr = (const float*)d_in[15];
    const float* c1_ui_Wl = (const float*)d_in[16];
    const float* c1_ui_bl = (const float*)d_in[17];
    const float* c1_ui_Wr = (const float*)d_in[18];
    const float* c1_iu_Wl = (const float*)d_in[19];
    const float* c1_iu_bl = (const float*)d_in[20];
    const float* c1_iu_Wr = (const float*)d_in[21];
    const float* out_user_W = (const float*)d_in[22];
    const float* out_user_b = (const float*)d_in[23];
    const float* out_item_W = (const float*)d_in[24];
    const float* out_item_b = (const float*)d_in[25];
    const float* ln_user_g  = (const float*)d_in[26];
    const float* ln_user_b2 = (const float*)d_in[27];
    const float* ln_item_g  = (const float*)d_in[28];
    const float* ln_item_b2 = (const float*)d_in[29];

    float* out = (float*)d_out;
    const int nE = in_sizes[2];
    const int M  = NNODE;

    float *hu, *hi, *tu, *ti, *agg;
    int *deg;
    cudaGetSymbolAddress((void**)&hu,  g_hu);
    cudaGetSymbolAddress((void**)&hi,  g_hi);
    cudaGetSymbolAddress((void**)&tu,  g_tu);
    cudaGetSymbolAddress((void**)&ti,  g_ti);
    cudaGetSymbolAddress((void**)&agg, g_agg);
    cudaGetSymbolAddress((void**)&deg, g_deg);

    float* agg0 = agg;
    float* agg1 = agg + (size_t)M * HDIM;
    int*   deg0 = deg;        // item degrees (ui edges)
    int*   deg1 = deg + M;    // user degrees (iu edges)

    const size_t AGGB = 2 * (size_t)M * HDIM * sizeof(float);

    dim3 blk(256);
    dim3 grid_gemm((M + BM - 1) / BM, 2);
    dim3 grid_scat(((size_t)nE * 32 + 255) / 256);
    dim3 grid_ln((M + 7) / 8);

    // Launch order chosen so ncu (-s 5 -c 1) captures launch #6 = SAGE gemm.
    /* 1 */ cudaMemsetAsync(deg, 0, 2 * M * sizeof(int));
    /* 2 */ gemm_tc<DIN, false, false, 0><<<grid_gemm, blk>>>(
                x_user, nullptr, nullptr, lin_user_W, nullptr, lin_user_b, hu, M);
    /* 3 */ gemm_tc<DIN, false, false, 0><<<grid_gemm, blk>>>(
                x_item, nullptr, nullptr, lin_item_W, nullptr, lin_item_b, hi, M);
    /* 4 */ cudaMemsetAsync(agg, 0, AGGB);
    /* 5 */ scatter_kernel<true><<<grid_scat, blk>>>(hu, ei_ui_src, ei_ui_dst, agg0, deg0, nE);
    /* 6 */ gemm_tc<HDIM, true, true, 0><<<grid_gemm, blk>>>(          // <- profiled
                agg0, deg0, hi, c0_ui_Wl, c0_ui_Wr, c0_ui_bl, ti, M);
    /* 7 */ scatter_kernel<true><<<grid_scat, blk>>>(hi, ei_iu_src, ei_iu_dst, agg1, deg1, nE);
    /* 8 */ gemm_tc<HDIM, true, true, 0><<<grid_gemm, blk>>>(
                agg1, deg1, hu, c0_iu_Wl, c0_iu_Wr, c0_iu_bl, tu, M);
    /* 9 */ cudaMemsetAsync(agg, 0, AGGB);
    /*10 */ scatter_kernel<false><<<grid_scat, blk>>>(tu, ei_ui_src, ei_ui_dst, agg0, nullptr, nE);
    /*11 */ gemm_tc<HDIM, true, true, 0><<<grid_gemm, blk>>>(
                agg0, deg0, ti, c1_ui_Wl, c1_ui_Wr, c1_ui_bl, hi, M);
    /*12 */ scatter_kernel<false><<<grid_scat, blk>>>(ti, ei_iu_src, ei_iu_dst, agg1, nullptr, nE);
    /*13 */ gemm_tc<HDIM, true, true, 0><<<grid_gemm, blk>>>(
                agg1, deg1, tu, c1_iu_Wl, c1_iu_Wr, c1_iu_bl, hu, M);
    /*14 */ gemm_tc<HDIM, false, false, 1><<<grid_gemm, blk>>>(
                hu, nullptr, nullptr, out_user_W, nullptr, out_user_b, out, M);
    /*15 */ gemm_tc<HDIM, false, false, 1><<<grid_gemm, blk>>>(
                hi, nullptr, nullptr, out_item_W, nullptr, out_item_b,
                out + (size_t)M * HDIM, M);
    /*16 */ ln_kernel<<<grid_ln, blk>>>(out, ln_user_g, ln_user_b2, M);
    /*17 */ ln_kernel<<<grid_ln, blk>>>(out + (size_t)M * HDIM, ln_item_g, ln_item_b2, M);
}

// round 5
// speedup vs baseline: 1.3040x; 1.0143x over previous
#include <cuda_runtime.h>
#include <math.h>
#include <stdint.h>

#define NNODE 100000
#define EDGES 800000
#define DIN   128
#define HDIM  256

// ---------------------------------------------------------------------------
// Scratch (__device__ globals; no allocation allowed)
// ---------------------------------------------------------------------------
__device__ float g_hu [(size_t)NNODE * HDIM];
__device__ float g_hi [(size_t)NNODE * HDIM];
__device__ float g_tu [(size_t)NNODE * HDIM];
__device__ float g_ti [(size_t)NNODE * HDIM];
__device__ float g_agg[2 * (size_t)NNODE * HDIM];  // agg0 | agg1
__device__ int   g_deg[2 * NNODE];                 // deg0 (item) | deg1 (user)

// ---------------------------------------------------------------------------
// Helpers
// ---------------------------------------------------------------------------
__device__ __forceinline__ float gelu_f(float x) {
    return 0.5f * x * (1.0f + erff(x * 0.70710678118654752f));
}
__device__ __forceinline__ float to_tf32(float x) {
    float r;
    asm("cvt.rna.tf32.f32 %0, %1;" : "=f"(r) : "f"(x));
    return r;
}
__device__ __forceinline__ void cvt4(float4& v) {
    v.x = to_tf32(v.x); v.y = to_tf32(v.y); v.z = to_tf32(v.z); v.w = to_tf32(v.w);
}
__device__ __forceinline__ void mma_tf32(float& d0, float& d1, float& d2, float& d3,
                                         uint32_t a0, uint32_t a1, uint32_t a2, uint32_t a3,
                                         uint32_t b0, uint32_t b1)
{
    asm volatile(
        "mma.sync.aligned.m16n8k8.row.col.f32.tf32.tf32.f32 "
        "{%0,%1,%2,%3}, {%4,%5,%6,%7}, {%8,%9}, {%0,%1,%2,%3};"
        : "+f"(d0), "+f"(d1), "+f"(d2), "+f"(d3)
        : "r"(a0), "r"(a1), "r"(a2), "r"(a3), "r"(b0), "r"(b1));
}

// ---------------------------------------------------------------------------
// Edge scatter: agg[dst] += h[src]; optionally counts deg[dst] (lane 0).
// One warp per edge, red.global.add.v4.f32.
// ---------------------------------------------------------------------------
template<bool COUNT>
__global__ void __launch_bounds__(256)
scatter_kernel(const float* __restrict__ h, const int* __restrict__ src,
               const int* __restrict__ dst, float* __restrict__ agg,
               int* __restrict__ deg, int nE)
{
    int gid  = blockIdx.x * blockDim.x + threadIdx.x;
    int e    = gid >> 5;
    int lane = gid & 31;
    if (e >= nE) return;
    int s = __ldg(&src[e]);
    int d = __ldg(&dst[e]);
    if (COUNT && lane == 0) atomicAdd(&deg[d], 1);
    const float4* hp = reinterpret_cast<const float4*>(h + (size_t)s * HDIM) + lane * 2;
    float4*       ap = reinterpret_cast<float4*>(agg + (size_t)d * HDIM) + lane * 2;
    float4 v0 = hp[0];
    float4 v1 = hp[1];
    asm volatile("red.global.add.v4.f32 [%0], {%1,%2,%3,%4};"
                 :: "l"(ap), "f"(v0.x), "f"(v0.y), "f"(v0.z), "f"(v0.w) : "memory");
    asm volatile("red.global.add.v4.f32 [%0], {%1,%2,%3,%4};"
                 :: "l"(ap + 1), "f"(v1.x), "f"(v1.y), "f"(v1.z), "f"(v1.w) : "memory");
}

// ---------------------------------------------------------------------------
// In-place LayerNorm over 256 cols, one warp per row.
// ---------------------------------------------------------------------------
__global__ void __launch_bounds__(256)
ln_kernel(float* __restrict__ x, const float* __restrict__ g,
          const float* __restrict__ b, int M)
{
    int row  = blockIdx.x * 8 + (threadIdx.x >> 5);
    int lane = threadIdx.x & 31;
    if (row >= M) return;
    float* p = x + (size_t)row * HDIM + lane * 8;
    float4 v0 = *reinterpret_cast<const float4*>(p);
    float4 v1 = *reinterpret_cast<const float4*>(p + 4);
    float s  = v0.x + v0.y + v0.z + v0.w + v1.x + v1.y + v1.z + v1.w;
    float sq = v0.x*v0.x + v0.y*v0.y + v0.z*v0.z + v0.w*v0.w
             + v1.x*v1.x + v1.y*v1.y + v1.z*v1.z + v1.w*v1.w;
    #pragma unroll
    for (int m = 16; m > 0; m >>= 1) {
        s  += __shfl_xor_sync(0xffffffffu, s,  m);
        sq += __shfl_xor_sync(0xffffffffu, sq, m);
    }
    float mu   = s * (1.0f / 256.0f);
    float var  = sq * (1.0f / 256.0f) - mu * mu;
    float rstd = rsqrtf(var + 1e-5f);
    float4 g0 = *reinterpret_cast<const float4*>(g + lane * 8);
    float4 g1 = *reinterpret_cast<const float4*>(g + lane * 8 + 4);
    float4 b0 = *reinterpret_cast<const float4*>(b + lane * 8);
    float4 b1 = *reinterpret_cast<const float4*>(b + lane * 8 + 4);
    float4 o0, o1;
    o0.x = (v0.x - mu) * rstd * g0.x + b0.x;
    o0.y = (v0.y - mu) * rstd * g0.y + b0.y;
    o0.z = (v0.z - mu) * rstd * g0.z + b0.z;
    o0.w = (v0.w - mu) * rstd * g0.w + b0.w;
    o1.x = (v1.x - mu) * rstd * g1.x + b1.x;
    o1.y = (v1.y - mu) * rstd * g1.y + b1.y;
    o1.z = (v1.z - mu) * rstd * g1.z + b1.z;
    o1.w = (v1.w - mu) * rstd * g1.w + b1.w;
    *reinterpret_cast<float4*>(p)     = o0;
    *reinterpret_cast<float4*>(p + 4) = o1;
}

// ---------------------------------------------------------------------------
// Double-buffered tensor-core tf32 GEMM:
//   C[M,256] = EPI( A1(*1/max(deg,1))@W1 (+ A2@W2) + bias )
//   EPI=0: exact GELU   EPI=1: none
// Block 128x128 (grid.y=2), BK=32, 8 warps 2x4, warp tile 64x32.
// 2-stage smem pipeline with register prefetch; 1 sync per k-iter.
// ---------------------------------------------------------------------------
constexpr int BM  = 128;
constexpr int BK  = 32;
constexpr int LDA = 36;
constexpr int LDB = 136;

template<int K, bool HAS_A2, bool SCALE1, int EPI>
__global__ void __launch_bounds__(256)
gemm_tc(const float* __restrict__ A1, const int* __restrict__ deg,
        const float* __restrict__ A2,
        const float* __restrict__ W1, const float* __restrict__ W2,
        const float* __restrict__ bias,
        float* __restrict__ C, int M)
{
    __shared__ float a_s[2][BM * LDA];
    __shared__ float b_s[2][BK * LDB];

    constexpr int NIT = (HAS_A2 ? 2 : 1) * K / BK;

    const int tid  = threadIdx.x;
    const int lane = tid & 31;
    const int wid  = tid >> 5;
    const int wm   = wid >> 2;
    const int wn   = wid & 3;
    const int lq   = lane >> 2;
    const int lr   = lane & 3;
    const int row0 = blockIdx.x * BM;
    const int ncol0 = blockIdx.y * 128;

    // Per-thread load coordinates (u = 0..3 strided by 256 threads)
    const int ar  = tid >> 3;          // + u*32 : A row 0..127
    const int ac4 = (tid & 7) << 2;    // A col (float index)
    const int bkr = tid >> 5;          // + u*8  : B k-row 0..31
    const int bc4 = (tid & 31) << 2;   // B col

    float d[4][4][4];
    #pragma unroll
    for (int i = 0; i < 4; i++)
        #pragma unroll
        for (int j = 0; j < 4; j++)
            #pragma unroll
            for (int q = 0; q < 4; q++)
                d[i][j][q] = 0.f;

    float4 va[4], vb[4];

    auto load_tile = [&](int kt) {
        int kk = kt * BK;
        const float* __restrict__ A = (HAS_A2 && kk >= K) ? A2 : A1;
        const float* __restrict__ W = (HAS_A2 && kk >= K) ? W2 : W1;
        const bool ph0 = !(HAS_A2 && kk >= K);
        const int k0 = HAS_A2 ? (kk & (K - 1)) : kk;
        #pragma unroll
        for (int u = 0; u < 4; u++) {
            int r  = ar + u * 32;
            int gr = row0 + r;
            float4 v = make_float4(0.f, 0.f, 0.f, 0.f);
            if (gr < M) {
                v = *reinterpret_cast<const float4*>(A + (size_t)gr * K + k0 + ac4);
                if (SCALE1 && ph0) {
                    float s = 1.0f / fmaxf((float)__ldg(&deg[gr]), 1.0f);
                    v.x *= s; v.y *= s; v.z *= s; v.w *= s;
                }
                cvt4(v);
            }
            va[u] = v;
            float4 w = *reinterpret_cast<const float4*>(
                W + (size_t)(k0 + bkr + u * 8) * HDIM + ncol0 + bc4);
            cvt4(w);
            vb[u] = w;
        }
    };
    auto store_tile = [&](int buf) {
        #pragma unroll
        for (int u = 0; u < 4; u++) {
            *reinterpret_cast<float4*>(&a_s[buf][(ar + u * 32) * LDA + ac4]) = va[u];
            *reinterpret_cast<float4*>(&b_s[buf][(bkr + u * 8) * LDB + bc4]) = vb[u];
        }
    };

    load_tile(0);
    store_tile(0);
    __syncthreads();

    #pragma unroll 1
    for (int kt = 0; kt < NIT; kt++) {
        const int buf = kt & 1;
        if (kt + 1 < NIT) load_tile(kt + 1);

        const float* __restrict__ as = a_s[buf];
        const float* __restrict__ bs = b_s[buf];
        #pragma unroll
        for (int ks = 0; ks < 4; ks++) {
            uint32_t af[4][4];
            #pragma unroll
            for (int i = 0; i < 4; i++) {
                int rm = wm * 64 + i * 16 + lq;
                af[i][0] = __float_as_uint(as[rm * LDA + ks * 8 + lr]);
                af[i][1] = __float_as_uint(as[(rm + 8) * LDA + ks * 8 + lr]);
                af[i][2] = __float_as_uint(as[rm * LDA + ks * 8 + lr + 4]);
                af[i][3] = __float_as_uint(as[(rm + 8) * LDA + ks * 8 + lr + 4]);
            }
            uint32_t bf[4][2];
            #pragma unroll
            for (int j = 0; j < 4; j++) {
                int cb = wn * 32 + j * 8 + lq;
                bf[j][0] = __float_as_uint(bs[(ks * 8 + lr) * LDB + cb]);
                bf[j][1] = __float_as_uint(bs[(ks * 8 + lr + 4) * LDB + cb]);
            }
            #pragma unroll
            for (int i = 0; i < 4; i++)
                #pragma unroll
                for (int j = 0; j < 4; j++)
                    mma_tf32(d[i][j][0], d[i][j][1], d[i][j][2], d[i][j][3],
                             af[i][0], af[i][1], af[i][2], af[i][3],
                             bf[j][0], bf[j][1]);
        }
        if (kt + 1 < NIT) {
            store_tile(buf ^ 1);
            __syncthreads();
        }
    }

    // ---- bias
    #pragma unroll
    for (int j = 0; j < 4; j++) {
        float2 b = *reinterpret_cast<const float2*>(bias + ncol0 + wn * 32 + j * 8 + 2 * lr);
        #pragma unroll
        for (int i = 0; i < 4; i++) {
            d[i][j][0] += b.x; d[i][j][1] += b.y;
            d[i][j][2] += b.x; d[i][j][3] += b.y;
        }
    }

    const int cbase = ncol0 + wn * 32;
    #pragma unroll
    for (int i = 0; i < 4; i++) {
        #pragma unroll
        for (int rr = 0; rr < 2; rr++) {
            int gr = row0 + wm * 64 + i * 16 + lq + rr * 8;
            if (gr < M) {
                #pragma unroll
                for (int j = 0; j < 4; j++) {
                    float2 v;
                    if (EPI == 0) {
                        v.x = gelu_f(d[i][j][rr * 2 + 0]);
                        v.y = gelu_f(d[i][j][rr * 2 + 1]);
                    } else {
                        v.x = d[i][j][rr * 2 + 0];
                        v.y = d[i][j][rr * 2 + 1];
                    }
                    *reinterpret_cast<float2*>(
                        C + (size_t)gr * HDIM + cbase + j * 8 + 2 * lr) = v;
                }
            }
        }
    }
}

// ---------------------------------------------------------------------------
// kernel_launch
// ---------------------------------------------------------------------------
extern "C" void kernel_launch(void* const* d_in, const int* in_sizes, int n_in,
                              void* d_out, int out_size)
{
    const float* x_user    = (const float*)d_in[0];
    const float* x_item    = (const float*)d_in[1];
    const int*   ei_ui_src = (const int*)  d_in[2];
    const int*   ei_ui_dst = (const int*)  d_in[3];
    const int*   ei_iu_src = (const int*)  d_in[4];
    const int*   ei_iu_dst = (const int*)  d_in[5];
    const float* lin_user_W = (const float*)d_in[6];
    const float* lin_user_b = (const float*)d_in[7];
    const float* lin_item_W = (const float*)d_in[8];
    const float* lin_item_b = (const float*)d_in[9];
    const float* c0_ui_Wl = (const float*)d_in[10];
    const float* c0_ui_bl = (const float*)d_in[11];
    const float* c0_ui_Wr = (const float*)d_in[12];
    const float* c0_iu_Wl = (const float*)d_in[13];
    const float* c0_iu_bl = (const float*)d_in[14];
    const float* c0_iu_Wr = (const float*)d_in[15];
    const float* c1_ui_Wl = (const float*)d_in[16];
    const float* c1_ui_bl = (const float*)d_in[17];
    const float* c1_ui_Wr = (const float*)d_in[18];
    const float* c1_iu_Wl = (const float*)d_in[19];
    const float* c1_iu_bl = (const float*)d_in[20];
    const float* c1_iu_Wr = (const float*)d_in[21];
    const float* out_user_W = (const float*)d_in[22];
    const float* out_user_b = (const float*)d_in[23];
    const float* out_item_W = (const float*)d_in[24];
    const float* out_item_b = (const float*)d_in[25];
    const float* ln_user_g  = (const float*)d_in[26];
    const float* ln_user_b2 = (const float*)d_in[27];
    const float* ln_item_g  = (const float*)d_in[28];
    const float* ln_item_b2 = (const float*)d_in[29];

    float* out = (float*)d_out;
    const int nE = in_sizes[2];
    const int M  = NNODE;

    float *hu, *hi, *tu, *ti, *agg;
    int *deg;
    cudaGetSymbolAddress((void**)&hu,  g_hu);
    cudaGetSymbolAddress((void**)&hi,  g_hi);
    cudaGetSymbolAddress((void**)&tu,  g_tu);
    cudaGetSymbolAddress((void**)&ti,  g_ti);
    cudaGetSymbolAddress((void**)&agg, g_agg);
    cudaGetSymbolAddress((void**)&deg, g_deg);

    float* agg0 = agg;
    float* agg1 = agg + (size_t)M * HDIM;
    int*   deg0 = deg;        // item degrees (ui edges)
    int*   deg1 = deg + M;    // user degrees (iu edges)

    const size_t AGGB = 2 * (size_t)M * HDIM * sizeof(float);

    dim3 blk(256);
    dim3 grid_gemm((M + BM - 1) / BM, 2);
    dim3 grid_scat(((size_t)nE * 32 + 255) / 256);
    dim3 grid_ln((M + 7) / 8);

    // Launch order chosen so ncu (-s 5 -c 1) captures launch #6 = SAGE gemm.
    /* 1 */ cudaMemsetAsync(deg, 0, 2 * M * sizeof(int));
    /* 2 */ gemm_tc<DIN, false, false, 0><<<grid_gemm, blk>>>(
                x_user, nullptr, nullptr, lin_user_W, nullptr, lin_user_b, hu, M);
    /* 3 */ gemm_tc<DIN, false, false, 0><<<grid_gemm, blk>>>(
                x_item, nullptr, nullptr, lin_item_W, nullptr, lin_item_b, hi, M);
    /* 4 */ cudaMemsetAsync(agg, 0, AGGB);
    /* 5 */ scatter_kernel<true><<<grid_scat, blk>>>(hu, ei_ui_src, ei_ui_dst, agg0, deg0, nE);
    /* 6 */ gemm_tc<HDIM, true, true, 0><<<grid_gemm, blk>>>(          // <- profiled
                agg0, deg0, hi, c0_ui_Wl, c0_ui_Wr, c0_ui_bl, ti, M);
    /* 7 */ scatter_kernel<true><<<grid_scat, blk>>>(hi, ei_iu_src, ei_iu_dst, agg1, deg1, nE);
    /* 8 */ gemm_tc<HDIM, true, true, 0><<<grid_gemm, blk>>>(
                agg1, deg1, hu, c0_iu_Wl, c0_iu_Wr, c0_iu_bl, tu, M);
    /* 9 */ cudaMemsetAsync(agg, 0, AGGB);
    /*10 */ scatter_kernel<false><<<grid_scat, blk>>>(tu, ei_ui_src, ei_ui_dst, agg0, nullptr, nE);
    /*11 */ gemm_tc<HDIM, true, true, 0><<<grid_gemm, blk>>>(
                agg0, deg0, ti, c1_ui_Wl, c1_ui_Wr, c1_ui_bl, hi, M);
    /*12 */ scatter_kernel<false><<<grid_scat, blk>>>(ti, ei_iu_src, ei_iu_dst, agg1, nullptr, nE);
    /*13 */ gemm_tc<HDIM, true, true, 0><<<grid_gemm, blk>>>(
                agg1, deg1, tu, c1_iu_Wl, c1_iu_Wr, c1_iu_bl, hu, M);
    /*14 */ gemm_tc<HDIM, false, false, 1><<<grid_gemm, blk>>>(
                hu, nullptr, nullptr, out_user_W, nullptr, out_user_b, out, M);
    /*15 */ gemm_tc<HDIM, false, false, 1><<<grid_gemm, blk>>>(
                hi, nullptr, nullptr, out_item_W, nullptr, out_item_b,
                out + (size_t)M * HDIM, M);
    /*16 */ ln_kernel<<<grid_ln, blk>>>(out, ln_user_g, ln_user_b2, M);
    /*17 */ ln_kernel<<<grid_ln, blk>>>(out + (size_t)M * HDIM, ln_item_g, ln_item_b2, M);
}

// round 6
// speedup vs baseline: 1.5951x; 1.2232x over previous
#include <cuda_runtime.h>
#include <math.h>
#include <stdint.h>

#define NNODE 100000
#define EDGES 800000
#define DIN   128
#define HDIM  256

// ---------------------------------------------------------------------------
// Scratch (__device__ globals; no allocation allowed)
// ---------------------------------------------------------------------------
__device__ float g_hu [(size_t)NNODE * HDIM];
__device__ float g_hi [(size_t)NNODE * HDIM];
__device__ float g_tu [(size_t)NNODE * HDIM];
__device__ float g_ti [(size_t)NNODE * HDIM];
__device__ float g_agg[2 * (size_t)NNODE * HDIM];   // agg0 | agg1
__device__ int   g_deg[2 * NNODE];                  // deg0 (item) | deg1 (user)
__device__ float g_xu [(size_t)NNODE * DIN];        // tf32 x_user
__device__ float g_xi [(size_t)NNODE * DIN];        // tf32 x_item
__device__ float g_wts[2 * 32768 + 10 * 65536];     // tf32 weights

// ---------------------------------------------------------------------------
// Helpers
// ---------------------------------------------------------------------------
__device__ __forceinline__ float gelu_f(float x) {
    return 0.5f * x * (1.0f + erff(x * 0.70710678118654752f));
}
__device__ __forceinline__ float to_tf32(float x) {
    float r;
    asm("cvt.rna.tf32.f32 %0, %1;" : "=f"(r) : "f"(x));
    return r;
}
__device__ __forceinline__ void cvt4(float4& v) {
    v.x = to_tf32(v.x); v.y = to_tf32(v.y); v.z = to_tf32(v.z); v.w = to_tf32(v.w);
}
__device__ __forceinline__ void mma_tf32(float& d0, float& d1, float& d2, float& d3,
                                         uint32_t a0, uint32_t a1, uint32_t a2, uint32_t a3,
                                         uint32_t b0, uint32_t b1)
{
    asm volatile(
        "mma.sync.aligned.m16n8k8.row.col.f32.tf32.tf32.f32 "
        "{%0,%1,%2,%3}, {%4,%5,%6,%7}, {%8,%9}, {%0,%1,%2,%3};"
        : "+f"(d0), "+f"(d1), "+f"(d2), "+f"(d3)
        : "r"(a0), "r"(a1), "r"(a2), "r"(a3), "r"(b0), "r"(b1));
}
__device__ __forceinline__ void cp16(uint32_t dst, const void* src, bool pred) {
    int sz = pred ? 16 : 0;
    asm volatile("cp.async.ca.shared.global [%0], [%1], 16, %2;"
                 :: "r"(dst), "l"(src), "r"(sz));
}

// ---------------------------------------------------------------------------
// Pre-pass: convert weights + x to tf32 (grid.y selects tensor, grid-stride x)
// ---------------------------------------------------------------------------
#define NPACK 14
struct PtrPack {
    const float* src[NPACK];
    float*       dst[NPACK];
    int          n  [NPACK];
};

__global__ void __launch_bounds__(256)
cvt_pack_kernel(PtrPack p)
{
    int m = blockIdx.y;
    const float4* s = reinterpret_cast<const float4*>(p.src[m]);
    float4*       d = reinterpret_cast<float4*>(p.dst[m]);
    int n4 = p.n[m] >> 2;
    for (int i = blockIdx.x * blockDim.x + threadIdx.x; i < n4;
         i += gridDim.x * blockDim.x) {
        float4 v = s[i];
        cvt4(v);
        d[i] = v;
    }
}

// ---------------------------------------------------------------------------
// Edge scatter: agg[dst] += h[src]; optionally counts deg[dst] (lane 0).
// ---------------------------------------------------------------------------
template<bool COUNT>
__global__ void __launch_bounds__(256)
scatter_kernel(const float* __restrict__ h, const int* __restrict__ src,
               const int* __restrict__ dst, float* __restrict__ agg,
               int* __restrict__ deg, int nE)
{
    int gid  = blockIdx.x * blockDim.x + threadIdx.x;
    int e    = gid >> 5;
    int lane = gid & 31;
    if (e >= nE) return;
    int s = __ldg(&src[e]);
    int d = __ldg(&dst[e]);
    if (COUNT && lane == 0) atomicAdd(&deg[d], 1);
    const float4* hp = reinterpret_cast<const float4*>(h + (size_t)s * HDIM) + lane * 2;
    float4*       ap = reinterpret_cast<float4*>(agg + (size_t)d * HDIM) + lane * 2;
    float4 v0 = hp[0];
    float4 v1 = hp[1];
    asm volatile("red.global.add.v4.f32 [%0], {%1,%2,%3,%4};"
                 :: "l"(ap), "f"(v0.x), "f"(v0.y), "f"(v0.z), "f"(v0.w) : "memory");
    asm volatile("red.global.add.v4.f32 [%0], {%1,%2,%3,%4};"
                 :: "l"(ap + 1), "f"(v1.x), "f"(v1.y), "f"(v1.z), "f"(v1.w) : "memory");
}

// ---------------------------------------------------------------------------
// In-place LayerNorm over 256 cols, one warp per row.
// ---------------------------------------------------------------------------
__global__ void __launch_bounds__(256)
ln_kernel(float* __restrict__ x, const float* __restrict__ g,
          const float* __restrict__ b, int M)
{
    int row  = blockIdx.x * 8 + (threadIdx.x >> 5);
    int lane = threadIdx.x & 31;
    if (row >= M) return;
    float* p = x + (size_t)row * HDIM + lane * 8;
    float4 v0 = *reinterpret_cast<const float4*>(p);
    float4 v1 = *reinterpret_cast<const float4*>(p + 4);
    float s  = v0.x + v0.y + v0.z + v0.w + v1.x + v1.y + v1.z + v1.w;
    float sq = v0.x*v0.x + v0.y*v0.y + v0.z*v0.z + v0.w*v0.w
             + v1.x*v1.x + v1.y*v1.y + v1.z*v1.z + v1.w*v1.w;
    #pragma unroll
    for (int m = 16; m > 0; m >>= 1) {
        s  += __shfl_xor_sync(0xffffffffu, s,  m);
        sq += __shfl_xor_sync(0xffffffffu, sq, m);
    }
    float mu   = s * (1.0f / 256.0f);
    float var  = sq * (1.0f / 256.0f) - mu * mu;
    float rstd = rsqrtf(var + 1e-5f);
    float4 g0 = *reinterpret_cast<const float4*>(g + lane * 8);
    float4 g1 = *reinterpret_cast<const float4*>(g + lane * 8 + 4);
    float4 b0 = *reinterpret_cast<const float4*>(b + lane * 8);
    float4 b1 = *reinterpret_cast<const float4*>(b + lane * 8 + 4);
    float4 o0, o1;
    o0.x = (v0.x - mu) * rstd * g0.x + b0.x;
    o0.y = (v0.y - mu) * rstd * g0.y + b0.y;
    o0.z = (v0.z - mu) * rstd * g0.z + b0.z;
    o0.w = (v0.w - mu) * rstd * g0.w + b0.w;
    o1.x = (v1.x - mu) * rstd * g1.x + b1.x;
    o1.y = (v1.y - mu) * rstd * g1.y + b1.y;
    o1.z = (v1.z - mu) * rstd * g1.z + b1.z;
    o1.w = (v1.w - mu) * rstd * g1.w + b1.w;
    *reinterpret_cast<float4*>(p)     = o0;
    *reinterpret_cast<float4*>(p + 4) = o1;
}

// ---------------------------------------------------------------------------
// 3-stage cp.async tf32 tensor-core GEMM.
//   C[M,256] = EPI( A1(*1/max(deg,1))@W1 (+ A2@W2) + bias )
// Inputs (A2, W1, W2, A1-for-non-SCALE1) are pre-rounded to tf32.
// SCALE1: A1 fragments scaled by invdeg + cvt.rna after LDS.
// Block 128x128 (grid.y=2), BK=32, 8 warps 2x4, warp tile 64x32.
// ---------------------------------------------------------------------------
constexpr int BM  = 128;
constexpr int BK  = 32;
constexpr int LDA = 36;
constexpr int LDB = 136;
constexpr int ST  = 3;

template<bool DS>
__device__ __forceinline__ void compute_tile(
    const float* __restrict__ as, const float* __restrict__ bs,
    float (&d)[4][4][4], const float (&sA)[4][2],
    int wm, int wn, int lq, int lr)
{
    #pragma unroll
    for (int ks = 0; ks < 4; ks++) {
        uint32_t af[4][4];
        #pragma unroll
        for (int i = 0; i < 4; i++) {
            int rm = wm * 64 + i * 16 + lq;
            float a0 = as[rm * LDA + ks * 8 + lr];
            float a1 = as[(rm + 8) * LDA + ks * 8 + lr];
            float a2 = as[rm * LDA + ks * 8 + lr + 4];
            float a3 = as[(rm + 8) * LDA + ks * 8 + lr + 4];
            if (DS) {
                a0 = to_tf32(a0 * sA[i][0]);
                a1 = to_tf32(a1 * sA[i][1]);
                a2 = to_tf32(a2 * sA[i][0]);
                a3 = to_tf32(a3 * sA[i][1]);
            }
            af[i][0] = __float_as_uint(a0);
            af[i][1] = __float_as_uint(a1);
            af[i][2] = __float_as_uint(a2);
            af[i][3] = __float_as_uint(a3);
        }
        uint32_t bf[4][2];
        #pragma unroll
        for (int j = 0; j < 4; j++) {
            int cb = wn * 32 + j * 8 + lq;
            bf[j][0] = __float_as_uint(bs[(ks * 8 + lr) * LDB + cb]);
            bf[j][1] = __float_as_uint(bs[(ks * 8 + lr + 4) * LDB + cb]);
        }
        #pragma unroll
        for (int i = 0; i < 4; i++)
            #pragma unroll
            for (int j = 0; j < 4; j++)
                mma_tf32(d[i][j][0], d[i][j][1], d[i][j][2], d[i][j][3],
                         af[i][0], af[i][1], af[i][2], af[i][3],
                         bf[j][0], bf[j][1]);
    }
}

template<int K, bool HAS_A2, bool SCALE1, int EPI>
__global__ void __launch_bounds__(256, 2)
gemm_tc(const float* __restrict__ A1, const int* __restrict__ deg,
        const float* __restrict__ A2,
        const float* __restrict__ W1, const float* __restrict__ W2,
        const float* __restrict__ bias,
        float* __restrict__ C, int M)
{
    __shared__ float a_s[ST][BM * LDA];
    __shared__ float b_s[ST][BK * LDB];

    constexpr int NIT = (HAS_A2 ? 2 : 1) * K / BK;

    const int tid  = threadIdx.x;
    const int lane = tid & 31;
    const int wid  = tid >> 5;
    const int wm   = wid >> 2;
    const int wn   = wid & 3;
    const int lq   = lane >> 2;
    const int lr   = lane & 3;
    const int row0 = blockIdx.x * BM;
    const int ncol0 = blockIdx.y * 128;

    const int ar  = tid >> 3;          // + u*32 : A row 0..127
    const int ac4 = (tid & 7) << 2;    // A col (float)
    const int bkr = tid >> 5;          // + u*8  : B k-row
    const int bc4 = (tid & 31) << 2;   // B col

    const uint32_t a_base = (uint32_t)__cvta_generic_to_shared(a_s);
    const uint32_t b_base = (uint32_t)__cvta_generic_to_shared(b_s);

    float d[4][4][4];
    #pragma unroll
    for (int i = 0; i < 4; i++)
        #pragma unroll
        for (int j = 0; j < 4; j++)
            #pragma unroll
            for (int q = 0; q < 4; q++)
                d[i][j][q] = 0.f;

    auto load_stage = [&](int kt, int buf) {
        int kk = kt * BK;
        const float* __restrict__ A = (HAS_A2 && kk >= K) ? A2 : A1;
        const float* __restrict__ W = (HAS_A2 && kk >= K) ? W2 : W1;
        const int k0 = HAS_A2 ? (kk & (K - 1)) : kk;
        uint32_t ab = a_base + (uint32_t)(buf * BM * LDA) * 4u;
        uint32_t bb = b_base + (uint32_t)(buf * BK * LDB) * 4u;
        #pragma unroll
        for (int u = 0; u < 4; u++) {
            int r  = ar + u * 32;
            int gr = row0 + r;
            int gc = gr < M ? gr : (M - 1);
            cp16(ab + (uint32_t)(r * LDA + ac4) * 4u,
                 A + (size_t)gc * K + k0 + ac4, gr < M);
            cp16(bb + (uint32_t)((bkr + u * 8) * LDB + bc4) * 4u,
                 W + (size_t)(k0 + bkr + u * 8) * HDIM + ncol0 + bc4, true);
        }
    };

    load_stage(0, 0);
    asm volatile("cp.async.commit_group;" ::: "memory");
    load_stage(1, 1);
    asm volatile("cp.async.commit_group;" ::: "memory");

    float sA[4][2];
    if (SCALE1) {
        #pragma unroll
        for (int i = 0; i < 4; i++) {
            int r0 = row0 + wm * 64 + i * 16 + lq;
            int r1 = r0 + 8;
            if (r0 >= M) r0 = M - 1;
            if (r1 >= M) r1 = M - 1;
            sA[i][0] = 1.0f / fmaxf((float)__ldg(&deg[r0]), 1.0f);
            sA[i][1] = 1.0f / fmaxf((float)__ldg(&deg[r1]), 1.0f);
        }
    } else {
        sA[0][0] = sA[0][1] = sA[1][0] = sA[1][1] = 1.f;
        sA[2][0] = sA[2][1] = sA[3][0] = sA[3][1] = 1.f;
    }

    #pragma unroll 1
    for (int kt = 0; kt < NIT; kt++) {
        asm volatile("cp.async.wait_group 1;" ::: "memory");
        __syncthreads();
        if (kt + 2 < NIT) load_stage(kt + 2, (kt + 2) % ST);
        asm volatile("cp.async.commit_group;" ::: "memory");

        const float* as = a_s[kt % ST];
        const float* bs = b_s[kt % ST];
        const bool doScale = SCALE1 && (kt * BK < K);
        if (doScale) compute_tile<true >(as, bs, d, sA, wm, wn, lq, lr);
        else         compute_tile<false>(as, bs, d, sA, wm, wn, lq, lr);
    }

    // ---- bias
    #pragma unroll
    for (int j = 0; j < 4; j++) {
        float2 b = *reinterpret_cast<const float2*>(bias + ncol0 + wn * 32 + j * 8 + 2 * lr);
        #pragma unroll
        for (int i = 0; i < 4; i++) {
            d[i][j][0] += b.x; d[i][j][1] += b.y;
            d[i][j][2] += b.x; d[i][j][3] += b.y;
        }
    }

    const int cbase = ncol0 + wn * 32;
    #pragma unroll
    for (int i = 0; i < 4; i++) {
        #pragma unroll
        for (int rr = 0; rr < 2; rr++) {
            int gr = row0 + wm * 64 + i * 16 + lq + rr * 8;
            if (gr < M) {
                #pragma unroll
                for (int j = 0; j < 4; j++) {
                    float2 v;
                    if (EPI == 0) {
                        // GELU + tf32 round (consumers read as pre-rounded A)
                        v.x = to_tf32(gelu_f(d[i][j][rr * 2 + 0]));
                        v.y = to_tf32(gelu_f(d[i][j][rr * 2 + 1]));
                    } else {
                        v.x = d[i][j][rr * 2 + 0];
                        v.y = d[i][j][rr * 2 + 1];
                    }
                    *reinterpret_cast<float2*>(
                        C + (size_t)gr * HDIM + cbase + j * 8 + 2 * lr) = v;
                }
            }
        }
    }
}

// ---------------------------------------------------------------------------
// kernel_launch
// ---------------------------------------------------------------------------
extern "C" void kernel_launch(void* const* d_in, const int* in_sizes, int n_in,
                              void* d_out, int out_size)
{
    const float* x_user    = (const float*)d_in[0];
    const float* x_item    = (const float*)d_in[1];
    const int*   ei_ui_src = (const int*)  d_in[2];
    const int*   ei_ui_dst = (const int*)  d_in[3];
    const int*   ei_iu_src = (const int*)  d_in[4];
    const int*   ei_iu_dst = (const int*)  d_in[5];
    const float* lin_user_W = (const float*)d_in[6];
    const float* lin_user_b = (const float*)d_in[7];
    const float* lin_item_W = (const float*)d_in[8];
    const float* lin_item_b = (const float*)d_in[9];
    const float* c0_ui_Wl = (const float*)d_in[10];
    const float* c0_ui_bl = (const float*)d_in[11];
    const float* c0_ui_Wr = (const float*)d_in[12];
    const float* c0_iu_Wl = (const float*)d_in[13];
    const float* c0_iu_bl = (const float*)d_in[14];
    const float* c0_iu_Wr = (const float*)d_in[15];
    const float* c1_ui_Wl = (const float*)d_in[16];
    const float* c1_ui_bl = (const float*)d_in[17];
    const float* c1_ui_Wr = (const float*)d_in[18];
    const float* c1_iu_Wl = (const float*)d_in[19];
    const float* c1_iu_bl = (const float*)d_in[20];
    const float* c1_iu_Wr = (const float*)d_in[21];
    const float* out_user_W = (const float*)d_in[22];
    const float* out_user_b = (const float*)d_in[23];
    const float* out_item_W = (const float*)d_in[24];
    const float* out_item_b = (const float*)d_in[25];
    const float* ln_user_g  = (const float*)d_in[26];
    const float* ln_user_b2 = (const float*)d_in[27];
    const float* ln_item_g  = (const float*)d_in[28];
    const float* ln_item_b2 = (const float*)d_in[29];

    float* out = (float*)d_out;
    const int nE = in_sizes[2];
    const int M  = NNODE;

    float *hu, *hi, *tu, *ti, *agg, *xu, *xi, *wts;
    int *deg;
    cudaGetSymbolAddress((void**)&hu,  g_hu);
    cudaGetSymbolAddress((void**)&hi,  g_hi);
    cudaGetSymbolAddress((void**)&tu,  g_tu);
    cudaGetSymbolAddress((void**)&ti,  g_ti);
    cudaGetSymbolAddress((void**)&agg, g_agg);
    cudaGetSymbolAddress((void**)&deg, g_deg);
    cudaGetSymbolAddress((void**)&xu,  g_xu);
    cudaGetSymbolAddress((void**)&xi,  g_xi);
    cudaGetSymbolAddress((void**)&wts, g_wts);

    float* agg0 = agg;
    float* agg1 = agg + (size_t)M * HDIM;
    int*   deg0 = deg;
    int*   deg1 = deg + M;

    // tf32 weight scratch layout
    float* w_lin_u = wts;                      // 32768
    float* w_lin_i = w_lin_u + 32768;          // 32768
    float* w_c[8];
    w_c[0] = w_lin_i + 32768;                  // c0_ui_Wl
    for (int i = 1; i < 8; i++) w_c[i] = w_c[i - 1] + 65536;
    float* w_out_u = w_c[7] + 65536;
    float* w_out_i = w_out_u + 65536;

    PtrPack pk;
    const float* wsrc[NPACK] = {
        lin_user_W, lin_item_W,
        c0_ui_Wl, c0_ui_Wr, c0_iu_Wl, c0_iu_Wr,
        c1_ui_Wl, c1_ui_Wr, c1_iu_Wl, c1_iu_Wr,
        out_user_W, out_item_W, x_user, x_item };
    float* wdst[NPACK] = {
        w_lin_u, w_lin_i,
        w_c[0], w_c[1], w_c[2], w_c[3], w_c[4], w_c[5], w_c[6], w_c[7],
        w_out_u, w_out_i, xu, xi };
    int wn[NPACK] = {
        32768, 32768,
        65536, 65536, 65536, 65536, 65536, 65536, 65536, 65536,
        65536, 65536, NNODE * DIN, NNODE * DIN };
    for (int i = 0; i < NPACK; i++) { pk.src[i] = wsrc[i]; pk.dst[i] = wdst[i]; pk.n[i] = wn[i]; }

    const size_t AGGB = 2 * (size_t)M * HDIM * sizeof(float);

    dim3 blk(256);
    dim3 grid_gemm((M + BM - 1) / BM, 2);
    dim3 grid_scat(((size_t)nE * 32 + 255) / 256);
    dim3 grid_ln((M + 7) / 8);
    dim3 grid_cvt(2048, NPACK);

    /* 1 */ cudaMemsetAsync(deg, 0, 2 * M * sizeof(int));
    /* 2 */ cudaMemsetAsync(agg, 0, AGGB);
    /* 3 */ cvt_pack_kernel<<<grid_cvt, blk>>>(pk);
    /* 4 */ gemm_tc<DIN, false, false, 0><<<grid_gemm, blk>>>(
                xu, nullptr, nullptr, w_lin_u, nullptr, lin_user_b, hu, M);
    /* 5 */ gemm_tc<DIN, false, false, 0><<<grid_gemm, blk>>>(
                xi, nullptr, nullptr, w_lin_i, nullptr, lin_item_b, hi, M);
    /* 6 */ scatter_kernel<true><<<grid_scat, blk>>>(hu, ei_ui_src, ei_ui_dst, agg0, deg0, nE);
    /* 7 */ gemm_tc<HDIM, true, true, 0><<<grid_gemm, blk>>>(
                agg0, deg0, hi, w_c[0], w_c[1], c0_ui_bl, ti, M);
    /* 8 */ scatter_kernel<true><<<grid_scat, blk>>>(hi, ei_iu_src, ei_iu_dst, agg1, deg1, nE);
    /* 9 */ gemm_tc<HDIM, true, true, 0><<<grid_gemm, blk>>>(
                agg1, deg1, hu, w_c[2], w_c[3], c0_iu_bl, tu, M);
    /*10 */ cudaMemsetAsync(agg, 0, AGGB);
    /*11 */ scatter_kernel<false><<<grid_scat, blk>>>(tu, ei_ui_src, ei_ui_dst, agg0, nullptr, nE);
    /*12 */ gemm_tc<HDIM, true, true, 0><<<grid_gemm, blk>>>(
                agg0, deg0, ti, w_c[4], w_c[5], c1_ui_bl, hi, M);
    /*13 */ scatter_kernel<false><<<grid_scat, blk>>>(ti, ei_iu_src, ei_iu_dst, agg1, nullptr, nE);
    /*14 */ gemm_tc<HDIM, true, true, 0><<<grid_gemm, blk>>>(
                agg1, deg1, tu, w_c[6], w_c[7], c1_iu_bl, hu, M);
    /*15 */ gemm_tc<HDIM, false, false, 1><<<grid_gemm, blk>>>(
                hu, nullptr, nullptr, w_out_u, nullptr, out_user_b, out, M);
    /*16 */ gemm_tc<HDIM, false, false, 1><<<grid_gemm, blk>>>(
                hi, nullptr, nullptr, w_out_i, nullptr, out_item_b,
                out + (size_t)M * HDIM, M);
    /*17 */ ln_kernel<<<grid_ln, blk>>>(out, ln_user_g, ln_user_b2, M);
    /*18 */ ln_kernel<<<grid_ln, blk>>>(out + (size_t)M * HDIM, ln_item_g, ln_item_b2, M);
}

// round 7
// speedup vs baseline: 1.7985x; 1.1275x over previous
#include <cuda_runtime.h>
#include <math.h>
#include <stdint.h>

#define NNODE 100000
#define EDGES 800000
#define DIN   128
#define HDIM  256

// ---------------------------------------------------------------------------
// Scratch (__device__ globals; no allocation allowed)
// ---------------------------------------------------------------------------
__device__ float g_hu [(size_t)NNODE * HDIM];
__device__ float g_hi [(size_t)NNODE * HDIM];
__device__ float g_tu [(size_t)NNODE * HDIM];
__device__ float g_ti [(size_t)NNODE * HDIM];
__device__ float g_agg[2 * (size_t)NNODE * HDIM];   // agg0 | agg1
__device__ int   g_deg[2 * NNODE];                  // deg0 (item) | deg1 (user)
__device__ float g_xu [(size_t)NNODE * DIN];        // tf32 x_user
__device__ float g_xi [(size_t)NNODE * DIN];        // tf32 x_item
__device__ float g_wts[2 * 32768 + 10 * 65536];     // tf32 weights

// ---------------------------------------------------------------------------
// Helpers
// ---------------------------------------------------------------------------
__device__ __forceinline__ float gelu_f(float x) {
    return 0.5f * x * (1.0f + erff(x * 0.70710678118654752f));
}
__device__ __forceinline__ float to_tf32(float x) {
    float r;
    asm("cvt.rna.tf32.f32 %0, %1;" : "=f"(r) : "f"(x));
    return r;
}
__device__ __forceinline__ void cvt4(float4& v) {
    v.x = to_tf32(v.x); v.y = to_tf32(v.y); v.z = to_tf32(v.z); v.w = to_tf32(v.w);
}
__device__ __forceinline__ void mma_tf32(float& d0, float& d1, float& d2, float& d3,
                                         uint32_t a0, uint32_t a1, uint32_t a2, uint32_t a3,
                                         uint32_t b0, uint32_t b1)
{
    asm volatile(
        "mma.sync.aligned.m16n8k8.row.col.f32.tf32.tf32.f32 "
        "{%0,%1,%2,%3}, {%4,%5,%6,%7}, {%8,%9}, {%0,%1,%2,%3};"
        : "+f"(d0), "+f"(d1), "+f"(d2), "+f"(d3)
        : "r"(a0), "r"(a1), "r"(a2), "r"(a3), "r"(b0), "r"(b1));
}
__device__ __forceinline__ void cp16(uint32_t dst, const void* src, bool pred) {
    int sz = pred ? 16 : 0;
    asm volatile("cp.async.ca.shared.global [%0], [%1], 16, %2;"
                 :: "r"(dst), "l"(src), "r"(sz));
}

// ---------------------------------------------------------------------------
// Pre-pass: convert weights + x to tf32 (grid.y selects tensor, grid-stride x)
// ---------------------------------------------------------------------------
#define NPACK 14
struct PtrPack {
    const float* src[NPACK];
    float*       dst[NPACK];
    int          n  [NPACK];
};

__global__ void __launch_bounds__(256)
cvt_pack_kernel(PtrPack p)
{
    int m = blockIdx.y;
    const float4* s = reinterpret_cast<const float4*>(p.src[m]);
    float4*       d = reinterpret_cast<float4*>(p.dst[m]);
    int n4 = p.n[m] >> 2;
    for (int i = blockIdx.x * blockDim.x + threadIdx.x; i < n4;
         i += gridDim.x * blockDim.x) {
        float4 v = s[i];
        cvt4(v);
        d[i] = v;
    }
}

// ---------------------------------------------------------------------------
// Column-split edge scatter: agg[dst][coff..coff+127] += h[src][coff..coff+127]
// One warp per edge, one float4 gather + one red.v4 per lane (512B per warp).
// Working set per pass (h half + agg half ~= 102MB) fits in the 126MB L2.
// ---------------------------------------------------------------------------
template<bool COUNT>
__global__ void __launch_bounds__(256)
scatter_half_kernel(const float* __restrict__ h, const int* __restrict__ src,
                    const int* __restrict__ dst, float* __restrict__ agg,
                    int* __restrict__ deg, int nE, int coff)
{
    int gid  = blockIdx.x * blockDim.x + threadIdx.x;
    int e    = gid >> 5;
    int lane = gid & 31;
    if (e >= nE) return;
    int s = __ldg(&src[e]);
    int d = __ldg(&dst[e]);
    if (COUNT && lane == 0) atomicAdd(&deg[d], 1);
    const float4* hp = reinterpret_cast<const float4*>(h + (size_t)s * HDIM + coff) + lane;
    float4*       ap = reinterpret_cast<float4*>(agg + (size_t)d * HDIM + coff) + lane;
    float4 v = *hp;
    asm volatile("red.global.add.v4.f32 [%0], {%1,%2,%3,%4};"
                 :: "l"(ap), "f"(v.x), "f"(v.y), "f"(v.z), "f"(v.w) : "memory");
}

// ---------------------------------------------------------------------------
// In-place LayerNorm over 256 cols, one warp per row.
// ---------------------------------------------------------------------------
__global__ void __launch_bounds__(256)
ln_kernel(float* __restrict__ x, const float* __restrict__ g,
          const float* __restrict__ b, int M)
{
    int row  = blockIdx.x * 8 + (threadIdx.x >> 5);
    int lane = threadIdx.x & 31;
    if (row >= M) return;
    float* p = x + (size_t)row * HDIM + lane * 8;
    float4 v0 = *reinterpret_cast<const float4*>(p);
    float4 v1 = *reinterpret_cast<const float4*>(p + 4);
    float s  = v0.x + v0.y + v0.z + v0.w + v1.x + v1.y + v1.z + v1.w;
    float sq = v0.x*v0.x + v0.y*v0.y + v0.z*v0.z + v0.w*v0.w
             + v1.x*v1.x + v1.y*v1.y + v1.z*v1.z + v1.w*v1.w;
    #pragma unroll
    for (int m = 16; m > 0; m >>= 1) {
        s  += __shfl_xor_sync(0xffffffffu, s,  m);
        sq += __shfl_xor_sync(0xffffffffu, sq, m);
    }
    float mu   = s * (1.0f / 256.0f);
    float var  = sq * (1.0f / 256.0f) - mu * mu;
    float rstd = rsqrtf(var + 1e-5f);
    float4 g0 = *reinterpret_cast<const float4*>(g + lane * 8);
    float4 g1 = *reinterpret_cast<const float4*>(g + lane * 8 + 4);
    float4 b0 = *reinterpret_cast<const float4*>(b + lane * 8);
    float4 b1 = *reinterpret_cast<const float4*>(b + lane * 8 + 4);
    float4 o0, o1;
    o0.x = (v0.x - mu) * rstd * g0.x + b0.x;
    o0.y = (v0.y - mu) * rstd * g0.y + b0.y;
    o0.z = (v0.z - mu) * rstd * g0.z + b0.z;
    o0.w = (v0.w - mu) * rstd * g0.w + b0.w;
    o1.x = (v1.x - mu) * rstd * g1.x + b1.x;
    o1.y = (v1.y - mu) * rstd * g1.y + b1.y;
    o1.z = (v1.z - mu) * rstd * g1.z + b1.z;
    o1.w = (v1.w - mu) * rstd * g1.w + b1.w;
    *reinterpret_cast<float4*>(p)     = o0;
    *reinterpret_cast<float4*>(p + 4) = o1;
}

// ---------------------------------------------------------------------------
// 3-stage cp.async tf32 tensor-core GEMM (unchanged from R6).
// ---------------------------------------------------------------------------
constexpr int BM  = 128;
constexpr int BK  = 32;
constexpr int LDA = 36;
constexpr int LDB = 136;
constexpr int ST  = 3;

template<bool DS>
__device__ __forceinline__ void compute_tile(
    const float* __restrict__ as, const float* __restrict__ bs,
    float (&d)[4][4][4], const float (&sA)[4][2],
    int wm, int wn, int lq, int lr)
{
    #pragma unroll
    for (int ks = 0; ks < 4; ks++) {
        uint32_t af[4][4];
        #pragma unroll
        for (int i = 0; i < 4; i++) {
            int rm = wm * 64 + i * 16 + lq;
            float a0 = as[rm * LDA + ks * 8 + lr];
            float a1 = as[(rm + 8) * LDA + ks * 8 + lr];
            float a2 = as[rm * LDA + ks * 8 + lr + 4];
            float a3 = as[(rm + 8) * LDA + ks * 8 + lr + 4];
            if (DS) {
                a0 = to_tf32(a0 * sA[i][0]);
                a1 = to_tf32(a1 * sA[i][1]);
                a2 = to_tf32(a2 * sA[i][0]);
                a3 = to_tf32(a3 * sA[i][1]);
            }
            af[i][0] = __float_as_uint(a0);
            af[i][1] = __float_as_uint(a1);
            af[i][2] = __float_as_uint(a2);
            af[i][3] = __float_as_uint(a3);
        }
        uint32_t bf[4][2];
        #pragma unroll
        for (int j = 0; j < 4; j++) {
            int cb = wn * 32 + j * 8 + lq;
            bf[j][0] = __float_as_uint(bs[(ks * 8 + lr) * LDB + cb]);
            bf[j][1] = __float_as_uint(bs[(ks * 8 + lr + 4) * LDB + cb]);
        }
        #pragma unroll
        for (int i = 0; i < 4; i++)
            #pragma unroll
            for (int j = 0; j < 4; j++)
                mma_tf32(d[i][j][0], d[i][j][1], d[i][j][2], d[i][j][3],
                         af[i][0], af[i][1], af[i][2], af[i][3],
                         bf[j][0], bf[j][1]);
    }
}

template<int K, bool HAS_A2, bool SCALE1, int EPI>
__global__ void __launch_bounds__(256, 2)
gemm_tc(const float* __restrict__ A1, const int* __restrict__ deg,
        const float* __restrict__ A2,
        const float* __restrict__ W1, const float* __restrict__ W2,
        const float* __restrict__ bias,
        float* __restrict__ C, int M)
{
    __shared__ float a_s[ST][BM * LDA];
    __shared__ float b_s[ST][BK * LDB];

    constexpr int NIT = (HAS_A2 ? 2 : 1) * K / BK;

    const int tid  = threadIdx.x;
    const int lane = tid & 31;
    const int wid  = tid >> 5;
    const int wm   = wid >> 2;
    const int wn   = wid & 3;
    const int lq   = lane >> 2;
    const int lr   = lane & 3;
    const int row0 = blockIdx.x * BM;
    const int ncol0 = blockIdx.y * 128;

    const int ar  = tid >> 3;
    const int ac4 = (tid & 7) << 2;
    const int bkr = tid >> 5;
    const int bc4 = (tid & 31) << 2;

    const uint32_t a_base = (uint32_t)__cvta_generic_to_shared(a_s);
    const uint32_t b_base = (uint32_t)__cvta_generic_to_shared(b_s);

    float d[4][4][4];
    #pragma unroll
    for (int i = 0; i < 4; i++)
        #pragma unroll
        for (int j = 0; j < 4; j++)
            #pragma unroll
            for (int q = 0; q < 4; q++)
                d[i][j][q] = 0.f;

    auto load_stage = [&](int kt, int buf) {
        int kk = kt * BK;
        const float* __restrict__ A = (HAS_A2 && kk >= K) ? A2 : A1;
        const float* __restrict__ W = (HAS_A2 && kk >= K) ? W2 : W1;
        const int k0 = HAS_A2 ? (kk & (K - 1)) : kk;
        uint32_t ab = a_base + (uint32_t)(buf * BM * LDA) * 4u;
        uint32_t bb = b_base + (uint32_t)(buf * BK * LDB) * 4u;
        #pragma unroll
        for (int u = 0; u < 4; u++) {
            int r  = ar + u * 32;
            int gr = row0 + r;
            int gc = gr < M ? gr : (M - 1);
            cp16(ab + (uint32_t)(r * LDA + ac4) * 4u,
                 A + (size_t)gc * K + k0 + ac4, gr < M);
            cp16(bb + (uint32_t)((bkr + u * 8) * LDB + bc4) * 4u,
                 W + (size_t)(k0 + bkr + u * 8) * HDIM + ncol0 + bc4, true);
        }
    };

    load_stage(0, 0);
    asm volatile("cp.async.commit_group;" ::: "memory");
    load_stage(1, 1);
    asm volatile("cp.async.commit_group;" ::: "memory");

    float sA[4][2];
    if (SCALE1) {
        #pragma unroll
        for (int i = 0; i < 4; i++) {
            int r0 = row0 + wm * 64 + i * 16 + lq;
            int r1 = r0 + 8;
            if (r0 >= M) r0 = M - 1;
            if (r1 >= M) r1 = M - 1;
            sA[i][0] = 1.0f / fmaxf((float)__ldg(&deg[r0]), 1.0f);
            sA[i][1] = 1.0f / fmaxf((float)__ldg(&deg[r1]), 1.0f);
        }
    } else {
        sA[0][0] = sA[0][1] = sA[1][0] = sA[1][1] = 1.f;
        sA[2][0] = sA[2][1] = sA[3][0] = sA[3][1] = 1.f;
    }

    #pragma unroll 1
    for (int kt = 0; kt < NIT; kt++) {
        asm volatile("cp.async.wait_group 1;" ::: "memory");
        __syncthreads();
        if (kt + 2 < NIT) load_stage(kt + 2, (kt + 2) % ST);
        asm volatile("cp.async.commit_group;" ::: "memory");

        const float* as = a_s[kt % ST];
        const float* bs = b_s[kt % ST];
        const bool doScale = SCALE1 && (kt * BK < K);
        if (doScale) compute_tile<true >(as, bs, d, sA, wm, wn, lq, lr);
        else         compute_tile<false>(as, bs, d, sA, wm, wn, lq, lr);
    }

    #pragma unroll
    for (int j = 0; j < 4; j++) {
        float2 b = *reinterpret_cast<const float2*>(bias + ncol0 + wn * 32 + j * 8 + 2 * lr);
        #pragma unroll
        for (int i = 0; i < 4; i++) {
            d[i][j][0] += b.x; d[i][j][1] += b.y;
            d[i][j][2] += b.x; d[i][j][3] += b.y;
        }
    }

    const int cbase = ncol0 + wn * 32;
    #pragma unroll
    for (int i = 0; i < 4; i++) {
        #pragma unroll
        for (int rr = 0; rr < 2; rr++) {
            int gr = row0 + wm * 64 + i * 16 + lq + rr * 8;
            if (gr < M) {
                #pragma unroll
                for (int j = 0; j < 4; j++) {
                    float2 v;
                    if (EPI == 0) {
                        v.x = to_tf32(gelu_f(d[i][j][rr * 2 + 0]));
                        v.y = to_tf32(gelu_f(d[i][j][rr * 2 + 1]));
                    } else {
                        v.x = d[i][j][rr * 2 + 0];
                        v.y = d[i][j][rr * 2 + 1];
                    }
                    *reinterpret_cast<float2*>(
                        C + (size_t)gr * HDIM + cbase + j * 8 + 2 * lr) = v;
                }
            }
        }
    }
}

// ---------------------------------------------------------------------------
// kernel_launch
// ---------------------------------------------------------------------------
extern "C" void kernel_launch(void* const* d_in, const int* in_sizes, int n_in,
                              void* d_out, int out_size)
{
    const float* x_user    = (const float*)d_in[0];
    const float* x_item    = (const float*)d_in[1];
    const int*   ei_ui_src = (const int*)  d_in[2];
    const int*   ei_ui_dst = (const int*)  d_in[3];
    const int*   ei_iu_src = (const int*)  d_in[4];
    const int*   ei_iu_dst = (const int*)  d_in[5];
    const float* lin_user_W = (const float*)d_in[6];
    const float* lin_user_b = (const float*)d_in[7];
    const float* lin_item_W = (const float*)d_in[8];
    const float* lin_item_b = (const float*)d_in[9];
    const float* c0_ui_Wl = (const float*)d_in[10];
    const float* c0_ui_bl = (const float*)d_in[11];
    const float* c0_ui_Wr = (const float*)d_in[12];
    const float* c0_iu_Wl = (const float*)d_in[13];
    const float* c0_iu_bl = (const float*)d_in[14];
    const float* c0_iu_Wr = (const float*)d_in[15];
    const float* c1_ui_Wl = (const float*)d_in[16];
    const float* c1_ui_bl = (const float*)d_in[17];
    const float* c1_ui_Wr = (const float*)d_in[18];
    const float* c1_iu_Wl = (const float*)d_in[19];
    const float* c1_iu_bl = (const float*)d_in[20];
    const float* c1_iu_Wr = (const float*)d_in[21];
    const float* out_user_W = (const float*)d_in[22];
    const float* out_user_b = (const float*)d_in[23];
    const float* out_item_W = (const float*)d_in[24];
    const float* out_item_b = (const float*)d_in[25];
    const float* ln_user_g  = (const float*)d_in[26];
    const float* ln_user_b2 = (const float*)d_in[27];
    const float* ln_item_g  = (const float*)d_in[28];
    const float* ln_item_b2 = (const float*)d_in[29];

    float* out = (float*)d_out;
    const int nE = in_sizes[2];
    const int M  = NNODE;

    float *hu, *hi, *tu, *ti, *agg, *xu, *xi, *wts;
    int *deg;
    cudaGetSymbolAddress((void**)&hu,  g_hu);
    cudaGetSymbolAddress((void**)&hi,  g_hi);
    cudaGetSymbolAddress((void**)&tu,  g_tu);
    cudaGetSymbolAddress((void**)&ti,  g_ti);
    cudaGetSymbolAddress((void**)&agg, g_agg);
    cudaGetSymbolAddress((void**)&deg, g_deg);
    cudaGetSymbolAddress((void**)&xu,  g_xu);
    cudaGetSymbolAddress((void**)&xi,  g_xi);
    cudaGetSymbolAddress((void**)&wts, g_wts);

    float* agg0 = agg;
    float* agg1 = agg + (size_t)M * HDIM;
    int*   deg0 = deg;
    int*   deg1 = deg + M;

    float* w_lin_u = wts;
    float* w_lin_i = w_lin_u + 32768;
    float* w_c[8];
    w_c[0] = w_lin_i + 32768;
    for (int i = 1; i < 8; i++) w_c[i] = w_c[i - 1] + 65536;
    float* w_out_u = w_c[7] + 65536;
    float* w_out_i = w_out_u + 65536;

    PtrPack pk;
    const float* wsrc[NPACK] = {
        lin_user_W, lin_item_W,
        c0_ui_Wl, c0_ui_Wr, c0_iu_Wl, c0_iu_Wr,
        c1_ui_Wl, c1_ui_Wr, c1_iu_Wl, c1_iu_Wr,
        out_user_W, out_item_W, x_user, x_item };
    float* wdst[NPACK] = {
        w_lin_u, w_lin_i,
        w_c[0], w_c[1], w_c[2], w_c[3], w_c[4], w_c[5], w_c[6], w_c[7],
        w_out_u, w_out_i, xu, xi };
    int wnn[NPACK] = {
        32768, 32768,
        65536, 65536, 65536, 65536, 65536, 65536, 65536, 65536,
        65536, 65536, NNODE * DIN, NNODE * DIN };
    for (int i = 0; i < NPACK; i++) { pk.src[i] = wsrc[i]; pk.dst[i] = wdst[i]; pk.n[i] = wnn[i]; }

    const size_t AGGB = 2 * (size_t)M * HDIM * sizeof(float);

    dim3 blk(256);
    dim3 grid_gemm((M + BM - 1) / BM, 2);
    dim3 grid_scat(((size_t)nE * 32 + 255) / 256);
    dim3 grid_ln((M + 7) / 8);
    dim3 grid_cvt(2048, NPACK);

    // scatter both halves for one aggregation
    auto scat2 = [&](const float* h, const int* src, const int* dst,
                     float* a, int* dg, bool count) {
        if (count) {
            scatter_half_kernel<true ><<<grid_scat, blk>>>(h, src, dst, a, dg, nE, 0);
        } else {
            scatter_half_kernel<false><<<grid_scat, blk>>>(h, src, dst, a, nullptr, nE, 0);
        }
        scatter_half_kernel<false><<<grid_scat, blk>>>(h, src, dst, a, nullptr, nE, 128);
    };

    /* 1 */ cudaMemsetAsync(deg, 0, 2 * M * sizeof(int));
    /* 2 */ cudaMemsetAsync(agg, 0, AGGB);
    /* 3 */ cvt_pack_kernel<<<grid_cvt, blk>>>(pk);
    /* 4 */ gemm_tc<DIN, false, false, 0><<<grid_gemm, blk>>>(
                xu, nullptr, nullptr, w_lin_u, nullptr, lin_user_b, hu, M);
    /* 5 */ gemm_tc<DIN, false, false, 0><<<grid_gemm, blk>>>(
                xi, nullptr, nullptr, w_lin_i, nullptr, lin_item_b, hi, M);
    /* 6,7 */ scat2(hu, ei_ui_src, ei_ui_dst, agg0, deg0, true);   // #6 profiled
    /* 8 */ gemm_tc<HDIM, true, true, 0><<<grid_gemm, blk>>>(
                agg0, deg0, hi, w_c[0], w_c[1], c0_ui_bl, ti, M);
    /* 9,10 */ scat2(hi, ei_iu_src, ei_iu_dst, agg1, deg1, true);
    /*11 */ gemm_tc<HDIM, true, true, 0><<<grid_gemm, blk>>>(
                agg1, deg1, hu, w_c[2], w_c[3], c0_iu_bl, tu, M);
    /*12 */ cudaMemsetAsync(agg, 0, AGGB);
    /*13,14*/ scat2(tu, ei_ui_src, ei_ui_dst, agg0, nullptr, false);
    /*15 */ gemm_tc<HDIM, true, true, 0><<<grid_gemm, blk>>>(
                agg0, deg0, ti, w_c[4], w_c[5], c1_ui_bl, hi, M);
    /*16,17*/ scat2(ti, ei_iu_src, ei_iu_dst, agg1, nullptr, false);
    /*18 */ gemm_tc<HDIM, true, true, 0><<<grid_gemm, blk>>>(
                agg1, deg1, tu, w_c[6], w_c[7], c1_iu_bl, hu, M);
    /*19 */ gemm_tc<HDIM, false, false, 1><<<grid_gemm, blk>>>(
                hu, nullptr, nullptr, w_out_u, nullptr, out_user_b, out, M);
    /*20 */ gemm_tc<HDIM, false, false, 1><<<grid_gemm, blk>>>(
                hi, nullptr, nullptr, w_out_i, nullptr, out_item_b,
                out + (size_t)M * HDIM, M);
    /*21 */ ln_kernel<<<grid_ln, blk>>>(out, ln_user_g, ln_user_b2, M);
    /*22 */ ln_kernel<<<grid_ln, blk>>>(out + (size_t)M * HDIM, ln_item_g, ln_item_b2, M);
}

// round 8
// speedup vs baseline: 2.0730x; 1.1527x over previous
#include <cuda_runtime.h>
#include <math.h>
#include <stdint.h>

#define NNODE 100000
#define EDGES 800000
#define DIN   128
#define HDIM  256

// ---------------------------------------------------------------------------
// Scratch (__device__ globals; no allocation allowed)
// ---------------------------------------------------------------------------
__device__ float g_hu [(size_t)NNODE * HDIM];
__device__ float g_hi [(size_t)NNODE * HDIM];
__device__ float g_tu [(size_t)NNODE * HDIM];
__device__ float g_ti [(size_t)NNODE * HDIM];
__device__ float g_agg[2 * (size_t)NNODE * HDIM];   // agg0 | agg1
__device__ int   g_deg[2 * NNODE];                  // deg0 (item) | deg1 (user)
__device__ int   g_off[2 * NNODE];                  // CSR row offsets
__device__ int   g_cur[2 * NNODE];                  // build cursors
__device__ int   g_csr[2 * EDGES];                  // sorted src indices
__device__ float g_xu [(size_t)NNODE * DIN];        // tf32 x_user
__device__ float g_xi [(size_t)NNODE * DIN];        // tf32 x_item
__device__ float g_wts[2 * 32768 + 10 * 65536];     // tf32 weights

// ---------------------------------------------------------------------------
// Helpers
// ---------------------------------------------------------------------------
__device__ __forceinline__ float gelu_f(float x) {
    return 0.5f * x * (1.0f + erff(x * 0.70710678118654752f));
}
__device__ __forceinline__ float to_tf32(float x) {
    float r;
    asm("cvt.rna.tf32.f32 %0, %1;" : "=f"(r) : "f"(x));
    return r;
}
__device__ __forceinline__ void cvt4(float4& v) {
    v.x = to_tf32(v.x); v.y = to_tf32(v.y); v.z = to_tf32(v.z); v.w = to_tf32(v.w);
}
__device__ __forceinline__ void mma_tf32(float& d0, float& d1, float& d2, float& d3,
                                         uint32_t a0, uint32_t a1, uint32_t a2, uint32_t a3,
                                         uint32_t b0, uint32_t b1)
{
    asm volatile(
        "mma.sync.aligned.m16n8k8.row.col.f32.tf32.tf32.f32 "
        "{%0,%1,%2,%3}, {%4,%5,%6,%7}, {%8,%9}, {%0,%1,%2,%3};"
        : "+f"(d0), "+f"(d1), "+f"(d2), "+f"(d3)
        : "r"(a0), "r"(a1), "r"(a2), "r"(a3), "r"(b0), "r"(b1));
}
__device__ __forceinline__ void cp16(uint32_t dst, const void* src, bool pred) {
    int sz = pred ? 16 : 0;
    asm volatile("cp.async.ca.shared.global [%0], [%1], 16, %2;"
                 :: "r"(dst), "l"(src), "r"(sz));
}

// ---------------------------------------------------------------------------
// Pre-pass: convert weights + x to tf32
// ---------------------------------------------------------------------------
#define NPACK 14
struct PtrPack {
    const float* src[NPACK];
    float*       dst[NPACK];
    int          n  [NPACK];
};

__global__ void __launch_bounds__(256)
cvt_pack_kernel(PtrPack p)
{
    int m = blockIdx.y;
    const float4* s = reinterpret_cast<const float4*>(p.src[m]);
    float4*       d = reinterpret_cast<float4*>(p.dst[m]);
    int n4 = p.n[m] >> 2;
    for (int i = blockIdx.x * blockDim.x + threadIdx.x; i < n4;
         i += gridDim.x * blockDim.x) {
        float4 v = s[i];
        cvt4(v);
        d[i] = v;
    }
}

// ---------------------------------------------------------------------------
// Degree count
// ---------------------------------------------------------------------------
__global__ void __launch_bounds__(256)
deg_kernel(const int* __restrict__ dst, int* __restrict__ deg, int nE) {
    int i = blockIdx.x * blockDim.x + threadIdx.x;
    if (i < nE) atomicAdd(&deg[dst[i]], 1);
}

// ---------------------------------------------------------------------------
// Single-block exclusive scan of deg[0..n) -> off, cursor
// ---------------------------------------------------------------------------
__global__ void __launch_bounds__(1024)
scan_kernel(const int* __restrict__ deg, int* __restrict__ off,
            int* __restrict__ cur, int n)
{
    __shared__ int carry;
    __shared__ int wsum[32];
    const int tid  = threadIdx.x;
    const int lane = tid & 31;
    const int wid  = tid >> 5;
    if (tid == 0) carry = 0;
    __syncthreads();
    for (int base = 0; base < n; base += 1024) {
        int i = base + tid;
        int v = (i < n) ? deg[i] : 0;
        int x = v;
        #pragma unroll
        for (int s = 1; s < 32; s <<= 1) {
            int y = __shfl_up_sync(0xffffffffu, x, s);
            if (lane >= s) x += y;
        }
        if (lane == 31) wsum[wid] = x;
        __syncthreads();
        if (wid == 0) {
            int ws = wsum[lane];
            #pragma unroll
            for (int s = 1; s < 32; s <<= 1) {
                int y = __shfl_up_sync(0xffffffffu, ws, s);
                if (lane >= s) ws += y;
            }
            wsum[lane] = ws;
        }
        __syncthreads();
        int excl = x - v + (wid > 0 ? wsum[wid - 1] : 0) + carry;
        if (i < n) { off[i] = excl; cur[i] = excl; }
        __syncthreads();
        if (tid == 0) carry += wsum[31];
        __syncthreads();
    }
}

// ---------------------------------------------------------------------------
// CSR build: csr[cursor[dst[e]]++] = src[e]
// ---------------------------------------------------------------------------
__global__ void __launch_bounds__(256)
csr_build_kernel(const int* __restrict__ src, const int* __restrict__ dst,
                 int* __restrict__ cur, int* __restrict__ csr, int nE)
{
    int e = blockIdx.x * blockDim.x + threadIdx.x;
    if (e >= nE) return;
    int p = atomicAdd(&cur[dst[e]], 1);
    csr[p] = src[e];
}

// ---------------------------------------------------------------------------
// CSR aggregation (half of columns): one warp per node.
//   agg[node][coff+lane*4 .. +3] = tf32( mean_{s in N(node)} h[s][...] )
// Gather-only: no atomics, single write, no agg memset needed.
// ---------------------------------------------------------------------------
__global__ void __launch_bounds__(256)
agg_csr_kernel(const float* __restrict__ h, const int* __restrict__ csr,
               const int* __restrict__ off, const int* __restrict__ deg,
               float* __restrict__ agg, int n, int coff)
{
    int node = blockIdx.x * 8 + (threadIdx.x >> 5);
    if (node >= n) return;
    int lane = threadIdx.x & 31;
    int o = __ldg(&off[node]);
    int d = __ldg(&deg[node]);
    float4 acc = make_float4(0.f, 0.f, 0.f, 0.f);
    int j = 0;
    for (; j + 4 <= d; j += 4) {
        int s0 = __ldg(&csr[o + j]);
        int s1 = __ldg(&csr[o + j + 1]);
        int s2 = __ldg(&csr[o + j + 2]);
        int s3 = __ldg(&csr[o + j + 3]);
        float4 v0 = *reinterpret_cast<const float4*>(h + (size_t)s0 * HDIM + coff + lane * 4);
        float4 v1 = *reinterpret_cast<const float4*>(h + (size_t)s1 * HDIM + coff + lane * 4);
        float4 v2 = *reinterpret_cast<const float4*>(h + (size_t)s2 * HDIM + coff + lane * 4);
        float4 v3 = *reinterpret_cast<const float4*>(h + (size_t)s3 * HDIM + coff + lane * 4);
        acc.x += v0.x + v1.x + v2.x + v3.x;
        acc.y += v0.y + v1.y + v2.y + v3.y;
        acc.z += v0.z + v1.z + v2.z + v3.z;
        acc.w += v0.w + v1.w + v2.w + v3.w;
    }
    for (; j < d; j++) {
        int s = __ldg(&csr[o + j]);
        float4 v = *reinterpret_cast<const float4*>(h + (size_t)s * HDIM + coff + lane * 4);
        acc.x += v.x; acc.y += v.y; acc.z += v.z; acc.w += v.w;
    }
    float sc = 1.0f / fmaxf((float)d, 1.0f);
    float4 r;
    r.x = to_tf32(acc.x * sc);
    r.y = to_tf32(acc.y * sc);
    r.z = to_tf32(acc.z * sc);
    r.w = to_tf32(acc.w * sc);
    *reinterpret_cast<float4*>(agg + (size_t)node * HDIM + coff + lane * 4) = r;
}

// ---------------------------------------------------------------------------
// In-place LayerNorm over 256 cols, one warp per row.
// ---------------------------------------------------------------------------
__global__ void __launch_bounds__(256)
ln_kernel(float* __restrict__ x, const float* __restrict__ g,
          const float* __restrict__ b, int M)
{
    int row  = blockIdx.x * 8 + (threadIdx.x >> 5);
    int lane = threadIdx.x & 31;
    if (row >= M) return;
    float* p = x + (size_t)row * HDIM + lane * 8;
    float4 v0 = *reinterpret_cast<const float4*>(p);
    float4 v1 = *reinterpret_cast<const float4*>(p + 4);
    float s  = v0.x + v0.y + v0.z + v0.w + v1.x + v1.y + v1.z + v1.w;
    float sq = v0.x*v0.x + v0.y*v0.y + v0.z*v0.z + v0.w*v0.w
             + v1.x*v1.x + v1.y*v1.y + v1.z*v1.z + v1.w*v1.w;
    #pragma unroll
    for (int m = 16; m > 0; m >>= 1) {
        s  += __shfl_xor_sync(0xffffffffu, s,  m);
        sq += __shfl_xor_sync(0xffffffffu, sq, m);
    }
    float mu   = s * (1.0f / 256.0f);
    float var  = sq * (1.0f / 256.0f) - mu * mu;
    float rstd = rsqrtf(var + 1e-5f);
    float4 g0 = *reinterpret_cast<const float4*>(g + lane * 8);
    float4 g1 = *reinterpret_cast<const float4*>(g + lane * 8 + 4);
    float4 b0 = *reinterpret_cast<const float4*>(b + lane * 8);
    float4 b1 = *reinterpret_cast<const float4*>(b + lane * 8 + 4);
    float4 o0, o1;
    o0.x = (v0.x - mu) * rstd * g0.x + b0.x;
    o0.y = (v0.y - mu) * rstd * g0.y + b0.y;
    o0.z = (v0.z - mu) * rstd * g0.z + b0.z;
    o0.w = (v0.w - mu) * rstd * g0.w + b0.w;
    o1.x = (v1.x - mu) * rstd * g1.x + b1.x;
    o1.y = (v1.y - mu) * rstd * g1.y + b1.y;
    o1.z = (v1.z - mu) * rstd * g1.z + b1.z;
    o1.w = (v1.w - mu) * rstd * g1.w + b1.w;
    *reinterpret_cast<float4*>(p)     = o0;
    *reinterpret_cast<float4*>(p + 4) = o1;
}

// ---------------------------------------------------------------------------
// 3-stage cp.async tf32 tensor-core GEMM (all inputs pre-rounded to tf32).
//   C[M,256] = EPI( A1@W1 (+ A2@W2) + bias )
// ---------------------------------------------------------------------------
constexpr int BM  = 128;
constexpr int BK  = 32;
constexpr int LDA = 36;
constexpr int LDB = 136;
constexpr int ST  = 3;

__device__ __forceinline__ void compute_tile(
    const float* __restrict__ as, const float* __restrict__ bs,
    float (&d)[4][4][4], int wm, int wn, int lq, int lr)
{
    #pragma unroll
    for (int ks = 0; ks < 4; ks++) {
        uint32_t af[4][4];
        #pragma unroll
        for (int i = 0; i < 4; i++) {
            int rm = wm * 64 + i * 16 + lq;
            af[i][0] = __float_as_uint(as[rm * LDA + ks * 8 + lr]);
            af[i][1] = __float_as_uint(as[(rm + 8) * LDA + ks * 8 + lr]);
            af[i][2] = __float_as_uint(as[rm * LDA + ks * 8 + lr + 4]);
            af[i][3] = __float_as_uint(as[(rm + 8) * LDA + ks * 8 + lr + 4]);
        }
        uint32_t bf[4][2];
        #pragma unroll
        for (int j = 0; j < 4; j++) {
            int cb = wn * 32 + j * 8 + lq;
            bf[j][0] = __float_as_uint(bs[(ks * 8 + lr) * LDB + cb]);
            bf[j][1] = __float_as_uint(bs[(ks * 8 + lr + 4) * LDB + cb]);
        }
        #pragma unroll
        for (int i = 0; i < 4; i++)
            #pragma unroll
            for (int j = 0; j < 4; j++)
                mma_tf32(d[i][j][0], d[i][j][1], d[i][j][2], d[i][j][3],
                         af[i][0], af[i][1], af[i][2], af[i][3],
                         bf[j][0], bf[j][1]);
    }
}

template<int K, bool HAS_A2, int EPI>
__global__ void __launch_bounds__(256, 2)
gemm_tc(const float* __restrict__ A1, const float* __restrict__ A2,
        const float* __restrict__ W1, const float* __restrict__ W2,
        const float* __restrict__ bias,
        float* __restrict__ C, int M)
{
    __shared__ float a_s[ST][BM * LDA];
    __shared__ float b_s[ST][BK * LDB];

    constexpr int NIT = (HAS_A2 ? 2 : 1) * K / BK;

    const int tid  = threadIdx.x;
    const int lane = tid & 31;
    const int wid  = tid >> 5;
    const int wm   = wid >> 2;
    const int wn   = wid & 3;
    const int lq   = lane >> 2;
    const int lr   = lane & 3;
    const int row0 = blockIdx.x * BM;
    const int ncol0 = blockIdx.y * 128;

    const int ar  = tid >> 3;
    const int ac4 = (tid & 7) << 2;
    const int bkr = tid >> 5;
    const int bc4 = (tid & 31) << 2;

    const uint32_t a_base = (uint32_t)__cvta_generic_to_shared(a_s);
    const uint32_t b_base = (uint32_t)__cvta_generic_to_shared(b_s);

    float d[4][4][4];
    #pragma unroll
    for (int i = 0; i < 4; i++)
        #pragma unroll
        for (int j = 0; j < 4; j++)
            #pragma unroll
            for (int q = 0; q < 4; q++)
                d[i][j][q] = 0.f;

    auto load_stage = [&](int kt, int buf) {
        int kk = kt * BK;
        const float* __restrict__ A = (HAS_A2 && kk >= K) ? A2 : A1;
        const float* __restrict__ W = (HAS_A2 && kk >= K) ? W2 : W1;
        const int k0 = HAS_A2 ? (kk & (K - 1)) : kk;
        uint32_t ab = a_base + (uint32_t)(buf * BM * LDA) * 4u;
        uint32_t bb = b_base + (uint32_t)(buf * BK * LDB) * 4u;
        #pragma unroll
        for (int u = 0; u < 4; u++) {
            int r  = ar + u * 32;
            int gr = row0 + r;
            int gc = gr < M ? gr : (M - 1);
            cp16(ab + (uint32_t)(r * LDA + ac4) * 4u,
                 A + (size_t)gc * K + k0 + ac4, gr < M);
            cp16(bb + (uint32_t)((bkr + u * 8) * LDB + bc4) * 4u,
                 W + (size_t)(k0 + bkr + u * 8) * HDIM + ncol0 + bc4, true);
        }
    };

    load_stage(0, 0);
    asm volatile("cp.async.commit_group;" ::: "memory");
    load_stage(1, 1);
    asm volatile("cp.async.commit_group;" ::: "memory");

    #pragma unroll 1
    for (int kt = 0; kt < NIT; kt++) {
        asm volatile("cp.async.wait_group 1;" ::: "memory");
        __syncthreads();
        if (kt + 2 < NIT) load_stage(kt + 2, (kt + 2) % ST);
        asm volatile("cp.async.commit_group;" ::: "memory");
        compute_tile(a_s[kt % ST], b_s[kt % ST], d, wm, wn, lq, lr);
    }

    #pragma unroll
    for (int j = 0; j < 4; j++) {
        float2 b = *reinterpret_cast<const float2*>(bias + ncol0 + wn * 32 + j * 8 + 2 * lr);
        #pragma unroll
        for (int i = 0; i < 4; i++) {
            d[i][j][0] += b.x; d[i][j][1] += b.y;
            d[i][j][2] += b.x; d[i][j][3] += b.y;
        }
    }

    const int cbase = ncol0 + wn * 32;
    #pragma unroll
    for (int i = 0; i < 4; i++) {
        #pragma unroll
        for (int rr = 0; rr < 2; rr++) {
            int gr = row0 + wm * 64 + i * 16 + lq + rr * 8;
            if (gr < M) {
                #pragma unroll
                for (int j = 0; j < 4; j++) {
                    float2 v;
                    if (EPI == 0) {
                        v.x = to_tf32(gelu_f(d[i][j][rr * 2 + 0]));
                        v.y = to_tf32(gelu_f(d[i][j][rr * 2 + 1]));
                    } else {
                        v.x = d[i][j][rr * 2 + 0];
                        v.y = d[i][j][rr * 2 + 1];
                    }
                    *reinterpret_cast<float2*>(
                        C + (size_t)gr * HDIM + cbase + j * 8 + 2 * lr) = v;
                }
            }
        }
    }
}

// ---------------------------------------------------------------------------
// kernel_launch
// ---------------------------------------------------------------------------
extern "C" void kernel_launch(void* const* d_in, const int* in_sizes, int n_in,
                              void* d_out, int out_size)
{
    const float* x_user    = (const float*)d_in[0];
    const float* x_item    = (const float*)d_in[1];
    const int*   ei_ui_src = (const int*)  d_in[2];
    const int*   ei_ui_dst = (const int*)  d_in[3];
    const int*   ei_iu_src = (const int*)  d_in[4];
    const int*   ei_iu_dst = (const int*)  d_in[5];
    const float* lin_user_W = (const float*)d_in[6];
    const float* lin_user_b = (const float*)d_in[7];
    const float* lin_item_W = (const float*)d_in[8];
    const float* lin_item_b = (const float*)d_in[9];
    const float* c0_ui_Wl = (const float*)d_in[10];
    const float* c0_ui_bl = (const float*)d_in[11];
    const float* c0_ui_Wr = (const float*)d_in[12];
    const float* c0_iu_Wl = (const float*)d_in[13];
    const float* c0_iu_bl = (const float*)d_in[14];
    const float* c0_iu_Wr = (const float*)d_in[15];
    const float* c1_ui_Wl = (const float*)d_in[16];
    const float* c1_ui_bl = (const float*)d_in[17];
    const float* c1_ui_Wr = (const float*)d_in[18];
    const float* c1_iu_Wl = (const float*)d_in[19];
    const float* c1_iu_bl = (const float*)d_in[20];
    const float* c1_iu_Wr = (const float*)d_in[21];
    const float* out_user_W = (const float*)d_in[22];
    const float* out_user_b = (const float*)d_in[23];
    const float* out_item_W = (const float*)d_in[24];
    const float* out_item_b = (const float*)d_in[25];
    const float* ln_user_g  = (const float*)d_in[26];
    const float* ln_user_b2 = (const float*)d_in[27];
    const float* ln_item_g  = (const float*)d_in[28];
    const float* ln_item_b2 = (const float*)d_in[29];

    float* out = (float*)d_out;
    const int nE = in_sizes[2];
    const int M  = NNODE;

    float *hu, *hi, *tu, *ti, *agg, *xu, *xi, *wts;
    int *deg, *off, *cur, *csr;
    cudaGetSymbolAddress((void**)&hu,  g_hu);
    cudaGetSymbolAddress((void**)&hi,  g_hi);
    cudaGetSymbolAddress((void**)&tu,  g_tu);
    cudaGetSymbolAddress((void**)&ti,  g_ti);
    cudaGetSymbolAddress((void**)&agg, g_agg);
    cudaGetSymbolAddress((void**)&deg, g_deg);
    cudaGetSymbolAddress((void**)&off, g_off);
    cudaGetSymbolAddress((void**)&cur, g_cur);
    cudaGetSymbolAddress((void**)&csr, g_csr);
    cudaGetSymbolAddress((void**)&xu,  g_xu);
    cudaGetSymbolAddress((void**)&xi,  g_xi);
    cudaGetSymbolAddress((void**)&wts, g_wts);

    float* agg0 = agg;
    float* agg1 = agg + (size_t)M * HDIM;
    int *deg0 = deg,     *deg1 = deg + M;
    int *off0 = off,     *off1 = off + M;
    int *cur0 = cur,     *cur1 = cur + M;
    int *csr0 = csr,     *csr1 = csr + EDGES;

    float* w_lin_u = wts;
    float* w_lin_i = w_lin_u + 32768;
    float* w_c[8];
    w_c[0] = w_lin_i + 32768;
    for (int i = 1; i < 8; i++) w_c[i] = w_c[i - 1] + 65536;
    float* w_out_u = w_c[7] + 65536;
    float* w_out_i = w_out_u + 65536;

    PtrPack pk;
    const float* wsrc[NPACK] = {
        lin_user_W, lin_item_W,
        c0_ui_Wl, c0_ui_Wr, c0_iu_Wl, c0_iu_Wr,
        c1_ui_Wl, c1_ui_Wr, c1_iu_Wl, c1_iu_Wr,
        out_user_W, out_item_W, x_user, x_item };
    float* wdst[NPACK] = {
        w_lin_u, w_lin_i,
        w_c[0], w_c[1], w_c[2], w_c[3], w_c[4], w_c[5], w_c[6], w_c[7],
        w_out_u, w_out_i, xu, xi };
    int wnn[NPACK] = {
        32768, 32768,
        65536, 65536, 65536, 65536, 65536, 65536, 65536, 65536,
        65536, 65536, NNODE * DIN, NNODE * DIN };
    for (int i = 0; i < NPACK; i++) { pk.src[i] = wsrc[i]; pk.dst[i] = wdst[i]; pk.n[i] = wnn[i]; }

    dim3 blk(256);
    dim3 grid_gemm((M + BM - 1) / BM, 2);
    dim3 grid_edge((nE + 255) / 256);
    dim3 grid_node((M + 7) / 8);
    dim3 grid_cvt(2048, NPACK);

    auto agg2 = [&](const float* h, const int* c, const int* o, const int* dg, float* a) {
        agg_csr_kernel<<<grid_node, blk>>>(h, c, o, dg, a, M, 0);
        agg_csr_kernel<<<grid_node, blk>>>(h, c, o, dg, a, M, 128);
    };

    /* 1 */ cudaMemsetAsync(deg, 0, 2 * M * sizeof(int));
    /* 2 */ cvt_pack_kernel<<<grid_cvt, blk>>>(pk);
    /* 3 */ deg_kernel<<<grid_edge, blk>>>(ei_ui_dst, deg0, nE);
    /* 4 */ deg_kernel<<<grid_edge, blk>>>(ei_iu_dst, deg1, nE);
    /* 5 */ gemm_tc<DIN, false, 0><<<grid_gemm, blk>>>(
                xu, nullptr, w_lin_u, nullptr, lin_user_b, hu, M);
    /* 6 */ gemm_tc<DIN, false, 0><<<grid_gemm, blk>>>(   // <- profiled
                xi, nullptr, w_lin_i, nullptr, lin_item_b, hi, M);
    /* 7 */ scan_kernel<<<1, 1024>>>(deg0, off0, cur0, M);
    /* 8 */ scan_kernel<<<1, 1024>>>(deg1, off1, cur1, M);
    /* 9 */ csr_build_kernel<<<grid_edge, blk>>>(ei_ui_src, ei_ui_dst, cur0, csr0, nE);
    /*10 */ csr_build_kernel<<<grid_edge, blk>>>(ei_iu_src, ei_iu_dst, cur1, csr1, nE);

    // layer 0
    /*11,12*/ agg2(hu, csr0, off0, deg0, agg0);
    /*13 */ gemm_tc<HDIM, true, 0><<<grid_gemm, blk>>>(
                agg0, hi, w_c[0], w_c[1], c0_ui_bl, ti, M);
    /*14,15*/ agg2(hi, csr1, off1, deg1, agg1);
    /*16 */ gemm_tc<HDIM, true, 0><<<grid_gemm, blk>>>(
                agg1, hu, w_c[2], w_c[3], c0_iu_bl, tu, M);
    // layer 1
    /*17,18*/ agg2(tu, csr0, off0, deg0, agg0);
    /*19 */ gemm_tc<HDIM, true, 0><<<grid_gemm, blk>>>(
                agg0, ti, w_c[4], w_c[5], c1_ui_bl, hi, M);
    /*20,21*/ agg2(ti, csr1, off1, deg1, agg1);
    /*22 */ gemm_tc<HDIM, true, 0><<<grid_gemm, blk>>>(
                agg1, tu, w_c[6], w_c[7], c1_iu_bl, hu, M);
    // heads
    /*23 */ gemm_tc<HDIM, false, 1><<<grid_gemm, blk>>>(
                hu, nullptr, w_out_u, nullptr, out_user_b, out, M);
    /*24 */ gemm_tc<HDIM, false, 1><<<grid_gemm, blk>>>(
                hi, nullptr, w_out_i, nullptr, out_item_b, out + (size_t)M * HDIM, M);
    /*25 */ ln_kernel<<<grid_node, blk>>>(out, ln_user_g, ln_user_b2, M);
    /*26 */ ln_kernel<<<grid_node, blk>>>(out + (size_t)M * HDIM, ln_item_g, ln_item_b2, M);
}

// round 10
// speedup vs baseline: 2.1471x; 1.0357x over previous
#include <cuda_runtime.h>
#include <math.h>
#include <stdint.h>

#define NNODE 100000
#define EDGES 800000
#define DIN   128
#define HDIM  256

// ---------------------------------------------------------------------------
// Scratch (__device__ globals; no allocation allowed)
// ---------------------------------------------------------------------------
__device__ float g_hu [(size_t)NNODE * HDIM];
__device__ float g_hi [(size_t)NNODE * HDIM];
__device__ float g_tu [(size_t)NNODE * HDIM];
__device__ float g_ti [(size_t)NNODE * HDIM];
__device__ float g_agg[2 * (size_t)NNODE * HDIM];   // agg0 | agg1
__device__ int   g_deg[2 * NNODE];                  // deg0 (item) | deg1 (user)
__device__ int   g_off[2 * NNODE];                  // CSR row offsets
__device__ int   g_cur[2 * NNODE];                  // build cursors
__device__ int   g_csr[2 * EDGES];                  // sorted src indices
__device__ float g_xu [(size_t)NNODE * DIN];        // tf32 x_user
__device__ float g_xi [(size_t)NNODE * DIN];        // tf32 x_item
__device__ float g_wts[2 * 32768 + 10 * 65536];     // tf32 weights

// ---------------------------------------------------------------------------
// Helpers
// ---------------------------------------------------------------------------
__device__ __forceinline__ float gelu_f(float x) {
    return 0.5f * x * (1.0f + erff(x * 0.70710678118654752f));
}
__device__ __forceinline__ float to_tf32(float x) {
    float r;
    asm("cvt.rna.tf32.f32 %0, %1;" : "=f"(r) : "f"(x));
    return r;
}
__device__ __forceinline__ void cvt4(float4& v) {
    v.x = to_tf32(v.x); v.y = to_tf32(v.y); v.z = to_tf32(v.z); v.w = to_tf32(v.w);
}
__device__ __forceinline__ void mma_tf32(float& d0, float& d1, float& d2, float& d3,
                                         uint32_t a0, uint32_t a1, uint32_t a2, uint32_t a3,
                                         uint32_t b0, uint32_t b1)
{
    asm volatile(
        "mma.sync.aligned.m16n8k8.row.col.f32.tf32.tf32.f32 "
        "{%0,%1,%2,%3}, {%4,%5,%6,%7}, {%8,%9}, {%0,%1,%2,%3};"
        : "+f"(d0), "+f"(d1), "+f"(d2), "+f"(d3)
        : "r"(a0), "r"(a1), "r"(a2), "r"(a3), "r"(b0), "r"(b1));
}
__device__ __forceinline__ void cp16(uint32_t dst, const void* src, bool pred) {
    int sz = pred ? 16 : 0;
    asm volatile("cp.async.ca.shared.global [%0], [%1], 16, %2;"
                 :: "r"(dst), "l"(src), "r"(sz));
}

// ---------------------------------------------------------------------------
// Pre-pass: convert weights + x to tf32
// ---------------------------------------------------------------------------
#define NPACK 14
struct PtrPack {
    const float* src[NPACK];
    float*       dst[NPACK];
    int          n  [NPACK];
};

__global__ void __launch_bounds__(256)
cvt_pack_kernel(PtrPack p)
{
    int m = blockIdx.y;
    const float4* s = reinterpret_cast<const float4*>(p.src[m]);
    float4*       d = reinterpret_cast<float4*>(p.dst[m]);
    int n4 = p.n[m] >> 2;
    for (int i = blockIdx.x * blockDim.x + threadIdx.x; i < n4;
         i += gridDim.x * blockDim.x) {
        float4 v = s[i];
        cvt4(v);
        d[i] = v;
    }
}

// ---------------------------------------------------------------------------
// Paired CSR construction kernels (blockIdx.y / blockIdx.x selects side)
// ---------------------------------------------------------------------------
struct EdgePair {
    const int* src[2];
    const int* dst[2];
    int*       deg[2];
    int*       off[2];
    int*       cur[2];
    int*       csr[2];
};

__global__ void __launch_bounds__(256)
deg_pair_kernel(EdgePair p, int nE) {
    int z = blockIdx.y;
    int i = blockIdx.x * blockDim.x + threadIdx.x;
    if (i < nE) atomicAdd(&p.deg[z][p.dst[z][i]], 1);
}

__global__ void __launch_bounds__(1024)
scan_pair_kernel(EdgePair p, int n)
{
    const int z = blockIdx.x;       // one block per side
    const int* __restrict__ deg = p.deg[z];
    int* __restrict__ off = p.off[z];
    int* __restrict__ cur = p.cur[z];
    __shared__ int carry;
    __shared__ int wsum[32];
    const int tid  = threadIdx.x;
    const int lane = tid & 31;
    const int wid  = tid >> 5;
    if (tid == 0) carry = 0;
    __syncthreads();
    for (int base = 0; base < n; base += 1024) {
        int i = base + tid;
        int v = (i < n) ? deg[i] : 0;
        int x = v;
        #pragma unroll
        for (int s = 1; s < 32; s <<= 1) {
            int y = __shfl_up_sync(0xffffffffu, x, s);
            if (lane >= s) x += y;
        }
        if (lane == 31) wsum[wid] = x;
        __syncthreads();
        if (wid == 0) {
            int ws = wsum[lane];
            #pragma unroll
            for (int s = 1; s < 32; s <<= 1) {
                int y = __shfl_up_sync(0xffffffffu, ws, s);
                if (lane >= s) ws += y;
            }
            wsum[lane] = ws;
        }
        __syncthreads();
        int excl = x - v + (wid > 0 ? wsum[wid - 1] : 0) + carry;
        if (i < n) { off[i] = excl; cur[i] = excl; }
        __syncthreads();
        if (tid == 0) carry += wsum[31];
        __syncthreads();
    }
}

__global__ void __launch_bounds__(256)
csr_pair_kernel(EdgePair p, int nE)
{
    int z = blockIdx.y;
    int e = blockIdx.x * blockDim.x + threadIdx.x;
    if (e >= nE) return;
    int pos = atomicAdd(&p.cur[z][p.dst[z][e]], 1);
    p.csr[z][pos] = p.src[z][e];
}

// ---------------------------------------------------------------------------
// Paired CSR aggregation: grid (nodes/8, 2 halves, 2 sides)
// ---------------------------------------------------------------------------
struct AggPair {
    const float* h[2];
    const int*   csr[2];
    const int*   off[2];
    const int*   deg[2];
    float*       agg[2];
};

__global__ void __launch_bounds__(256)
agg_pair_kernel(AggPair p, int n)
{
    int node = blockIdx.x * 8 + (threadIdx.x >> 5);
    if (node >= n) return;
    const int z = blockIdx.z;
    const float* __restrict__ h   = p.h[z];
    const int*   __restrict__ csr = p.csr[z];
    float*       __restrict__ agg = p.agg[z];
    int coff = blockIdx.y * 128;
    int lane = threadIdx.x & 31;
    int o = __ldg(&p.off[z][node]);
    int d = __ldg(&p.deg[z][node]);
    float4 acc = make_float4(0.f, 0.f, 0.f, 0.f);
    int j = 0;
    for (; j + 4 <= d; j += 4) {
        int s0 = __ldg(&csr[o + j]);
        int s1 = __ldg(&csr[o + j + 1]);
        int s2 = __ldg(&csr[o + j + 2]);
        int s3 = __ldg(&csr[o + j + 3]);
        float4 v0 = *reinterpret_cast<const float4*>(h + (size_t)s0 * HDIM + coff + lane * 4);
        float4 v1 = *reinterpret_cast<const float4*>(h + (size_t)s1 * HDIM + coff + lane * 4);
        float4 v2 = *reinterpret_cast<const float4*>(h + (size_t)s2 * HDIM + coff + lane * 4);
        float4 v3 = *reinterpret_cast<const float4*>(h + (size_t)s3 * HDIM + coff + lane * 4);
        acc.x += v0.x + v1.x + v2.x + v3.x;
        acc.y += v0.y + v1.y + v2.y + v3.y;
        acc.z += v0.z + v1.z + v2.z + v3.z;
        acc.w += v0.w + v1.w + v2.w + v3.w;
    }
    for (; j < d; j++) {
        int s = __ldg(&csr[o + j]);
        float4 v = *reinterpret_cast<const float4*>(h + (size_t)s * HDIM + coff + lane * 4);
        acc.x += v.x; acc.y += v.y; acc.z += v.z; acc.w += v.w;
    }
    float sc = 1.0f / fmaxf((float)d, 1.0f);
    float4 r;
    r.x = to_tf32(acc.x * sc);
    r.y = to_tf32(acc.y * sc);
    r.z = to_tf32(acc.z * sc);
    r.w = to_tf32(acc.w * sc);
    *reinterpret_cast<float4*>(agg + (size_t)node * HDIM + coff + lane * 4) = r;
}

// ---------------------------------------------------------------------------
// Paired in-place LayerNorm (blockIdx.y selects side)
// ---------------------------------------------------------------------------
struct LnPair {
    float*       x[2];
    const float* g[2];
    const float* b[2];
};

__global__ void __launch_bounds__(256)
ln_pair_kernel(LnPair pp, int M)
{
    int row  = blockIdx.x * 8 + (threadIdx.x >> 5);
    int lane = threadIdx.x & 31;
    if (row >= M) return;
    const int z = blockIdx.y;
    float* p = pp.x[z] + (size_t)row * HDIM + lane * 8;
    const float* g = pp.g[z];
    const float* b = pp.b[z];
    float4 v0 = *reinterpret_cast<const float4*>(p);
    float4 v1 = *reinterpret_cast<const float4*>(p + 4);
    float s  = v0.x + v0.y + v0.z + v0.w + v1.x + v1.y + v1.z + v1.w;
    float sq = v0.x*v0.x + v0.y*v0.y + v0.z*v0.z + v0.w*v0.w
             + v1.x*v1.x + v1.y*v1.y + v1.z*v1.z + v1.w*v1.w;
    #pragma unroll
    for (int m = 16; m > 0; m >>= 1) {
        s  += __shfl_xor_sync(0xffffffffu, s,  m);
        sq += __shfl_xor_sync(0xffffffffu, sq, m);
    }
    float mu   = s * (1.0f / 256.0f);
    float var  = sq * (1.0f / 256.0f) - mu * mu;
    float rstd = rsqrtf(var + 1e-5f);
    float4 g0 = *reinterpret_cast<const float4*>(g + lane * 8);
    float4 g1 = *reinterpret_cast<const float4*>(g + lane * 8 + 4);
    float4 b0 = *reinterpret_cast<const float4*>(b + lane * 8);
    float4 b1 = *reinterpret_cast<const float4*>(b + lane * 8 + 4);
    float4 o0, o1;
    o0.x = (v0.x - mu) * rstd * g0.x + b0.x;
    o0.y = (v0.y - mu) * rstd * g0.y + b0.y;
    o0.z = (v0.z - mu) * rstd * g0.z + b0.z;
    o0.w = (v0.w - mu) * rstd * g0.w + b0.w;
    o1.x = (v1.x - mu) * rstd * g1.x + b1.x;
    o1.y = (v1.y - mu) * rstd * g1.y + b1.y;
    o1.z = (v1.z - mu) * rstd * g1.z + b1.z;
    o1.w = (v1.w - mu) * rstd * g1.w + b1.w;
    *reinterpret_cast<float4*>(p)     = o0;
    *reinterpret_cast<float4*>(p + 4) = o1;
}

// ---------------------------------------------------------------------------
// Paired 3-stage cp.async tf32 tensor-core GEMM. blockIdx.z selects side.
//   C[M,256] = EPI( A1@W1 (+ A2@W2) + bias )
// ---------------------------------------------------------------------------
constexpr int BM  = 128;
constexpr int BK  = 32;
constexpr int LDA = 36;
constexpr int LDB = 136;
constexpr int ST  = 3;

struct GemmPair {
    const float* A1[2];
    const float* A2[2];
    const float* W1[2];
    const float* W2[2];
    const float* bias[2];
    float*       C[2];
};

__device__ __forceinline__ void compute_tile(
    const float* __restrict__ as, const float* __restrict__ bs,
    float (&d)[4][4][4], int wm, int wn, int lq, int lr)
{
    #pragma unroll
    for (int ks = 0; ks < 4; ks++) {
        uint32_t af[4][4];
        #pragma unroll
        for (int i = 0; i < 4; i++) {
            int rm = wm * 64 + i * 16 + lq;
            af[i][0] = __float_as_uint(as[rm * LDA + ks * 8 + lr]);
            af[i][1] = __float_as_uint(as[(rm + 8) * LDA + ks * 8 + lr]);
            af[i][2] = __float_as_uint(as[rm * LDA + ks * 8 + lr + 4]);
            af[i][3] = __float_as_uint(as[(rm + 8) * LDA + ks * 8 + lr + 4]);
        }
        uint32_t bf[4][2];
        #pragma unroll
        for (int j = 0; j < 4; j++) {
            int cb = wn * 32 + j * 8 + lq;
            bf[j][0] = __float_as_uint(bs[(ks * 8 + lr) * LDB + cb]);
            bf[j][1] = __float_as_uint(bs[(ks * 8 + lr + 4) * LDB + cb]);
        }
        #pragma unroll
        for (int i = 0; i < 4; i++)
            #pragma unroll
            for (int j = 0; j < 4; j++)
                mma_tf32(d[i][j][0], d[i][j][1], d[i][j][2], d[i][j][3],
                         af[i][0], af[i][1], af[i][2], af[i][3],
                         bf[j][0], bf[j][1]);
    }
}

template<int K, bool HAS_A2, int EPI>
__global__ void __launch_bounds__(256, 2)
gemm_pair(GemmPair p, int M)
{
    __shared__ float a_s[ST][BM * LDA];
    __shared__ float b_s[ST][BK * LDB];

    constexpr int NIT = (HAS_A2 ? 2 : 1) * K / BK;

    const int zz = blockIdx.z;
    const float* __restrict__ A1g  = p.A1[zz];
    const float* __restrict__ A2g  = p.A2[zz];
    const float* __restrict__ W1g  = p.W1[zz];
    const float* __restrict__ W2g  = p.W2[zz];
    const float* __restrict__ bias = p.bias[zz];
    float*       __restrict__ C    = p.C[zz];

    const int tid  = threadIdx.x;
    const int lane = tid & 31;
    const int wid  = tid >> 5;
    const int wm   = wid >> 2;
    const int wn   = wid & 3;
    const int lq   = lane >> 2;
    const int lr   = lane & 3;
    const int row0 = blockIdx.x * BM;
    const int ncol0 = blockIdx.y * 128;

    const int ar  = tid >> 3;
    const int ac4 = (tid & 7) << 2;
    const int bkr = tid >> 5;
    const int bc4 = (tid & 31) << 2;

    const uint32_t a_base = (uint32_t)__cvta_generic_to_shared(a_s);
    const uint32_t b_base = (uint32_t)__cvta_generic_to_shared(b_s);

    float d[4][4][4];
    #pragma unroll
    for (int i = 0; i < 4; i++)
        #pragma unroll
        for (int j = 0; j < 4; j++)
            #pragma unroll
            for (int q = 0; q < 4; q++)
                d[i][j][q] = 0.f;

    auto load_stage = [&](int kt, int buf) {
        int kk = kt * BK;
        const float* __restrict__ A = (HAS_A2 && kk >= K) ? A2g : A1g;
        const float* __restrict__ W = (HAS_A2 && kk >= K) ? W2g : W1g;
        const int k0 = HAS_A2 ? (kk & (K - 1)) : kk;
        uint32_t ab = a_base + (uint32_t)(buf * BM * LDA) * 4u;
        uint32_t bb = b_base + (uint32_t)(buf * BK * LDB) * 4u;
        #pragma unroll
        for (int u = 0; u < 4; u++) {
            int r  = ar + u * 32;
            int gr = row0 + r;
            int gc = gr < M ? gr : (M - 1);
            cp16(ab + (uint32_t)(r * LDA + ac4) * 4u,
                 A + (size_t)gc * K + k0 + ac4, gr < M);
            cp16(bb + (uint32_t)((bkr + u * 8) * LDB + bc4) * 4u,
                 W + (size_t)(k0 + bkr + u * 8) * HDIM + ncol0 + bc4, true);
        }
    };

    load_stage(0, 0);
    asm volatile("cp.async.commit_group;" ::: "memory");
    load_stage(1, 1);
    asm volatile("cp.async.commit_group;" ::: "memory");

    #pragma unroll 1
    for (int kt = 0; kt < NIT; kt++) {
        asm volatile("cp.async.wait_group 1;" ::: "memory");
        __syncthreads();
        if (kt + 2 < NIT) load_stage(kt + 2, (kt + 2) % ST);
        asm volatile("cp.async.commit_group;" ::: "memory");
        compute_tile(a_s[kt % ST], b_s[kt % ST], d, wm, wn, lq, lr);
    }

    #pragma unroll
    for (int j = 0; j < 4; j++) {
        float2 b = *reinterpret_cast<const float2*>(bias + ncol0 + wn * 32 + j * 8 + 2 * lr);
        #pragma unroll
        for (int i = 0; i < 4; i++) {
            d[i][j][0] += b.x; d[i][j][1] += b.y;
            d[i][j][2] += b.x; d[i][j][3] += b.y;
        }
    }

    const int cbase = ncol0 + wn * 32;
    #pragma unroll
    for (int i = 0; i < 4; i++) {
        #pragma unroll
        for (int rr = 0; rr < 2; rr++) {
            int gr = row0 + wm * 64 + i * 16 + lq + rr * 8;
            if (gr < M) {
                #pragma unroll
                for (int j = 0; j < 4; j++) {
                    float2 v;
                    if (EPI == 0) {
                        v.x = to_tf32(gelu_f(d[i][j][rr * 2 + 0]));
                        v.y = to_tf32(gelu_f(d[i][j][rr * 2 + 1]));
                    } else {
                        v.x = d[i][j][rr * 2 + 0];
                        v.y = d[i][j][rr * 2 + 1];
                    }
                    *reinterpret_cast<float2*>(
                        C + (size_t)gr * HDIM + cbase + j * 8 + 2 * lr) = v;
                }
            }
        }
    }
}

// ---------------------------------------------------------------------------
// kernel_launch — fused-pair schedule, single stream (graph-capturable)
// ---------------------------------------------------------------------------
extern "C" void kernel_launch(void* const* d_in, const int* in_sizes, int n_in,
                              void* d_out, int out_size)
{
    const float* x_user    = (const float*)d_in[0];
    const float* x_item    = (const float*)d_in[1];
    const int*   ei_ui_src = (const int*)  d_in[2];
    const int*   ei_ui_dst = (const int*)  d_in[3];
    const int*   ei_iu_src = (const int*)  d_in[4];
    const int*   ei_iu_dst = (const int*)  d_in[5];
    const float* lin_user_W = (const float*)d_in[6];
    const float* lin_user_b = (const float*)d_in[7];
    const float* lin_item_W = (const float*)d_in[8];
    const float* lin_item_b = (const float*)d_in[9];
    const float* c0_ui_Wl = (const float*)d_in[10];
    const float* c0_ui_bl = (const float*)d_in[11];
    const float* c0_ui_Wr = (const float*)d_in[12];
    const float* c0_iu_Wl = (const float*)d_in[13];
    const float* c0_iu_bl = (const float*)d_in[14];
    const float* c0_iu_Wr = (const float*)d_in[15];
    const float* c1_ui_Wl = (const float*)d_in[16];
    const float* c1_ui_bl = (const float*)d_in[17];
    const float* c1_ui_Wr = (const float*)d_in[18];
    const float* c1_iu_Wl = (const float*)d_in[19];
    const float* c1_iu_bl = (const float*)d_in[20];
    const float* c1_iu_Wr = (const float*)d_in[21];
    const float* out_user_W = (const float*)d_in[22];
    const float* out_user_b = (const float*)d_in[23];
    const float* out_item_W = (const float*)d_in[24];
    const float* out_item_b = (const float*)d_in[25];
    const float* ln_user_g  = (const float*)d_in[26];
    const float* ln_user_b2 = (const float*)d_in[27];
    const float* ln_item_g  = (const float*)d_in[28];
    const float* ln_item_b2 = (const float*)d_in[29];

    float* out = (float*)d_out;
    const int nE = in_sizes[2];
    const int M  = NNODE;

    float *hu, *hi, *tu, *ti, *agg, *xu, *xi, *wts;
    int *deg, *off, *cur, *csr;
    cudaGetSymbolAddress((void**)&hu,  g_hu);
    cudaGetSymbolAddress((void**)&hi,  g_hi);
    cudaGetSymbolAddress((void**)&tu,  g_tu);
    cudaGetSymbolAddress((void**)&ti,  g_ti);
    cudaGetSymbolAddress((void**)&agg, g_agg);
    cudaGetSymbolAddress((void**)&deg, g_deg);
    cudaGetSymbolAddress((void**)&off, g_off);
    cudaGetSymbolAddress((void**)&cur, g_cur);
    cudaGetSymbolAddress((void**)&csr, g_csr);
    cudaGetSymbolAddress((void**)&xu,  g_xu);
    cudaGetSymbolAddress((void**)&xi,  g_xi);
    cudaGetSymbolAddress((void**)&wts, g_wts);

    float* agg0 = agg;
    float* agg1 = agg + (size_t)M * HDIM;
    int *deg0 = deg,     *deg1 = deg + M;
    int *off0 = off,     *off1 = off + M;
    int *cur0 = cur,     *cur1 = cur + M;
    int *csr0 = csr,     *csr1 = csr + EDGES;

    float* w_lin_u = wts;
    float* w_lin_i = w_lin_u + 32768;
    float* w_c[8];
    w_c[0] = w_lin_i + 32768;
    for (int i = 1; i < 8; i++) w_c[i] = w_c[i - 1] + 65536;
    float* w_out_u = w_c[7] + 65536;
    float* w_out_i = w_out_u + 65536;

    PtrPack pk;
    const float* wsrc[NPACK] = {
        lin_user_W, lin_item_W,
        c0_ui_Wl, c0_ui_Wr, c0_iu_Wl, c0_iu_Wr,
        c1_ui_Wl, c1_ui_Wr, c1_iu_Wl, c1_iu_Wr,
        out_user_W, out_item_W, x_user, x_item };
    float* wdst[NPACK] = {
        w_lin_u, w_lin_i,
        w_c[0], w_c[1], w_c[2], w_c[3], w_c[4], w_c[5], w_c[6], w_c[7],
        w_out_u, w_out_i, xu, xi };
    int wnn[NPACK] = {
        32768, 32768,
        65536, 65536, 65536, 65536, 65536, 65536, 65536, 65536,
        65536, 65536, NNODE * DIN, NNODE * DIN };
    for (int i = 0; i < NPACK; i++) { pk.src[i] = wsrc[i]; pk.dst[i] = wdst[i]; pk.n[i] = wnn[i]; }

    EdgePair ep;
    ep.src[0] = ei_ui_src; ep.src[1] = ei_iu_src;
    ep.dst[0] = ei_ui_dst; ep.dst[1] = ei_iu_dst;
    ep.deg[0] = deg0; ep.deg[1] = deg1;
    ep.off[0] = off0; ep.off[1] = off1;
    ep.cur[0] = cur0; ep.cur[1] = cur1;
    ep.csr[0] = csr0; ep.csr[1] = csr1;

    dim3 blk(256);
    dim3 grid_gemm((M + BM - 1) / BM, 2, 2);
    dim3 grid_edge((nE + 255) / 256, 2);
    dim3 grid_agg((M + 7) / 8, 2, 2);
    dim3 grid_ln((M + 7) / 8, 2);
    dim3 grid_cvt(2048, NPACK);

    auto agg_pair = [&](const float* h0, const float* h1) {
        AggPair ap;
        ap.h[0] = h0;   ap.h[1] = h1;
        ap.csr[0] = csr0; ap.csr[1] = csr1;
        ap.off[0] = off0; ap.off[1] = off1;
        ap.deg[0] = deg0; ap.deg[1] = deg1;
        ap.agg[0] = agg0; ap.agg[1] = agg1;
        agg_pair_kernel<<<grid_agg, blk>>>(ap, M);
    };
    auto sage_pair = [&](const float* a1_0, const float* a2_0, float* wl0, float* wr0,
                         const float* bl0, float* c_0,
                         const float* a1_1, const float* a2_1, float* wl1, float* wr1,
                         const float* bl1, float* c_1) {
        GemmPair gp;
        gp.A1[0] = a1_0; gp.A2[0] = a2_0; gp.W1[0] = wl0; gp.W2[0] = wr0;
        gp.bias[0] = bl0; gp.C[0] = c_0;
        gp.A1[1] = a1_1; gp.A2[1] = a2_1; gp.W1[1] = wl1; gp.W2[1] = wr1;
        gp.bias[1] = bl1; gp.C[1] = c_1;
        gemm_pair<HDIM, true, 0><<<grid_gemm, blk>>>(gp, M);
    };

    /* 1 */ cudaMemsetAsync(deg, 0, 2 * M * sizeof(int));
    /* 2 */ cvt_pack_kernel<<<grid_cvt, blk>>>(pk);
    /* 3 */ deg_pair_kernel<<<grid_edge, blk>>>(ep, nE);
    /* 4 */ scan_pair_kernel<<<2, 1024>>>(ep, M);
    /* 5 */ csr_pair_kernel<<<grid_edge, blk>>>(ep, nE);

    /* 6: input projections (pair) */
    {
        GemmPair gp;
        gp.A1[0] = xu; gp.A2[0] = nullptr; gp.W1[0] = w_lin_u; gp.W2[0] = nullptr;
        gp.bias[0] = lin_user_b; gp.C[0] = hu;
        gp.A1[1] = xi; gp.A2[1] = nullptr; gp.W1[1] = w_lin_i; gp.W2[1] = nullptr;
        gp.bias[1] = lin_item_b; gp.C[1] = hi;
        gemm_pair<DIN, false, 0><<<grid_gemm, blk>>>(gp, M);
    }

    /* 7: layer-0 aggregation (pair): agg0 = mean(hu over ui), agg1 = mean(hi over iu) */
    agg_pair(hu, hi);
    /* 8: layer-0 SAGE gemms (pair): ti, tu */
    sage_pair(agg0, hi, w_c[0], w_c[1], c0_ui_bl, ti,
              agg1, hu, w_c[2], w_c[3], c0_iu_bl, tu);

    /* 9: layer-1 aggregation (pair) */
    agg_pair(tu, ti);
    /*10: layer-1 SAGE gemms (pair): hi, hu */
    sage_pair(agg0, ti, w_c[4], w_c[5], c1_ui_bl, hi,
              agg1, tu, w_c[6], w_c[7], c1_iu_bl, hu);

    /*11: heads (pair) */
    {
        GemmPair gp;
        gp.A1[0] = hu; gp.A2[0] = nullptr; gp.W1[0] = w_out_u; gp.W2[0] = nullptr;
        gp.bias[0] = out_user_b; gp.C[0] = out;
        gp.A1[1] = hi; gp.A2[1] = nullptr; gp.W1[1] = w_out_i; gp.W2[1] = nullptr;
        gp.bias[1] = out_item_b; gp.C[1] = out + (size_t)M * HDIM;
        gemm_pair<HDIM, false, 1><<<grid_gemm, blk>>>(gp, M);
    }
    /*12: LayerNorm (pair) */
    {
        LnPair lp;
        lp.x[0] = out;                     lp.x[1] = out + (size_t)M * HDIM;
        lp.g[0] = ln_user_g;               lp.g[1] = ln_item_g;
        lp.b[0] = ln_user_b2;              lp.b[1] = ln_item_b2;
        ln_pair_kernel<<<grid_ln, blk>>>(lp, M);
    }
}

// round 11
// speedup vs baseline: 2.2099x; 1.0293x over previous
#include <cuda_runtime.h>
#include <math.h>
#include <stdint.h>

#define NNODE 100000
#define EDGES 800000
#define DIN   128
#define HDIM  256

// ---------------------------------------------------------------------------
// Scratch (__device__ globals; no allocation allowed)
// ---------------------------------------------------------------------------
__device__ float g_hu [(size_t)NNODE * HDIM];
__device__ float g_hi [(size_t)NNODE * HDIM];
__device__ float g_tu [(size_t)NNODE * HDIM];
__device__ float g_ti [(size_t)NNODE * HDIM];
__device__ float g_agg[2 * (size_t)NNODE * HDIM];   // agg0 | agg1
__device__ int   g_deg[2 * NNODE];
__device__ int   g_off[2 * NNODE];
__device__ int   g_cur[2 * NNODE];
__device__ int   g_csr[2 * EDGES];
__device__ float g_xu [(size_t)NNODE * DIN];        // tf32 x_user
__device__ float g_xi [(size_t)NNODE * DIN];        // tf32 x_item
__device__ float g_wts[2 * 32768 + 10 * 65536];     // tf32 TRANSPOSED weights

// ---------------------------------------------------------------------------
// Helpers
// ---------------------------------------------------------------------------
__device__ __forceinline__ float gelu_f(float x) {
    return 0.5f * x * (1.0f + erff(x * 0.70710678118654752f));
}
__device__ __forceinline__ float to_tf32(float x) {
    float r;
    asm("cvt.rna.tf32.f32 %0, %1;" : "=f"(r) : "f"(x));
    return r;
}
__device__ __forceinline__ void cvt4(float4& v) {
    v.x = to_tf32(v.x); v.y = to_tf32(v.y); v.z = to_tf32(v.z); v.w = to_tf32(v.w);
}
__device__ __forceinline__ void mma_tf32(float& d0, float& d1, float& d2, float& d3,
                                         uint32_t a0, uint32_t a1, uint32_t a2, uint32_t a3,
                                         uint32_t b0, uint32_t b1)
{
    asm volatile(
        "mma.sync.aligned.m16n8k8.row.col.f32.tf32.tf32.f32 "
        "{%0,%1,%2,%3}, {%4,%5,%6,%7}, {%8,%9}, {%0,%1,%2,%3};"
        : "+f"(d0), "+f"(d1), "+f"(d2), "+f"(d3)
        : "r"(a0), "r"(a1), "r"(a2), "r"(a3), "r"(b0), "r"(b1));
}
__device__ __forceinline__ void cp16(uint32_t dst, const void* src, bool pred) {
    int sz = pred ? 16 : 0;
    asm volatile("cp.async.ca.shared.global [%0], [%1], 16, %2;"
                 :: "r"(dst), "l"(src), "r"(sz));
}
__device__ __forceinline__ void ldsm4(uint32_t& r0, uint32_t& r1, uint32_t& r2, uint32_t& r3,
                                      uint32_t addr)
{
    asm volatile("ldmatrix.sync.aligned.m8n8.x4.shared.b16 {%0,%1,%2,%3}, [%4];"
                 : "=r"(r0), "=r"(r1), "=r"(r2), "=r"(r3) : "r"(addr));
}

// ---------------------------------------------------------------------------
// Pre-pass A: convert x_user/x_item to tf32 (row-major, unchanged layout)
// ---------------------------------------------------------------------------
struct XPack { const float* src[2]; float* dst[2]; int n[2]; };

__global__ void __launch_bounds__(256)
cvt_x_kernel(XPack p)
{
    int m = blockIdx.y;
    const float4* s = reinterpret_cast<const float4*>(p.src[m]);
    float4*       d = reinterpret_cast<float4*>(p.dst[m]);
    int n4 = p.n[m] >> 2;
    for (int i = blockIdx.x * blockDim.x + threadIdx.x; i < n4;
         i += gridDim.x * blockDim.x) {
        float4 v = s[i];
        cvt4(v);
        d[i] = v;
    }
}

// ---------------------------------------------------------------------------
// Pre-pass B: convert + TRANSPOSE weights. src [K][256] -> dst [256][K], tf32.
// ---------------------------------------------------------------------------
#define NTW 12
struct TPack { const float* src[NTW]; float* dst[NTW]; int K[NTW]; };

__global__ void __launch_bounds__(256)
cvt_wT_kernel(TPack p)
{
    int m = blockIdx.y;
    const float* __restrict__ s = p.src[m];
    float*       __restrict__ d = p.dst[m];
    int K = p.K[m];
    int total = K * 256;
    for (int i = blockIdx.x * blockDim.x + threadIdx.x; i < total;
         i += gridDim.x * blockDim.x) {
        int k = i >> 8;
        int n = i & 255;
        d[n * K + k] = to_tf32(s[i]);
    }
}

// ---------------------------------------------------------------------------
// Paired CSR construction kernels
// ---------------------------------------------------------------------------
struct EdgePair {
    const int* src[2];
    const int* dst[2];
    int*       deg[2];
    int*       off[2];
    int*       cur[2];
    int*       csr[2];
};

__global__ void __launch_bounds__(256)
deg_pair_kernel(EdgePair p, int nE) {
    int z = blockIdx.y;
    int i = blockIdx.x * blockDim.x + threadIdx.x;
    if (i < nE) atomicAdd(&p.deg[z][p.dst[z][i]], 1);
}

__global__ void __launch_bounds__(1024)
scan_pair_kernel(EdgePair p, int n)
{
    const int z = blockIdx.x;
    const int* __restrict__ deg = p.deg[z];
    int* __restrict__ off = p.off[z];
    int* __restrict__ cur = p.cur[z];
    __shared__ int carry;
    __shared__ int wsum[32];
    const int tid  = threadIdx.x;
    const int lane = tid & 31;
    const int wid  = tid >> 5;
    if (tid == 0) carry = 0;
    __syncthreads();
    for (int base = 0; base < n; base += 1024) {
        int i = base + tid;
        int v = (i < n) ? deg[i] : 0;
        int x = v;
        #pragma unroll
        for (int s = 1; s < 32; s <<= 1) {
            int y = __shfl_up_sync(0xffffffffu, x, s);
            if (lane >= s) x += y;
        }
        if (lane == 31) wsum[wid] = x;
        __syncthreads();
        if (wid == 0) {
            int ws = wsum[lane];
            #pragma unroll
            for (int s = 1; s < 32; s <<= 1) {
                int y = __shfl_up_sync(0xffffffffu, ws, s);
                if (lane >= s) ws += y;
            }
            wsum[lane] = ws;
        }
        __syncthreads();
        int excl = x - v + (wid > 0 ? wsum[wid - 1] : 0) + carry;
        if (i < n) { off[i] = excl; cur[i] = excl; }
        __syncthreads();
        if (tid == 0) carry += wsum[31];
        __syncthreads();
    }
}

__global__ void __launch_bounds__(256)
csr_pair_kernel(EdgePair p, int nE)
{
    int z = blockIdx.y;
    int e = blockIdx.x * blockDim.x + threadIdx.x;
    if (e >= nE) return;
    int pos = atomicAdd(&p.cur[z][p.dst[z][e]], 1);
    p.csr[z][pos] = p.src[z][e];
}

// ---------------------------------------------------------------------------
// Paired CSR aggregation: grid (nodes/8, 2 halves, 2 sides)
// ---------------------------------------------------------------------------
struct AggPair {
    const float* h[2];
    const int*   csr[2];
    const int*   off[2];
    const int*   deg[2];
    float*       agg[2];
};

__global__ void __launch_bounds__(256)
agg_pair_kernel(AggPair p, int n)
{
    int node = blockIdx.x * 8 + (threadIdx.x >> 5);
    if (node >= n) return;
    const int z = blockIdx.z;
    const float* __restrict__ h   = p.h[z];
    const int*   __restrict__ csr = p.csr[z];
    float*       __restrict__ agg = p.agg[z];
    int coff = blockIdx.y * 128;
    int lane = threadIdx.x & 31;
    int o = __ldg(&p.off[z][node]);
    int d = __ldg(&p.deg[z][node]);
    float4 acc = make_float4(0.f, 0.f, 0.f, 0.f);
    int j = 0;
    for (; j + 4 <= d; j += 4) {
        int s0 = __ldg(&csr[o + j]);
        int s1 = __ldg(&csr[o + j + 1]);
        int s2 = __ldg(&csr[o + j + 2]);
        int s3 = __ldg(&csr[o + j + 3]);
        float4 v0 = *reinterpret_cast<const float4*>(h + (size_t)s0 * HDIM + coff + lane * 4);
        float4 v1 = *reinterpret_cast<const float4*>(h + (size_t)s1 * HDIM + coff + lane * 4);
        float4 v2 = *reinterpret_cast<const float4*>(h + (size_t)s2 * HDIM + coff + lane * 4);
        float4 v3 = *reinterpret_cast<const float4*>(h + (size_t)s3 * HDIM + coff + lane * 4);
        acc.x += v0.x + v1.x + v2.x + v3.x;
        acc.y += v0.y + v1.y + v2.y + v3.y;
        acc.z += v0.z + v1.z + v2.z + v3.z;
        acc.w += v0.w + v1.w + v2.w + v3.w;
    }
    for (; j < d; j++) {
        int s = __ldg(&csr[o + j]);
        float4 v = *reinterpret_cast<const float4*>(h + (size_t)s * HDIM + coff + lane * 4);
        acc.x += v.x; acc.y += v.y; acc.z += v.z; acc.w += v.w;
    }
    float sc = 1.0f / fmaxf((float)d, 1.0f);
    float4 r;
    r.x = to_tf32(acc.x * sc);
    r.y = to_tf32(acc.y * sc);
    r.z = to_tf32(acc.z * sc);
    r.w = to_tf32(acc.w * sc);
    *reinterpret_cast<float4*>(agg + (size_t)node * HDIM + coff + lane * 4) = r;
}

// ---------------------------------------------------------------------------
// Paired in-place LayerNorm
// ---------------------------------------------------------------------------
struct LnPair {
    float*       x[2];
    const float* g[2];
    const float* b[2];
};

__global__ void __launch_bounds__(256)
ln_pair_kernel(LnPair pp, int M)
{
    int row  = blockIdx.x * 8 + (threadIdx.x >> 5);
    int lane = threadIdx.x & 31;
    if (row >= M) return;
    const int z = blockIdx.y;
    float* p = pp.x[z] + (size_t)row * HDIM + lane * 8;
    const float* g = pp.g[z];
    const float* b = pp.b[z];
    float4 v0 = *reinterpret_cast<const float4*>(p);
    float4 v1 = *reinterpret_cast<const float4*>(p + 4);
    float s  = v0.x + v0.y + v0.z + v0.w + v1.x + v1.y + v1.z + v1.w;
    float sq = v0.x*v0.x + v0.y*v0.y + v0.z*v0.z + v0.w*v0.w
             + v1.x*v1.x + v1.y*v1.y + v1.z*v1.z + v1.w*v1.w;
    #pragma unroll
    for (int m = 16; m > 0; m >>= 1) {
        s  += __shfl_xor_sync(0xffffffffu, s,  m);
        sq += __shfl_xor_sync(0xffffffffu, sq, m);
    }
    float mu   = s * (1.0f / 256.0f);
    float var  = sq * (1.0f / 256.0f) - mu * mu;
    float rstd = rsqrtf(var + 1e-5f);
    float4 g0 = *reinterpret_cast<const float4*>(g + lane * 8);
    float4 g1 = *reinterpret_cast<const float4*>(g + lane * 8 + 4);
    float4 b0 = *reinterpret_cast<const float4*>(b + lane * 8);
    float4 b1 = *reinterpret_cast<const float4*>(b + lane * 8 + 4);
    float4 o0, o1;
    o0.x = (v0.x - mu) * rstd * g0.x + b0.x;
    o0.y = (v0.y - mu) * rstd * g0.y + b0.y;
    o0.z = (v0.z - mu) * rstd * g0.z + b0.z;
    o0.w = (v0.w - mu) * rstd * g0.w + b0.w;
    o1.x = (v1.x - mu) * rstd * g1.x + b1.x;
    o1.y = (v1.y - mu) * rstd * g1.y + b1.y;
    o1.z = (v1.z - mu) * rstd * g1.z + b1.z;
    o1.w = (v1.w - mu) * rstd * g1.w + b1.w;
    *reinterpret_cast<float4*>(p)     = o0;
    *reinterpret_cast<float4*>(p + 4) = o1;
}

// ---------------------------------------------------------------------------
// Paired 3-stage cp.async tf32 GEMM with ldmatrix fragment loads.
// A row-major [m][k]; W pre-transposed [n][k]. Both smem tiles 128x32, ld=36.
//   C[M,256] = EPI( A1@W1 (+ A2@W2) + bias )
// ---------------------------------------------------------------------------
constexpr int BM   = 128;
constexpr int BK   = 32;
constexpr int LDT  = 36;                  // both tiles
constexpr int TILE_B = BM * LDT * 4;      // 18432 bytes per tile
constexpr int ST   = 3;

struct GemmPair {
    const float* A1[2];
    const float* A2[2];
    const float* W1[2];   // transposed [256][K]
    const float* W2[2];   // transposed [256][K]
    const float* bias[2];
    float*       C[2];
};

template<int K, bool HAS_A2, int EPI>
__global__ void __launch_bounds__(256, 2)
gemm_pair(GemmPair p, int M)
{
    __shared__ float a_s[ST][BM * LDT];
    __shared__ float b_s[ST][BM * LDT];

    constexpr int NIT = (HAS_A2 ? 2 : 1) * K / BK;

    const int zz = blockIdx.z;
    const float* __restrict__ A1g  = p.A1[zz];
    const float* __restrict__ A2g  = p.A2[zz];
    const float* __restrict__ W1g  = p.W1[zz];
    const float* __restrict__ W2g  = p.W2[zz];
    const float* __restrict__ bias = p.bias[zz];
    float*       __restrict__ C    = p.C[zz];

    const int tid  = threadIdx.x;
    const int lane = tid & 31;
    const int wid  = tid >> 5;
    const int wm   = wid >> 2;
    const int wn   = wid & 3;
    const int lq   = lane >> 2;
    const int lr   = lane & 3;
    const int row0 = blockIdx.x * BM;
    const int ncol0 = blockIdx.y * 128;

    // gmem->smem coords (same shape for A and B tiles)
    const int ar  = tid >> 3;          // + u*32 : tile row 0..127
    const int ac4 = (tid & 7) << 2;    // tile col (float), 0..28

    const uint32_t a_base = (uint32_t)__cvta_generic_to_shared(a_s);
    const uint32_t b_base = (uint32_t)__cvta_generic_to_shared(b_s);

    // ldmatrix per-lane offsets
    const int g8 = lane >> 3;
    const int l8 = lane & 7;
    // A x4: m0 rows0-7 c0 (a0), m1 rows8-15 c0 (a1), m2 rows0-7 c4 (a2), m3 rows8-15 c4 (a3)
    const int row_a = ((g8 & 1) << 3) + l8;
    const int col_a = (g8 >> 1) << 2;
    const uint32_t a_frag0 = a_base + (uint32_t)(((wm * 64 + row_a) * LDT + col_a) << 2);
    // B x4: m0 rows0-7 c0 (b_j0,0), m1 rows0-7 c4 (b_j0,1), m2 rows8-15 c0 (b_j1,0), m3 rows8-15 c4 (b_j1,1)
    const int row_b = ((g8 >> 1) << 3) + l8;
    const int col_b = (g8 & 1) << 2;
    const uint32_t b_frag0 = b_base + (uint32_t)(((wn * 32 + row_b) * LDT + col_b) << 2);

    float d[4][4][4];
    #pragma unroll
    for (int i = 0; i < 4; i++)
        #pragma unroll
        for (int j = 0; j < 4; j++)
            #pragma unroll
            for (int q = 0; q < 4; q++)
                d[i][j][q] = 0.f;

    auto load_stage = [&](int kt, int buf) {
        int kk = kt * BK;
        const float* __restrict__ A  = (HAS_A2 && kk >= K) ? A2g : A1g;
        const float* __restrict__ WT = (HAS_A2 && kk >= K) ? W2g : W1g;
        const int k0 = HAS_A2 ? (kk & (K - 1)) : kk;
        uint32_t ab = a_base + (uint32_t)(buf * TILE_B);
        uint32_t bb = b_base + (uint32_t)(buf * TILE_B);
        #pragma unroll
        for (int u = 0; u < 4; u++) {
            int r  = ar + u * 32;
            int gr = row0 + r;
            int gc = gr < M ? gr : (M - 1);
            cp16(ab + (uint32_t)((r * LDT + ac4) << 2),
                 A + (size_t)gc * K + k0 + ac4, gr < M);
            cp16(bb + (uint32_t)((r * LDT + ac4) << 2),
                 WT + (size_t)(ncol0 + r) * K + k0 + ac4, true);
        }
    };

    load_stage(0, 0);
    asm volatile("cp.async.commit_group;" ::: "memory");
    load_stage(1, 1);
    asm volatile("cp.async.commit_group;" ::: "memory");

    #pragma unroll 1
    for (int kt = 0; kt < NIT; kt++) {
        asm volatile("cp.async.wait_group 1;" ::: "memory");
        __syncthreads();
        if (kt + 2 < NIT) load_stage(kt + 2, (kt + 2) % ST);
        asm volatile("cp.async.commit_group;" ::: "memory");

        const int buf = kt % ST;
        const uint32_t af_base = a_frag0 + (uint32_t)(buf * TILE_B);
        const uint32_t bf_base = b_frag0 + (uint32_t)(buf * TILE_B);

        #pragma unroll
        for (int ks = 0; ks < 4; ks++) {
            uint32_t af[4][4];
            #pragma unroll
            for (int i = 0; i < 4; i++)
                ldsm4(af[i][0], af[i][1], af[i][2], af[i][3],
                      af_base + (uint32_t)(i * 16 * LDT * 4 + ks * 32));
            uint32_t bf[2][4];
            ldsm4(bf[0][0], bf[0][1], bf[0][2], bf[0][3],
                  bf_base + (uint32_t)(ks * 32));
            ldsm4(bf[1][0], bf[1][1], bf[1][2], bf[1][3],
                  bf_base + (uint32_t)(16 * LDT * 4 + ks * 32));
            #pragma unroll
            for (int i = 0; i < 4; i++) {
                mma_tf32(d[i][0][0], d[i][0][1], d[i][0][2], d[i][0][3],
                         af[i][0], af[i][1], af[i][2], af[i][3], bf[0][0], bf[0][1]);
                mma_tf32(d[i][1][0], d[i][1][1], d[i][1][2], d[i][1][3],
                         af[i][0], af[i][1], af[i][2], af[i][3], bf[0][2], bf[0][3]);
                mma_tf32(d[i][2][0], d[i][2][1], d[i][2][2], d[i][2][3],
                         af[i][0], af[i][1], af[i][2], af[i][3], bf[1][0], bf[1][1]);
                mma_tf32(d[i][3][0], d[i][3][1], d[i][3][2], d[i][3][3],
                         af[i][0], af[i][1], af[i][2], af[i][3], bf[1][2], bf[1][3]);
            }
        }
    }

    #pragma unroll
    for (int j = 0; j < 4; j++) {
        float2 b = *reinterpret_cast<const float2*>(bias + ncol0 + wn * 32 + j * 8 + 2 * lr);
        #pragma unroll
        for (int i = 0; i < 4; i++) {
            d[i][j][0] += b.x; d[i][j][1] += b.y;
            d[i][j][2] += b.x; d[i][j][3] += b.y;
        }
    }

    const int cbase = ncol0 + wn * 32;
    #pragma unroll
    for (int i = 0; i < 4; i++) {
        #pragma unroll
        for (int rr = 0; rr < 2; rr++) {
            int gr = row0 + wm * 64 + i * 16 + lq + rr * 8;
            if (gr < M) {
                #pragma unroll
                for (int j = 0; j < 4; j++) {
                    float2 v;
                    if (EPI == 0) {
                        v.x = to_tf32(gelu_f(d[i][j][rr * 2 + 0]));
                        v.y = to_tf32(gelu_f(d[i][j][rr * 2 + 1]));
                    } else {
                        v.x = d[i][j][rr * 2 + 0];
                        v.y = d[i][j][rr * 2 + 1];
                    }
                    *reinterpret_cast<float2*>(
                        C + (size_t)gr * HDIM + cbase + j * 8 + 2 * lr) = v;
                }
            }
        }
    }
}

// ---------------------------------------------------------------------------
// kernel_launch — fused-pair schedule, single stream
// ---------------------------------------------------------------------------
extern "C" void kernel_launch(void* const* d_in, const int* in_sizes, int n_in,
                              void* d_out, int out_size)
{
    const float* x_user    = (const float*)d_in[0];
    const float* x_item    = (const float*)d_in[1];
    const int*   ei_ui_src = (const int*)  d_in[2];
    const int*   ei_ui_dst = (const int*)  d_in[3];
    const int*   ei_iu_src = (const int*)  d_in[4];
    const int*   ei_iu_dst = (const int*)  d_in[5];
    const float* lin_user_W = (const float*)d_in[6];
    const float* lin_user_b = (const float*)d_in[7];
    const float* lin_item_W = (const float*)d_in[8];
    const float* lin_item_b = (const float*)d_in[9];
    const float* c0_ui_Wl = (const float*)d_in[10];
    const float* c0_ui_bl = (const float*)d_in[11];
    const float* c0_ui_Wr = (const float*)d_in[12];
    const float* c0_iu_Wl = (const float*)d_in[13];
    const float* c0_iu_bl = (const float*)d_in[14];
    const float* c0_iu_Wr = (const float*)d_in[15];
    const float* c1_ui_Wl = (const float*)d_in[16];
    const float* c1_ui_bl = (const float*)d_in[17];
    const float* c1_ui_Wr = (const float*)d_in[18];
    const float* c1_iu_Wl = (const float*)d_in[19];
    const float* c1_iu_bl = (const float*)d_in[20];
    const float* c1_iu_Wr = (const float*)d_in[21];
    const float* out_user_W = (const float*)d_in[22];
    const float* out_user_b = (const float*)d_in[23];
    const float* out_item_W = (const float*)d_in[24];
    const float* out_item_b = (const float*)d_in[25];
    const float* ln_user_g  = (const float*)d_in[26];
    const float* ln_user_b2 = (const float*)d_in[27];
    const float* ln_item_g  = (const float*)d_in[28];
    const float* ln_item_b2 = (const float*)d_in[29];

    float* out = (float*)d_out;
    const int nE = in_sizes[2];
    const int M  = NNODE;

    float *hu, *hi, *tu, *ti, *agg, *xu, *xi, *wts;
    int *deg, *off, *cur, *csr;
    cudaGetSymbolAddress((void**)&hu,  g_hu);
    cudaGetSymbolAddress((void**)&hi,  g_hi);
    cudaGetSymbolAddress((void**)&tu,  g_tu);
    cudaGetSymbolAddress((void**)&ti,  g_ti);
    cudaGetSymbolAddress((void**)&agg, g_agg);
    cudaGetSymbolAddress((void**)&deg, g_deg);
    cudaGetSymbolAddress((void**)&off, g_off);
    cudaGetSymbolAddress((void**)&cur, g_cur);
    cudaGetSymbolAddress((void**)&csr, g_csr);
    cudaGetSymbolAddress((void**)&xu,  g_xu);
    cudaGetSymbolAddress((void**)&xi,  g_xi);
    cudaGetSymbolAddress((void**)&wts, g_wts);

    float* agg0 = agg;
    float* agg1 = agg + (size_t)M * HDIM;
    int *deg0 = deg,     *deg1 = deg + M;
    int *off0 = off,     *off1 = off + M;
    int *cur0 = cur,     *cur1 = cur + M;
    int *csr0 = csr,     *csr1 = csr + EDGES;

    float* w_lin_u = wts;
    float* w_lin_i = w_lin_u + 32768;
    float* w_c[8];
    w_c[0] = w_lin_i + 32768;
    for (int i = 1; i < 8; i++) w_c[i] = w_c[i - 1] + 65536;
    float* w_out_u = w_c[7] + 65536;
    float* w_out_i = w_out_u + 65536;

    // transpose-convert pack: all 12 weight matrices (dst layout [256][K])
    TPack tp;
    const float* twsrc[NTW] = {
        lin_user_W, lin_item_W,
        c0_ui_Wl, c0_ui_Wr, c0_iu_Wl, c0_iu_Wr,
        c1_ui_Wl, c1_ui_Wr, c1_iu_Wl, c1_iu_Wr,
        out_user_W, out_item_W };
    float* twdst[NTW] = {
        w_lin_u, w_lin_i,
        w_c[0], w_c[1], w_c[2], w_c[3], w_c[4], w_c[5], w_c[6], w_c[7],
        w_out_u, w_out_i };
    int twK[NTW] = { DIN, DIN, HDIM, HDIM, HDIM, HDIM, HDIM, HDIM, HDIM, HDIM, HDIM, HDIM };
    for (int i = 0; i < NTW; i++) { tp.src[i] = twsrc[i]; tp.dst[i] = twdst[i]; tp.K[i] = twK[i]; }

    XPack xp;
    xp.src[0] = x_user; xp.dst[0] = xu; xp.n[0] = NNODE * DIN;
    xp.src[1] = x_item; xp.dst[1] = xi; xp.n[1] = NNODE * DIN;

    EdgePair ep;
    ep.src[0] = ei_ui_src; ep.src[1] = ei_iu_src;
    ep.dst[0] = ei_ui_dst; ep.dst[1] = ei_iu_dst;
    ep.deg[0] = deg0; ep.deg[1] = deg1;
    ep.off[0] = off0; ep.off[1] = off1;
    ep.cur[0] = cur0; ep.cur[1] = cur1;
    ep.csr[0] = csr0; ep.csr[1] = csr1;

    dim3 blk(256);
    dim3 grid_gemm((M + BM - 1) / BM, 2, 2);
    dim3 grid_edge((nE + 255) / 256, 2);
    dim3 grid_agg((M + 7) / 8, 2, 2);
    dim3 grid_ln((M + 7) / 8, 2);
    dim3 grid_cvx(2048, 2);
    dim3 grid_cvw(128, NTW);

    auto agg_pair = [&](const float* h0, const float* h1) {
        AggPair ap;
        ap.h[0] = h0;   ap.h[1] = h1;
        ap.csr[0] = csr0; ap.csr[1] = csr1;
        ap.off[0] = off0; ap.off[1] = off1;
        ap.deg[0] = deg0; ap.deg[1] = deg1;
        ap.agg[0] = agg0; ap.agg[1] = agg1;
        agg_pair_kernel<<<grid_agg, blk>>>(ap, M);
    };
    auto sage_pair = [&](const float* a1_0, const float* a2_0, float* wl0, float* wr0,
                         const float* bl0, float* c_0,
                         const float* a1_1, const float* a2_1, float* wl1, float* wr1,
                         const float* bl1, float* c_1) {
        GemmPair gp;
        gp.A1[0] = a1_0; gp.A2[0] = a2_0; gp.W1[0] = wl0; gp.W2[0] = wr0;
        gp.bias[0] = bl0; gp.C[0] = c_0;
        gp.A1[1] = a1_1; gp.A2[1] = a2_1; gp.W1[1] = wl1; gp.W2[1] = wr1;
        gp.bias[1] = bl1; gp.C[1] = c_1;
        gemm_pair<HDIM, true, 0><<<grid_gemm, blk>>>(gp, M);
    };

    /* 1 */ cudaMemsetAsync(deg, 0, 2 * M * sizeof(int));
    /* 2 */ cvt_x_kernel<<<grid_cvx, blk>>>(xp);
    /* 3 */ cvt_wT_kernel<<<grid_cvw, blk>>>(tp);
    /* 4 */ deg_pair_kernel<<<grid_edge, blk>>>(ep, nE);
    /* 5 */ scan_pair_kernel<<<2, 1024>>>(ep, M);
    /* 6 */ csr_pair_kernel<<<grid_edge, blk>>>(ep, nE);

    /* 7: input projections (pair) */
    {
        GemmPair gp;
        gp.A1[0] = xu; gp.A2[0] = nullptr; gp.W1[0] = w_lin_u; gp.W2[0] = nullptr;
        gp.bias[0] = lin_user_b; gp.C[0] = hu;
        gp.A1[1] = xi; gp.A2[1] = nullptr; gp.W1[1] = w_lin_i; gp.W2[1] = nullptr;
        gp.bias[1] = lin_item_b; gp.C[1] = hi;
        gemm_pair<DIN, false, 0><<<grid_gemm, blk>>>(gp, M);
    }

    /* 8: layer-0 aggregation (pair) */
    agg_pair(hu, hi);
    /* 9: layer-0 SAGE gemms (pair): ti, tu */
    sage_pair(agg0, hi, w_c[0], w_c[1], c0_ui_bl, ti,
              agg1, hu, w_c[2], w_c[3], c0_iu_bl, tu);

    /*10: layer-1 aggregation (pair) */
    agg_pair(tu, ti);
    /*11: layer-1 SAGE gemms (pair): hi, hu */
    sage_pair(agg0, ti, w_c[4], w_c[5], c1_ui_bl, hi,
              agg1, tu, w_c[6], w_c[7], c1_iu_bl, hu);

    /*12: heads (pair) */
    {
        GemmPair gp;
        gp.A1[0] = hu; gp.A2[0] = nullptr; gp.W1[0] = w_out_u; gp.W2[0] = nullptr;
        gp.bias[0] = out_user_b; gp.C[0] = out;
        gp.A1[1] = hi; gp.A2[1] = nullptr; gp.W1[1] = w_out_i; gp.W2[1] = nullptr;
        gp.bias[1] = out_item_b; gp.C[1] = out + (size_t)M * HDIM;
        gemm_pair<HDIM, false, 1><<<grid_gemm, blk>>>(gp, M);
    }
    /*13: LayerNorm (pair) */
    {
        LnPair lp;
        lp.x[0] = out;                     lp.x[1] = out + (size_t)M * HDIM;
        lp.g[0] = ln_user_g;               lp.g[1] = ln_item_g;
        lp.b[0] = ln_user_b2;              lp.b[1] = ln_item_b2;
        ln_pair_kernel<<<grid_ln, blk>>>(lp, M);
    }
}

// round 12
// speedup vs baseline: 2.2589x; 1.0222x over previous
#include <cuda_runtime.h>
#include <math.h>
#include <stdint.h>

#define NNODE 100000
#define EDGES 800000
#define DIN   128
#define HDIM  256
#define NB    98          // scan blocks per side: ceil(100000/1024)

// ---------------------------------------------------------------------------
// Scratch (__device__ globals; no allocation allowed)
// ---------------------------------------------------------------------------
__device__ float g_hu [(size_t)NNODE * HDIM];
__device__ float g_hi [(size_t)NNODE * HDIM];
__device__ float g_tu [(size_t)NNODE * HDIM];
__device__ float g_ti [(size_t)NNODE * HDIM];
__device__ float g_agg[2 * (size_t)NNODE * HDIM];   // agg0 | agg1
__device__ int   g_deg[2 * NNODE];
__device__ int   g_off[2 * NNODE];
__device__ int   g_cur[2 * NNODE];
__device__ int   g_csr[2 * EDGES];
__device__ int   g_bsum[2 * NB];
__device__ int   g_bpre[2 * NB];
__device__ float g_xu [(size_t)NNODE * DIN];        // tf32 x_user
__device__ float g_xi [(size_t)NNODE * DIN];        // tf32 x_item
__device__ float g_wts[2 * 32768 + 10 * 65536];     // tf32 TRANSPOSED weights

// ---------------------------------------------------------------------------
// Helpers
// ---------------------------------------------------------------------------
__device__ __forceinline__ float gelu_f(float x) {
    return 0.5f * x * (1.0f + erff(x * 0.70710678118654752f));
}
__device__ __forceinline__ float to_tf32(float x) {
    float r;
    asm("cvt.rna.tf32.f32 %0, %1;" : "=f"(r) : "f"(x));
    return r;
}
__device__ __forceinline__ void cvt4(float4& v) {
    v.x = to_tf32(v.x); v.y = to_tf32(v.y); v.z = to_tf32(v.z); v.w = to_tf32(v.w);
}
__device__ __forceinline__ void mma_tf32(float& d0, float& d1, float& d2, float& d3,
                                         uint32_t a0, uint32_t a1, uint32_t a2, uint32_t a3,
                                         uint32_t b0, uint32_t b1)
{
    asm volatile(
        "mma.sync.aligned.m16n8k8.row.col.f32.tf32.tf32.f32 "
        "{%0,%1,%2,%3}, {%4,%5,%6,%7}, {%8,%9}, {%0,%1,%2,%3};"
        : "+f"(d0), "+f"(d1), "+f"(d2), "+f"(d3)
        : "r"(a0), "r"(a1), "r"(a2), "r"(a3), "r"(b0), "r"(b1));
}
__device__ __forceinline__ void cp16(uint32_t dst, const void* src, bool pred) {
    int sz = pred ? 16 : 0;
    asm volatile("cp.async.ca.shared.global [%0], [%1], 16, %2;"
                 :: "r"(dst), "l"(src), "r"(sz));
}
__device__ __forceinline__ void ldsm4(uint32_t& r0, uint32_t& r1, uint32_t& r2, uint32_t& r3,
                                      uint32_t addr)
{
    asm volatile("ldmatrix.sync.aligned.m8n8.x4.shared.b16 {%0,%1,%2,%3}, [%4];"
                 : "=r"(r0), "=r"(r1), "=r"(r2), "=r"(r3) : "r"(addr));
}

// ---------------------------------------------------------------------------
// Pre-pass A: convert x_user/x_item to tf32
// ---------------------------------------------------------------------------
struct XPack { const float* src[2]; float* dst[2]; int n[2]; };

__global__ void __launch_bounds__(256)
cvt_x_kernel(XPack p)
{
    int m = blockIdx.y;
    const float4* s = reinterpret_cast<const float4*>(p.src[m]);
    float4*       d = reinterpret_cast<float4*>(p.dst[m]);
    int n4 = p.n[m] >> 2;
    for (int i = blockIdx.x * blockDim.x + threadIdx.x; i < n4;
         i += gridDim.x * blockDim.x) {
        float4 v = s[i];
        cvt4(v);
        d[i] = v;
    }
}

// ---------------------------------------------------------------------------
// Pre-pass B: convert + TRANSPOSE weights. src [K][256] -> dst [256][K], tf32.
// ---------------------------------------------------------------------------
#define NTW 12
struct TPack { const float* src[NTW]; float* dst[NTW]; int K[NTW]; };

__global__ void __launch_bounds__(256)
cvt_wT_kernel(TPack p)
{
    int m = blockIdx.y;
    const float* __restrict__ s = p.src[m];
    float*       __restrict__ d = p.dst[m];
    int K = p.K[m];
    int total = K * 256;
    for (int i = blockIdx.x * blockDim.x + threadIdx.x; i < total;
         i += gridDim.x * blockDim.x) {
        int k = i >> 8;
        int n = i & 255;
        d[n * K + k] = to_tf32(s[i]);
    }
}

// ---------------------------------------------------------------------------
// Paired CSR construction
// ---------------------------------------------------------------------------
struct EdgePair {
    const int* src[2];
    const int* dst[2];
    int*       deg[2];
    int*       off[2];
    int*       cur[2];
    int*       csr[2];
};

__global__ void __launch_bounds__(256)
deg_pair_kernel(EdgePair p, int nE) {
    int z = blockIdx.y;
    int i = blockIdx.x * blockDim.x + threadIdx.x;
    if (i < nE) atomicAdd(&p.deg[z][p.dst[z][i]], 1);
}

// Phase 1: per-block (1024-elem chunk) sums
__global__ void __launch_bounds__(256)
bsum_pair_kernel(EdgePair p, int n, int* __restrict__ bsum)
{
    int z = blockIdx.y;
    int b = blockIdx.x;
    int t = threadIdx.x;
    int base = b * 1024;
    int s = 0;
    #pragma unroll
    for (int u = 0; u < 4; u++) {
        int i = base + t + u * 256;
        if (i < n) s += p.deg[z][i];
    }
    #pragma unroll
    for (int m = 16; m > 0; m >>= 1) s += __shfl_xor_sync(0xffffffffu, s, m);
    __shared__ int ws[8];
    if ((t & 31) == 0) ws[t >> 5] = s;
    __syncthreads();
    if (t < 8) {
        int v = ws[t];
        #pragma unroll
        for (int m = 4; m > 0; m >>= 1) v += __shfl_xor_sync(0xffu, v, m);
        if (t == 0) bsum[z * NB + b] = v;
    }
}

// Phase 2: serial scan of NB partials per side (tiny)
__global__ void __launch_bounds__(32)
bscan_kernel(const int* __restrict__ bsum, int* __restrict__ bpre)
{
    int z = threadIdx.x;
    if (z < 2) {
        int acc = 0;
        for (int b = 0; b < NB; b++) {
            bpre[z * NB + b] = acc;
            acc += bsum[z * NB + b];
        }
    }
}

// Phase 3: block-local exclusive scan + block prefix -> off, cur
__global__ void __launch_bounds__(1024)
addoff_pair_kernel(EdgePair p, int n, const int* __restrict__ bpre)
{
    int z = blockIdx.y;
    int b = blockIdx.x;
    int i = b * 1024 + threadIdx.x;
    int lane = threadIdx.x & 31;
    int wid  = threadIdx.x >> 5;
    int v = (i < n) ? p.deg[z][i] : 0;
    int x = v;
    #pragma unroll
    for (int s = 1; s < 32; s <<= 1) {
        int y = __shfl_up_sync(0xffffffffu, x, s);
        if (lane >= s) x += y;
    }
    __shared__ int ws[32];
    if (lane == 31) ws[wid] = x;
    __syncthreads();
    if (wid == 0) {
        int w = ws[lane];
        #pragma unroll
        for (int s = 1; s < 32; s <<= 1) {
            int y = __shfl_up_sync(0xffffffffu, w, s);
            if (lane >= s) w += y;
        }
        ws[lane] = w;
    }
    __syncthreads();
    int excl = x - v + (wid > 0 ? ws[wid - 1] : 0) + bpre[z * NB + b];
    if (i < n) { p.off[z][i] = excl; p.cur[z][i] = excl; }
}

__global__ void __launch_bounds__(256)
csr_pair_kernel(EdgePair p, int nE)
{
    int z = blockIdx.y;
    int e = blockIdx.x * blockDim.x + threadIdx.x;
    if (e >= nE) return;
    int pos = atomicAdd(&p.cur[z][p.dst[z][e]], 1);
    p.csr[z][pos] = p.src[z][e];
}

// ---------------------------------------------------------------------------
// Paired CSR aggregation: grid (nodes/8, 2 halves, 2 sides)
// ---------------------------------------------------------------------------
struct AggPair {
    const float* h[2];
    const int*   csr[2];
    const int*   off[2];
    const int*   deg[2];
    float*       agg[2];
};

__global__ void __launch_bounds__(256)
agg_pair_kernel(AggPair p, int n)
{
    int node = blockIdx.x * 8 + (threadIdx.x >> 5);
    if (node >= n) return;
    const int z = blockIdx.z;
    const float* __restrict__ h   = p.h[z];
    const int*   __restrict__ csr = p.csr[z];
    float*       __restrict__ agg = p.agg[z];
    int coff = blockIdx.y * 128;
    int lane = threadIdx.x & 31;
    int o = __ldg(&p.off[z][node]);
    int d = __ldg(&p.deg[z][node]);
    float4 acc = make_float4(0.f, 0.f, 0.f, 0.f);
    int j = 0;
    for (; j + 4 <= d; j += 4) {
        int s0 = __ldg(&csr[o + j]);
        int s1 = __ldg(&csr[o + j + 1]);
        int s2 = __ldg(&csr[o + j + 2]);
        int s3 = __ldg(&csr[o + j + 3]);
        float4 v0 = *reinterpret_cast<const float4*>(h + (size_t)s0 * HDIM + coff + lane * 4);
        float4 v1 = *reinterpret_cast<const float4*>(h + (size_t)s1 * HDIM + coff + lane * 4);
        float4 v2 = *reinterpret_cast<const float4*>(h + (size_t)s2 * HDIM + coff + lane * 4);
        float4 v3 = *reinterpret_cast<const float4*>(h + (size_t)s3 * HDIM + coff + lane * 4);
        acc.x += v0.x + v1.x + v2.x + v3.x;
        acc.y += v0.y + v1.y + v2.y + v3.y;
        acc.z += v0.z + v1.z + v2.z + v3.z;
        acc.w += v0.w + v1.w + v2.w + v3.w;
    }
    for (; j < d; j++) {
        int s = __ldg(&csr[o + j]);
        float4 v = *reinterpret_cast<const float4*>(h + (size_t)s * HDIM + coff + lane * 4);
        acc.x += v.x; acc.y += v.y; acc.z += v.z; acc.w += v.w;
    }
    float sc = 1.0f / fmaxf((float)d, 1.0f);
    float4 r;
    r.x = to_tf32(acc.x * sc);
    r.y = to_tf32(acc.y * sc);
    r.z = to_tf32(acc.z * sc);
    r.w = to_tf32(acc.w * sc);
    *reinterpret_cast<float4*>(agg + (size_t)node * HDIM + coff + lane * 4) = r;
}

// ---------------------------------------------------------------------------
// Paired in-place LayerNorm
// ---------------------------------------------------------------------------
struct LnPair {
    float*       x[2];
    const float* g[2];
    const float* b[2];
};

__global__ void __launch_bounds__(256)
ln_pair_kernel(LnPair pp, int M)
{
    int row  = blockIdx.x * 8 + (threadIdx.x >> 5);
    int lane = threadIdx.x & 31;
    if (row >= M) return;
    const int z = blockIdx.y;
    float* p = pp.x[z] + (size_t)row * HDIM + lane * 8;
    const float* g = pp.g[z];
    const float* b = pp.b[z];
    float4 v0 = *reinterpret_cast<const float4*>(p);
    float4 v1 = *reinterpret_cast<const float4*>(p + 4);
    float s  = v0.x + v0.y + v0.z + v0.w + v1.x + v1.y + v1.z + v1.w;
    float sq = v0.x*v0.x + v0.y*v0.y + v0.z*v0.z + v0.w*v0.w
             + v1.x*v1.x + v1.y*v1.y + v1.z*v1.z + v1.w*v1.w;
    #pragma unroll
    for (int m = 16; m > 0; m >>= 1) {
        s  += __shfl_xor_sync(0xffffffffu, s,  m);
        sq += __shfl_xor_sync(0xffffffffu, sq, m);
    }
    float mu   = s * (1.0f / 256.0f);
    float var  = sq * (1.0f / 256.0f) - mu * mu;
    float rstd = rsqrtf(var + 1e-5f);
    float4 g0 = *reinterpret_cast<const float4*>(g + lane * 8);
    float4 g1 = *reinterpret_cast<const float4*>(g + lane * 8 + 4);
    float4 b0 = *reinterpret_cast<const float4*>(b + lane * 8);
    float4 b1 = *reinterpret_cast<const float4*>(b + lane * 8 + 4);
    float4 o0, o1;
    o0.x = (v0.x - mu) * rstd * g0.x + b0.x;
    o0.y = (v0.y - mu) * rstd * g0.y + b0.y;
    o0.z = (v0.z - mu) * rstd * g0.z + b0.z;
    o0.w = (v0.w - mu) * rstd * g0.w + b0.w;
    o1.x = (v1.x - mu) * rstd * g1.x + b1.x;
    o1.y = (v1.y - mu) * rstd * g1.y + b1.y;
    o1.z = (v1.z - mu) * rstd * g1.z + b1.z;
    o1.w = (v1.w - mu) * rstd * g1.w + b1.w;
    *reinterpret_cast<float4*>(p)     = o0;
    *reinterpret_cast<float4*>(p + 4) = o1;
}

// ---------------------------------------------------------------------------
// Paired 3-stage cp.async tf32 GEMM with ldmatrix fragment loads.
// ---------------------------------------------------------------------------
constexpr int BM   = 128;
constexpr int BK   = 32;
constexpr int LDT  = 36;
constexpr int TILE_B = BM * LDT * 4;
constexpr int ST   = 3;

struct GemmPair {
    const float* A1[2];
    const float* A2[2];
    const float* W1[2];   // transposed [256][K]
    const float* W2[2];   // transposed [256][K]
    const float* bias[2];
    float*       C[2];
};

template<int K, bool HAS_A2, int EPI>
__global__ void __launch_bounds__(256, 2)
gemm_pair(GemmPair p, int M)
{
    __shared__ float a_s[ST][BM * LDT];
    __shared__ float b_s[ST][BM * LDT];

    constexpr int NIT = (HAS_A2 ? 2 : 1) * K / BK;

    const int zz = blockIdx.z;
    const float* __restrict__ A1g  = p.A1[zz];
    const float* __restrict__ A2g  = p.A2[zz];
    const float* __restrict__ W1g  = p.W1[zz];
    const float* __restrict__ W2g  = p.W2[zz];
    const float* __restrict__ bias = p.bias[zz];
    float*       __restrict__ C    = p.C[zz];

    const int tid  = threadIdx.x;
    const int lane = tid & 31;
    const int wid  = tid >> 5;
    const int wm   = wid >> 2;
    const int wn   = wid & 3;
    const int lq   = lane >> 2;
    const int lr   = lane & 3;
    const int row0 = blockIdx.x * BM;
    const int ncol0 = blockIdx.y * 128;

    const int ar  = tid >> 3;
    const int ac4 = (tid & 7) << 2;

    const uint32_t a_base = (uint32_t)__cvta_generic_to_shared(a_s);
    const uint32_t b_base = (uint32_t)__cvta_generic_to_shared(b_s);

    const int g8 = lane >> 3;
    const int l8 = lane & 7;
    const int row_a = ((g8 & 1) << 3) + l8;
    const int col_a = (g8 >> 1) << 2;
    const uint32_t a_frag0 = a_base + (uint32_t)(((wm * 64 + row_a) * LDT + col_a) << 2);
    const int row_b = ((g8 >> 1) << 3) + l8;
    const int col_b = (g8 & 1) << 2;
    const uint32_t b_frag0 = b_base + (uint32_t)(((wn * 32 + row_b) * LDT + col_b) << 2);

    float d[4][4][4];
    #pragma unroll
    for (int i = 0; i < 4; i++)
        #pragma unroll
        for (int j = 0; j < 4; j++)
            #pragma unroll
            for (int q = 0; q < 4; q++)
                d[i][j][q] = 0.f;

    auto load_stage = [&](int kt, int buf) {
        int kk = kt * BK;
        const float* __restrict__ A  = (HAS_A2 && kk >= K) ? A2g : A1g;
        const float* __restrict__ WT = (HAS_A2 && kk >= K) ? W2g : W1g;
        const int k0 = HAS_A2 ? (kk & (K - 1)) : kk;
        uint32_t ab = a_base + (uint32_t)(buf * TILE_B);
        uint32_t bb = b_base + (uint32_t)(buf * TILE_B);
        #pragma unroll
        for (int u = 0; u < 4; u++) {
            int r  = ar + u * 32;
            int gr = row0 + r;
            int gc = gr < M ? gr : (M - 1);
            cp16(ab + (uint32_t)((r * LDT + ac4) << 2),
                 A + (size_t)gc * K + k0 + ac4, gr < M);
            cp16(bb + (uint32_t)((r * LDT + ac4) << 2),
                 WT + (size_t)(ncol0 + r) * K + k0 + ac4, true);
        }
    };

    load_stage(0, 0);
    asm volatile("cp.async.commit_group;" ::: "memory");
    load_stage(1, 1);
    asm volatile("cp.async.commit_group;" ::: "memory");

    #pragma unroll 1
    for (int kt = 0; kt < NIT; kt++) {
        asm volatile("cp.async.wait_group 1;" ::: "memory");
        __syncthreads();
        if (kt + 2 < NIT) load_stage(kt + 2, (kt + 2) % ST);
        asm volatile("cp.async.commit_group;" ::: "memory");

        const int buf = kt % ST;
        const uint32_t af_base = a_frag0 + (uint32_t)(buf * TILE_B);
        const uint32_t bf_base = b_frag0 + (uint32_t)(buf * TILE_B);

        #pragma unroll
        for (int ks = 0; ks < 4; ks++) {
            uint32_t af[4][4];
            #pragma unroll
            for (int i = 0; i < 4; i++)
                ldsm4(af[i][0], af[i][1], af[i][2], af[i][3],
                      af_base + (uint32_t)(i * 16 * LDT * 4 + ks * 32));
            uint32_t bf[2][4];
            ldsm4(bf[0][0], bf[0][1], bf[0][2], bf[0][3],
                  bf_base + (uint32_t)(ks * 32));
            ldsm4(bf[1][0], bf[1][1], bf[1][2], bf[1][3],
                  bf_base + (uint32_t)(16 * LDT * 4 + ks * 32));
            #pragma unroll
            for (int i = 0; i < 4; i++) {
                mma_tf32(d[i][0][0], d[i][0][1], d[i][0][2], d[i][0][3],
                         af[i][0], af[i][1], af[i][2], af[i][3], bf[0][0], bf[0][1]);
                mma_tf32(d[i][1][0], d[i][1][1], d[i][1][2], d[i][1][3],
                         af[i][0], af[i][1], af[i][2], af[i][3], bf[0][2], bf[0][3]);
                mma_tf32(d[i][2][0], d[i][2][1], d[i][2][2], d[i][2][3],
                         af[i][0], af[i][1], af[i][2], af[i][3], bf[1][0], bf[1][1]);
                mma_tf32(d[i][3][0], d[i][3][1], d[i][3][2], d[i][3][3],
                         af[i][0], af[i][1], af[i][2], af[i][3], bf[1][2], bf[1][3]);
            }
        }
    }

    #pragma unroll
    for (int j = 0; j < 4; j++) {
        float2 b = *reinterpret_cast<const float2*>(bias + ncol0 + wn * 32 + j * 8 + 2 * lr);
        #pragma unroll
        for (int i = 0; i < 4; i++) {
            d[i][j][0] += b.x; d[i][j][1] += b.y;
            d[i][j][2] += b.x; d[i][j][3] += b.y;
        }
    }

    const int cbase = ncol0 + wn * 32;
    #pragma unroll
    for (int i = 0; i < 4; i++) {
        #pragma unroll
        for (int rr = 0; rr < 2; rr++) {
            int gr = row0 + wm * 64 + i * 16 + lq + rr * 8;
            if (gr < M) {
                #pragma unroll
                for (int j = 0; j < 4; j++) {
                    float2 v;
                    if (EPI == 0) {
                        v.x = to_tf32(gelu_f(d[i][j][rr * 2 + 0]));
                        v.y = to_tf32(gelu_f(d[i][j][rr * 2 + 1]));
                    } else {
                        v.x = d[i][j][rr * 2 + 0];
                        v.y = d[i][j][rr * 2 + 1];
                    }
                    *reinterpret_cast<float2*>(
                        C + (size_t)gr * HDIM + cbase + j * 8 + 2 * lr) = v;
                }
            }
        }
    }
}

// ---------------------------------------------------------------------------
// kernel_launch
// ---------------------------------------------------------------------------
extern "C" void kernel_launch(void* const* d_in, const int* in_sizes, int n_in,
                              void* d_out, int out_size)
{
    const float* x_user    = (const float*)d_in[0];
    const float* x_item    = (const float*)d_in[1];
    const int*   ei_ui_src = (const int*)  d_in[2];
    const int*   ei_ui_dst = (const int*)  d_in[3];
    const int*   ei_iu_src = (const int*)  d_in[4];
    const int*   ei_iu_dst = (const int*)  d_in[5];
    const float* lin_user_W = (const float*)d_in[6];
    const float* lin_user_b = (const float*)d_in[7];
    const float* lin_item_W = (const float*)d_in[8];
    const float* lin_item_b = (const float*)d_in[9];
    const float* c0_ui_Wl = (const float*)d_in[10];
    const float* c0_ui_bl = (const float*)d_in[11];
    const float* c0_ui_Wr = (const float*)d_in[12];
    const float* c0_iu_Wl = (const float*)d_in[13];
    const float* c0_iu_bl = (const float*)d_in[14];
    const float* c0_iu_Wr = (const float*)d_in[15];
    const float* c1_ui_Wl = (const float*)d_in[16];
    const float* c1_ui_bl = (const float*)d_in[17];
    const float* c1_ui_Wr = (const float*)d_in[18];
    const float* c1_iu_Wl = (const float*)d_in[19];
    const float* c1_iu_bl = (const float*)d_in[20];
    const float* c1_iu_Wr = (const float*)d_in[21];
    const float* out_user_W = (const float*)d_in[22];
    const float* out_user_b = (const float*)d_in[23];
    const float* out_item_W = (const float*)d_in[24];
    const float* out_item_b = (const float*)d_in[25];
    const float* ln_user_g  = (const float*)d_in[26];
    const float* ln_user_b2 = (const float*)d_in[27];
    const float* ln_item_g  = (const float*)d_in[28];
    const float* ln_item_b2 = (const float*)d_in[29];

    float* out = (float*)d_out;
    const int nE = in_sizes[2];
    const int M  = NNODE;

    float *hu, *hi, *tu, *ti, *agg, *xu, *xi, *wts;
    int *deg, *off, *cur, *csr, *bsum, *bpre;
    cudaGetSymbolAddress((void**)&hu,  g_hu);
    cudaGetSymbolAddress((void**)&hi,  g_hi);
    cudaGetSymbolAddress((void**)&tu,  g_tu);
    cudaGetSymbolAddress((void**)&ti,  g_ti);
    cudaGetSymbolAddress((void**)&agg, g_agg);
    cudaGetSymbolAddress((void**)&deg, g_deg);
    cudaGetSymbolAddress((void**)&off, g_off);
    cudaGetSymbolAddress((void**)&cur, g_cur);
    cudaGetSymbolAddress((void**)&csr, g_csr);
    cudaGetSymbolAddress((void**)&bsum, g_bsum);
    cudaGetSymbolAddress((void**)&bpre, g_bpre);
    cudaGetSymbolAddress((void**)&xu,  g_xu);
    cudaGetSymbolAddress((void**)&xi,  g_xi);
    cudaGetSymbolAddress((void**)&wts, g_wts);

    float* agg0 = agg;
    float* agg1 = agg + (size_t)M * HDIM;
    int *deg0 = deg,     *deg1 = deg + M;
    int *off0 = off,     *off1 = off + M;
    int *cur0 = cur,     *cur1 = cur + M;
    int *csr0 = csr,     *csr1 = csr + EDGES;

    float* w_lin_u = wts;
    float* w_lin_i = w_lin_u + 32768;
    float* w_c[8];
    w_c[0] = w_lin_i + 32768;
    for (int i = 1; i < 8; i++) w_c[i] = w_c[i - 1] + 65536;
    float* w_out_u = w_c[7] + 65536;
    float* w_out_i = w_out_u + 65536;

    TPack tp;
    const float* twsrc[NTW] = {
        lin_user_W, lin_item_W,
        c0_ui_Wl, c0_ui_Wr, c0_iu_Wl, c0_iu_Wr,
        c1_ui_Wl, c1_ui_Wr, c1_iu_Wl, c1_iu_Wr,
        out_user_W, out_item_W };
    float* twdst[NTW] = {
        w_lin_u, w_lin_i,
        w_c[0], w_c[1], w_c[2], w_c[3], w_c[4], w_c[5], w_c[6], w_c[7],
        w_out_u, w_out_i };
    int twK[NTW] = { DIN, DIN, HDIM, HDIM, HDIM, HDIM, HDIM, HDIM, HDIM, HDIM, HDIM, HDIM };
    for (int i = 0; i < NTW; i++) { tp.src[i] = twsrc[i]; tp.dst[i] = twdst[i]; tp.K[i] = twK[i]; }

    XPack xp;
    xp.src[0] = x_user; xp.dst[0] = xu; xp.n[0] = NNODE * DIN;
    xp.src[1] = x_item; xp.dst[1] = xi; xp.n[1] = NNODE * DIN;

    EdgePair ep;
    ep.src[0] = ei_ui_src; ep.src[1] = ei_iu_src;
    ep.dst[0] = ei_ui_dst; ep.dst[1] = ei_iu_dst;
    ep.deg[0] = deg0; ep.deg[1] = deg1;
    ep.off[0] = off0; ep.off[1] = off1;
    ep.cur[0] = cur0; ep.cur[1] = cur1;
    ep.csr[0] = csr0; ep.csr[1] = csr1;

    dim3 blk(256);
    dim3 grid_gemm((M + BM - 1) / BM, 2, 2);
    dim3 grid_edge((nE + 255) / 256, 2);
    dim3 grid_scan(NB, 2);
    dim3 grid_agg((M + 7) / 8, 2, 2);
    dim3 grid_ln((M + 7) / 8, 2);
    dim3 grid_cvx(2048, 2);
    dim3 grid_cvw(128, NTW);

    auto agg_pair = [&](const float* h0, const float* h1) {
        AggPair ap;
        ap.h[0] = h0;   ap.h[1] = h1;
        ap.csr[0] = csr0; ap.csr[1] = csr1;
        ap.off[0] = off0; ap.off[1] = off1;
        ap.deg[0] = deg0; ap.deg[1] = deg1;
        ap.agg[0] = agg0; ap.agg[1] = agg1;
        agg_pair_kernel<<<grid_agg, blk>>>(ap, M);
    };
    auto sage_pair = [&](const float* a1_0, const float* a2_0, float* wl0, float* wr0,
                         const float* bl0, float* c_0,
                         const float* a1_1, const float* a2_1, float* wl1, float* wr1,
                         const float* bl1, float* c_1) {
        GemmPair gp;
        gp.A1[0] = a1_0; gp.A2[0] = a2_0; gp.W1[0] = wl0; gp.W2[0] = wr0;
        gp.bias[0] = bl0; gp.C[0] = c_0;
        gp.A1[1] = a1_1; gp.A2[1] = a2_1; gp.W1[1] = wl1; gp.W2[1] = wr1;
        gp.bias[1] = bl1; gp.C[1] = c_1;
        gemm_pair<HDIM, true, 0><<<grid_gemm, blk>>>(gp, M);
    };

    /* memset  */ cudaMemsetAsync(deg, 0, 2 * M * sizeof(int));
    /* k1 */ cvt_x_kernel<<<grid_cvx, blk>>>(xp);
    /* k2 */ cvt_wT_kernel<<<grid_cvw, blk>>>(tp);
    /* k3 */ deg_pair_kernel<<<grid_edge, blk>>>(ep, nE);

    /* k4: input projections (pair) — PROFILED SLOT */
    {
        GemmPair gp;
        gp.A1[0] = xu; gp.A2[0] = nullptr; gp.W1[0] = w_lin_u; gp.W2[0] = nullptr;
        gp.bias[0] = lin_user_b; gp.C[0] = hu;
        gp.A1[1] = xi; gp.A2[1] = nullptr; gp.W1[1] = w_lin_i; gp.W2[1] = nullptr;
        gp.bias[1] = lin_item_b; gp.C[1] = hi;
        gemm_pair<DIN, false, 0><<<grid_gemm, blk>>>(gp, M);
    }

    /* k5-7: multi-block scan */
    bsum_pair_kernel<<<grid_scan, blk>>>(ep, M, bsum);
    bscan_kernel<<<1, 32>>>(bsum, bpre);
    addoff_pair_kernel<<<dim3(NB, 2), 1024>>>(ep, M, bpre);
    /* k8 */ csr_pair_kernel<<<grid_edge, blk>>>(ep, nE);

    /* k9: layer-0 aggregation (pair) */
    agg_pair(hu, hi);
    /* k10: layer-0 SAGE gemms (pair): ti, tu */
    sage_pair(agg0, hi, w_c[0], w_c[1], c0_ui_bl, ti,
              agg1, hu, w_c[2], w_c[3], c0_iu_bl, tu);

    /* k11: layer-1 aggregation (pair) */
    agg_pair(tu, ti);
    /* k12: layer-1 SAGE gemms (pair): hi, hu */
    sage_pair(agg0, ti, w_c[4], w_c[5], c1_ui_bl, hi,
              agg1, tu, w_c[6], w_c[7], c1_iu_bl, hu);

    /* k13: heads (pair) */
    {
        GemmPair gp;
        gp.A1[0] = hu; gp.A2[0] = nullptr; gp.W1[0] = w_out_u; gp.W2[0] = nullptr;
        gp.bias[0] = out_user_b; gp.C[0] = out;
        gp.A1[1] = hi; gp.A2[1] = nullptr; gp.W1[1] = w_out_i; gp.W2[1] = nullptr;
        gp.bias[1] = out_item_b; gp.C[1] = out + (size_t)M * HDIM;
        gemm_pair<HDIM, false, 1><<<grid_gemm, blk>>>(gp, M);
    }
    /* k14: LayerNorm (pair) */
    {
        LnPair lp;
        lp.x[0] = out;                     lp.x[1] = out + (size_t)M * HDIM;
        lp.g[0] = ln_user_g;               lp.g[1] = ln_item_g;
        lp.b[0] = ln_user_b2;              lp.b[1] = ln_item_b2;
        ln_pair_kernel<<<grid_ln, blk>>>(lp, M);
    }
}

// round 13
// speedup vs baseline: 2.3811x; 1.0541x over previous
#include <cuda_runtime.h>
#include <math.h>
#include <stdint.h>

#define NNODE 100000
#define EDGES 800000
#define DIN   128
#define HDIM  256
#define NB    98          // scan blocks per side: ceil(100000/1024)

// ---------------------------------------------------------------------------
// Scratch (__device__ globals; no allocation allowed)
// ---------------------------------------------------------------------------
__device__ float g_hu [(size_t)NNODE * HDIM];
__device__ float g_hi [(size_t)NNODE * HDIM];
__device__ float g_tu [(size_t)NNODE * HDIM];
__device__ float g_ti [(size_t)NNODE * HDIM];
__device__ float g_agg[2 * (size_t)NNODE * HDIM];   // agg0 | agg1
__device__ int   g_deg[2 * NNODE];
__device__ int   g_off[2 * NNODE];
__device__ int   g_cur[2 * NNODE];
__device__ int   g_csr[2 * EDGES];
__device__ int   g_bsum[2 * NB];
__device__ int   g_bpre[2 * NB];
__device__ float g_xu [(size_t)NNODE * DIN];        // tf32 x_user
__device__ float g_xi [(size_t)NNODE * DIN];        // tf32 x_item
__device__ float g_wts[2 * 32768 + 10 * 65536];     // tf32 TRANSPOSED weights

// ---------------------------------------------------------------------------
// Helpers
// ---------------------------------------------------------------------------
__device__ __forceinline__ float gelu_f(float x) {
    return 0.5f * x * (1.0f + erff(x * 0.70710678118654752f));
}
__device__ __forceinline__ float to_tf32(float x) {
    float r;
    asm("cvt.rna.tf32.f32 %0, %1;" : "=f"(r) : "f"(x));
    return r;
}
__device__ __forceinline__ void cvt4(float4& v) {
    v.x = to_tf32(v.x); v.y = to_tf32(v.y); v.z = to_tf32(v.z); v.w = to_tf32(v.w);
}
__device__ __forceinline__ void mma_tf32(float& d0, float& d1, float& d2, float& d3,
                                         uint32_t a0, uint32_t a1, uint32_t a2, uint32_t a3,
                                         uint32_t b0, uint32_t b1)
{
    asm volatile(
        "mma.sync.aligned.m16n8k8.row.col.f32.tf32.tf32.f32 "
        "{%0,%1,%2,%3}, {%4,%5,%6,%7}, {%8,%9}, {%0,%1,%2,%3};"
        : "+f"(d0), "+f"(d1), "+f"(d2), "+f"(d3)
        : "r"(a0), "r"(a1), "r"(a2), "r"(a3), "r"(b0), "r"(b1));
}
__device__ __forceinline__ void cp16(uint32_t dst, const void* src, bool pred) {
    int sz = pred ? 16 : 0;
    asm volatile("cp.async.ca.shared.global [%0], [%1], 16, %2;"
                 :: "r"(dst), "l"(src), "r"(sz));
}
__device__ __forceinline__ void ldsm4(uint32_t& r0, uint32_t& r1, uint32_t& r2, uint32_t& r3,
                                      uint32_t addr)
{
    asm volatile("ldmatrix.sync.aligned.m8n8.x4.shared.b16 {%0,%1,%2,%3}, [%4];"
                 : "=r"(r0), "=r"(r1), "=r"(r2), "=r"(r3) : "r"(addr));
}

// ---------------------------------------------------------------------------
// Pre-pass A: convert x_user/x_item to tf32
// ---------------------------------------------------------------------------
struct XPack { const float* src[2]; float* dst[2]; int n[2]; };

__global__ void __launch_bounds__(256)
cvt_x_kernel(XPack p)
{
    int m = blockIdx.y;
    const float4* s = reinterpret_cast<const float4*>(p.src[m]);
    float4*       d = reinterpret_cast<float4*>(p.dst[m]);
    int n4 = p.n[m] >> 2;
    for (int i = blockIdx.x * blockDim.x + threadIdx.x; i < n4;
         i += gridDim.x * blockDim.x) {
        float4 v = s[i];
        cvt4(v);
        d[i] = v;
    }
}

// ---------------------------------------------------------------------------
// Pre-pass B: convert + TRANSPOSE weights via 32x32 smem tiles.
// src [K][256] -> dst [256][K], tf32. Coalesced reads AND writes.
// ---------------------------------------------------------------------------
#define NTW 12
struct TPack { const float* src[NTW]; float* dst[NTW]; int K[NTW]; };

__global__ void __launch_bounds__(256)
cvt_wT_kernel(TPack p)
{
    __shared__ float tile[32][33];
    int m = blockIdx.y;
    int K = p.K[m];
    int kt = (blockIdx.x & 7) * 32;     // k tile base
    int nt = (blockIdx.x >> 3) * 32;    // n tile base
    if (kt >= K) return;
    const float* __restrict__ s = p.src[m];
    float*       __restrict__ d = p.dst[m];
    int tx = threadIdx.x & 31;
    int ty = threadIdx.x >> 5;          // 0..7
    #pragma unroll
    for (int u = 0; u < 4; u++) {
        int r = ty + u * 8;
        tile[r][tx] = to_tf32(s[(size_t)(kt + r) * 256 + nt + tx]);
    }
    __syncthreads();
    #pragma unroll
    for (int u = 0; u < 4; u++) {
        int r = ty + u * 8;             // n within tile
        d[(size_t)(nt + r) * K + kt + tx] = tile[tx][r];
    }
}

// ---------------------------------------------------------------------------
// Paired CSR construction
// ---------------------------------------------------------------------------
struct EdgePair {
    const int* src[2];
    const int* dst[2];
    int*       deg[2];
    int*       off[2];
    int*       cur[2];
    int*       csr[2];
};

__global__ void __launch_bounds__(256)
deg_pair_kernel(EdgePair p, int nE) {
    int z = blockIdx.y;
    int i = blockIdx.x * blockDim.x + threadIdx.x;
    if (i < nE) atomicAdd(&p.deg[z][p.dst[z][i]], 1);
}

__global__ void __launch_bounds__(256)
bsum_pair_kernel(EdgePair p, int n, int* __restrict__ bsum)
{
    int z = blockIdx.y;
    int b = blockIdx.x;
    int t = threadIdx.x;
    int base = b * 1024;
    int s = 0;
    #pragma unroll
    for (int u = 0; u < 4; u++) {
        int i = base + t + u * 256;
        if (i < n) s += p.deg[z][i];
    }
    #pragma unroll
    for (int m = 16; m > 0; m >>= 1) s += __shfl_xor_sync(0xffffffffu, s, m);
    __shared__ int ws[8];
    if ((t & 31) == 0) ws[t >> 5] = s;
    __syncthreads();
    if (t < 8) {
        int v = ws[t];
        #pragma unroll
        for (int m = 4; m > 0; m >>= 1) v += __shfl_xor_sync(0xffu, v, m);
        if (t == 0) bsum[z * NB + b] = v;
    }
}

__global__ void __launch_bounds__(32)
bscan_kernel(const int* __restrict__ bsum, int* __restrict__ bpre)
{
    int z = threadIdx.x;
    if (z < 2) {
        int acc = 0;
        for (int b = 0; b < NB; b++) {
            bpre[z * NB + b] = acc;
            acc += bsum[z * NB + b];
        }
    }
}

__global__ void __launch_bounds__(1024)
addoff_pair_kernel(EdgePair p, int n, const int* __restrict__ bpre)
{
    int z = blockIdx.y;
    int b = blockIdx.x;
    int i = b * 1024 + threadIdx.x;
    int lane = threadIdx.x & 31;
    int wid  = threadIdx.x >> 5;
    int v = (i < n) ? p.deg[z][i] : 0;
    int x = v;
    #pragma unroll
    for (int s = 1; s < 32; s <<= 1) {
        int y = __shfl_up_sync(0xffffffffu, x, s);
        if (lane >= s) x += y;
    }
    __shared__ int ws[32];
    if (lane == 31) ws[wid] = x;
    __syncthreads();
    if (wid == 0) {
        int w = ws[lane];
        #pragma unroll
        for (int s = 1; s < 32; s <<= 1) {
            int y = __shfl_up_sync(0xffffffffu, w, s);
            if (lane >= s) w += y;
        }
        ws[lane] = w;
    }
    __syncthreads();
    int excl = x - v + (wid > 0 ? ws[wid - 1] : 0) + bpre[z * NB + b];
    if (i < n) { p.off[z][i] = excl; p.cur[z][i] = excl; }
}

__global__ void __launch_bounds__(256)
csr_pair_kernel(EdgePair p, int nE)
{
    int z = blockIdx.y;
    int e = blockIdx.x * blockDim.x + threadIdx.x;
    if (e >= nE) return;
    int pos = atomicAdd(&p.cur[z][p.dst[z][e]], 1);
    p.csr[z][pos] = p.src[z][e];
}

// ---------------------------------------------------------------------------
// Paired CSR aggregation
// ---------------------------------------------------------------------------
struct AggPair {
    const float* h[2];
    const int*   csr[2];
    const int*   off[2];
    const int*   deg[2];
    float*       agg[2];
};

__global__ void __launch_bounds__(256)
agg_pair_kernel(AggPair p, int n)
{
    int node = blockIdx.x * 8 + (threadIdx.x >> 5);
    if (node >= n) return;
    const int z = blockIdx.z;
    const float* __restrict__ h   = p.h[z];
    const int*   __restrict__ csr = p.csr[z];
    float*       __restrict__ agg = p.agg[z];
    int coff = blockIdx.y * 128;
    int lane = threadIdx.x & 31;
    int o = __ldg(&p.off[z][node]);
    int d = __ldg(&p.deg[z][node]);
    float4 acc = make_float4(0.f, 0.f, 0.f, 0.f);
    int j = 0;
    for (; j + 4 <= d; j += 4) {
        int s0 = __ldg(&csr[o + j]);
        int s1 = __ldg(&csr[o + j + 1]);
        int s2 = __ldg(&csr[o + j + 2]);
        int s3 = __ldg(&csr[o + j + 3]);
        float4 v0 = *reinterpret_cast<const float4*>(h + (size_t)s0 * HDIM + coff + lane * 4);
        float4 v1 = *reinterpret_cast<const float4*>(h + (size_t)s1 * HDIM + coff + lane * 4);
        float4 v2 = *reinterpret_cast<const float4*>(h + (size_t)s2 * HDIM + coff + lane * 4);
        float4 v3 = *reinterpret_cast<const float4*>(h + (size_t)s3 * HDIM + coff + lane * 4);
        acc.x += v0.x + v1.x + v2.x + v3.x;
        acc.y += v0.y + v1.y + v2.y + v3.y;
        acc.z += v0.z + v1.z + v2.z + v3.z;
        acc.w += v0.w + v1.w + v2.w + v3.w;
    }
    for (; j < d; j++) {
        int s = __ldg(&csr[o + j]);
        float4 v = *reinterpret_cast<const float4*>(h + (size_t)s * HDIM + coff + lane * 4);
        acc.x += v.x; acc.y += v.y; acc.z += v.z; acc.w += v.w;
    }
    float sc = 1.0f / fmaxf((float)d, 1.0f);
    float4 r;
    r.x = to_tf32(acc.x * sc);
    r.y = to_tf32(acc.y * sc);
    r.z = to_tf32(acc.z * sc);
    r.w = to_tf32(acc.w * sc);
    *reinterpret_cast<float4*>(agg + (size_t)node * HDIM + coff + lane * 4) = r;
}

// ---------------------------------------------------------------------------
// Paired in-place LayerNorm
// ---------------------------------------------------------------------------
struct LnPair {
    float*       x[2];
    const float* g[2];
    const float* b[2];
};

__global__ void __launch_bounds__(256)
ln_pair_kernel(LnPair pp, int M)
{
    int row  = blockIdx.x * 8 + (threadIdx.x >> 5);
    int lane = threadIdx.x & 31;
    if (row >= M) return;
    const int z = blockIdx.y;
    float* p = pp.x[z] + (size_t)row * HDIM + lane * 8;
    const float* g = pp.g[z];
    const float* b = pp.b[z];
    float4 v0 = *reinterpret_cast<const float4*>(p);
    float4 v1 = *reinterpret_cast<const float4*>(p + 4);
    float s  = v0.x + v0.y + v0.z + v0.w + v1.x + v1.y + v1.z + v1.w;
    float sq = v0.x*v0.x + v0.y*v0.y + v0.z*v0.z + v0.w*v0.w
             + v1.x*v1.x + v1.y*v1.y + v1.z*v1.z + v1.w*v1.w;
    #pragma unroll
    for (int m = 16; m > 0; m >>= 1) {
        s  += __shfl_xor_sync(0xffffffffu, s,  m);
        sq += __shfl_xor_sync(0xffffffffu, sq, m);
    }
    float mu   = s * (1.0f / 256.0f);
    float var  = sq * (1.0f / 256.0f) - mu * mu;
    float rstd = rsqrtf(var + 1e-5f);
    float4 g0 = *reinterpret_cast<const float4*>(g + lane * 8);
    float4 g1 = *reinterpret_cast<const float4*>(g + lane * 8 + 4);
    float4 b0 = *reinterpret_cast<const float4*>(b + lane * 8);
    float4 b1 = *reinterpret_cast<const float4*>(b + lane * 8 + 4);
    float4 o0, o1;
    o0.x = (v0.x - mu) * rstd * g0.x + b0.x;
    o0.y = (v0.y - mu) * rstd * g0.y + b0.y;
    o0.z = (v0.z - mu) * rstd * g0.z + b0.z;
    o0.w = (v0.w - mu) * rstd * g0.w + b0.w;
    o1.x = (v1.x - mu) * rstd * g1.x + b1.x;
    o1.y = (v1.y - mu) * rstd * g1.y + b1.y;
    o1.z = (v1.z - mu) * rstd * g1.z + b1.z;
    o1.w = (v1.w - mu) * rstd * g1.w + b1.w;
    *reinterpret_cast<float4*>(p)     = o0;
    *reinterpret_cast<float4*>(p + 4) = o1;
}

// ---------------------------------------------------------------------------
// Paired 3-stage cp.async tf32 GEMM with ldmatrix fragment loads.
// Grid: (ncol=2, rowblk, side=2) — x-fastest launch order co-schedules the
// two column-blocks of the SAME A rows for L2 reuse of the A stream.
// ---------------------------------------------------------------------------
constexpr int BM   = 128;
constexpr int BK   = 32;
constexpr int LDT  = 36;
constexpr int TILE_B = BM * LDT * 4;
constexpr int ST   = 3;

struct GemmPair {
    const float* A1[2];
    const float* A2[2];
    const float* W1[2];   // transposed [256][K]
    const float* W2[2];   // transposed [256][K]
    const float* bias[2];
    float*       C[2];
};

template<int K, bool HAS_A2, int EPI>
__global__ void __launch_bounds__(256, 2)
gemm_pair(GemmPair p, int M)
{
    __shared__ float a_s[ST][BM * LDT];
    __shared__ float b_s[ST][BM * LDT];

    constexpr int NIT = (HAS_A2 ? 2 : 1) * K / BK;

    const int zz = blockIdx.z;
    const float* __restrict__ A1g  = p.A1[zz];
    const float* __restrict__ A2g  = p.A2[zz];
    const float* __restrict__ W1g  = p.W1[zz];
    const float* __restrict__ W2g  = p.W2[zz];
    const float* __restrict__ bias = p.bias[zz];
    float*       __restrict__ C    = p.C[zz];

    const int tid  = threadIdx.x;
    const int lane = tid & 31;
    const int wid  = tid >> 5;
    const int wm   = wid >> 2;
    const int wn   = wid & 3;
    const int lq   = lane >> 2;
    const int lr   = lane & 3;
    const int row0 = blockIdx.y * BM;       // row block (slow axis)
    const int ncol0 = blockIdx.x * 128;     // column block (fast axis -> L2 reuse)

    const int ar  = tid >> 3;
    const int ac4 = (tid & 7) << 2;

    const uint32_t a_base = (uint32_t)__cvta_generic_to_shared(a_s);
    const uint32_t b_base = (uint32_t)__cvta_generic_to_shared(b_s);

    const int g8 = lane >> 3;
    const int l8 = lane & 7;
    const int row_a = ((g8 & 1) << 3) + l8;
    const int col_a = (g8 >> 1) << 2;
    const uint32_t a_frag0 = a_base + (uint32_t)(((wm * 64 + row_a) * LDT + col_a) << 2);
    const int row_b = ((g8 >> 1) << 3) + l8;
    const int col_b = (g8 & 1) << 2;
    const uint32_t b_frag0 = b_base + (uint32_t)(((wn * 32 + row_b) * LDT + col_b) << 2);

    float d[4][4][4];
    #pragma unroll
    for (int i = 0; i < 4; i++)
        #pragma unroll
        for (int j = 0; j < 4; j++)
            #pragma unroll
            for (int q = 0; q < 4; q++)
                d[i][j][q] = 0.f;

    auto load_stage = [&](int kt, int buf) {
        int kk = kt * BK;
        const float* __restrict__ A  = (HAS_A2 && kk >= K) ? A2g : A1g;
        const float* __restrict__ WT = (HAS_A2 && kk >= K) ? W2g : W1g;
        const int k0 = HAS_A2 ? (kk & (K - 1)) : kk;
        uint32_t ab = a_base + (uint32_t)(buf * TILE_B);
        uint32_t bb = b_base + (uint32_t)(buf * TILE_B);
        #pragma unroll
        for (int u = 0; u < 4; u++) {
            int r  = ar + u * 32;
            int gr = row0 + r;
            int gc = gr < M ? gr : (M - 1);
            cp16(ab + (uint32_t)((r * LDT + ac4) << 2),
                 A + (size_t)gc * K + k0 + ac4, gr < M);
            cp16(bb + (uint32_t)((r * LDT + ac4) << 2),
                 WT + (size_t)(ncol0 + r) * K + k0 + ac4, true);
        }
    };

    load_stage(0, 0);
    asm volatile("cp.async.commit_group;" ::: "memory");
    load_stage(1, 1);
    asm volatile("cp.async.commit_group;" ::: "memory");

    #pragma unroll 1
    for (int kt = 0; kt < NIT; kt++) {
        asm volatile("cp.async.wait_group 1;" ::: "memory");
        __syncthreads();
        if (kt + 2 < NIT) load_stage(kt + 2, (kt + 2) % ST);
        asm volatile("cp.async.commit_group;" ::: "memory");

        const int buf = kt % ST;
        const uint32_t af_base = a_frag0 + (uint32_t)(buf * TILE_B);
        const uint32_t bf_base = b_frag0 + (uint32_t)(buf * TILE_B);

        #pragma unroll
        for (int ks = 0; ks < 4; ks++) {
            uint32_t af[4][4];
            #pragma unroll
            for (int i = 0; i < 4; i++)
                ldsm4(af[i][0], af[i][1], af[i][2], af[i][3],
                      af_base + (uint32_t)(i * 16 * LDT * 4 + ks * 32));
            uint32_t bf[2][4];
            ldsm4(bf[0][0], bf[0][1], bf[0][2], bf[0][3],
                  bf_base + (uint32_t)(ks * 32));
            ldsm4(bf[1][0], bf[1][1], bf[1][2], bf[1][3],
                  bf_base + (uint32_t)(16 * LDT * 4 + ks * 32));
            #pragma unroll
            for (int i = 0; i < 4; i++) {
                mma_tf32(d[i][0][0], d[i][0][1], d[i][0][2], d[i][0][3],
                         af[i][0], af[i][1], af[i][2], af[i][3], bf[0][0], bf[0][1]);
                mma_tf32(d[i][1][0], d[i][1][1], d[i][1][2], d[i][1][3],
                         af[i][0], af[i][1], af[i][2], af[i][3], bf[0][2], bf[0][3]);
                mma_tf32(d[i][2][0], d[i][2][1], d[i][2][2], d[i][2][3],
                         af[i][0], af[i][1], af[i][2], af[i][3], bf[1][0], bf[1][1]);
                mma_tf32(d[i][3][0], d[i][3][1], d[i][3][2], d[i][3][3],
                         af[i][0], af[i][1], af[i][2], af[i][3], bf[1][2], bf[1][3]);
            }
        }
    }

    #pragma unroll
    for (int j = 0; j < 4; j++) {
        float2 b = *reinterpret_cast<const float2*>(bias + ncol0 + wn * 32 + j * 8 + 2 * lr);
        #pragma unroll
        for (int i = 0; i < 4; i++) {
            d[i][j][0] += b.x; d[i][j][1] += b.y;
            d[i][j][2] += b.x; d[i][j][3] += b.y;
        }
    }

    const int cbase = ncol0 + wn * 32;
    #pragma unroll
    for (int i = 0; i < 4; i++) {
        #pragma unroll
        for (int rr = 0; rr < 2; rr++) {
            int gr = row0 + wm * 64 + i * 16 + lq + rr * 8;
            if (gr < M) {
                #pragma unroll
                for (int j = 0; j < 4; j++) {
                    float2 v;
                    if (EPI == 0) {
                        v.x = to_tf32(gelu_f(d[i][j][rr * 2 + 0]));
                        v.y = to_tf32(gelu_f(d[i][j][rr * 2 + 1]));
                    } else {
                        v.x = d[i][j][rr * 2 + 0];
                        v.y = d[i][j][rr * 2 + 1];
                    }
                    *reinterpret_cast<float2*>(
                        C + (size_t)gr * HDIM + cbase + j * 8 + 2 * lr) = v;
                }
            }
        }
    }
}

// ---------------------------------------------------------------------------
// kernel_launch
// ---------------------------------------------------------------------------
extern "C" void kernel_launch(void* const* d_in, const int* in_sizes, int n_in,
                              void* d_out, int out_size)
{
    const float* x_user    = (const float*)d_in[0];
    const float* x_item    = (const float*)d_in[1];
    const int*   ei_ui_src = (const int*)  d_in[2];
    const int*   ei_ui_dst = (const int*)  d_in[3];
    const int*   ei_iu_src = (const int*)  d_in[4];
    const int*   ei_iu_dst = (const int*)  d_in[5];
    const float* lin_user_W = (const float*)d_in[6];
    const float* lin_user_b = (const float*)d_in[7];
    const float* lin_item_W = (const float*)d_in[8];
    const float* lin_item_b = (const float*)d_in[9];
    const float* c0_ui_Wl = (const float*)d_in[10];
    const float* c0_ui_bl = (const float*)d_in[11];
    const float* c0_ui_Wr = (const float*)d_in[12];
    const float* c0_iu_Wl = (const float*)d_in[13];
    const float* c0_iu_bl = (const float*)d_in[14];
    const float* c0_iu_Wr = (const float*)d_in[15];
    const float* c1_ui_Wl = (const float*)d_in[16];
    const float* c1_ui_bl = (const float*)d_in[17];
    const float* c1_ui_Wr = (const float*)d_in[18];
    const float* c1_iu_Wl = (const float*)d_in[19];
    const float* c1_iu_bl = (const float*)d_in[20];
    const float* c1_iu_Wr = (const float*)d_in[21];
    const float* out_user_W = (const float*)d_in[22];
    const float* out_user_b = (const float*)d_in[23];
    const float* out_item_W = (const float*)d_in[24];
    const float* out_item_b = (const float*)d_in[25];
    const float* ln_user_g  = (const float*)d_in[26];
    const float* ln_user_b2 = (const float*)d_in[27];
    const float* ln_item_g  = (const float*)d_in[28];
    const float* ln_item_b2 = (const float*)d_in[29];

    float* out = (float*)d_out;
    const int nE = in_sizes[2];
    const int M  = NNODE;

    float *hu, *hi, *tu, *ti, *agg, *xu, *xi, *wts;
    int *deg, *off, *cur, *csr, *bsum, *bpre;
    cudaGetSymbolAddress((void**)&hu,  g_hu);
    cudaGetSymbolAddress((void**)&hi,  g_hi);
    cudaGetSymbolAddress((void**)&tu,  g_tu);
    cudaGetSymbolAddress((void**)&ti,  g_ti);
    cudaGetSymbolAddress((void**)&agg, g_agg);
    cudaGetSymbolAddress((void**)&deg, g_deg);
    cudaGetSymbolAddress((void**)&off, g_off);
    cudaGetSymbolAddress((void**)&cur, g_cur);
    cudaGetSymbolAddress((void**)&csr, g_csr);
    cudaGetSymbolAddress((void**)&bsum, g_bsum);
    cudaGetSymbolAddress((void**)&bpre, g_bpre);
    cudaGetSymbolAddress((void**)&xu,  g_xu);
    cudaGetSymbolAddress((void**)&xi,  g_xi);
    cudaGetSymbolAddress((void**)&wts, g_wts);

    float* agg0 = agg;
    float* agg1 = agg + (size_t)M * HDIM;
    int *deg0 = deg,     *deg1 = deg + M;
    int *off0 = off,     *off1 = off + M;
    int *cur0 = cur,     *cur1 = cur + M;
    int *csr0 = csr,     *csr1 = csr + EDGES;

    float* w_lin_u = wts;
    float* w_lin_i = w_lin_u + 32768;
    float* w_c[8];
    w_c[0] = w_lin_i + 32768;
    for (int i = 1; i < 8; i++) w_c[i] = w_c[i - 1] + 65536;
    float* w_out_u = w_c[7] + 65536;
    float* w_out_i = w_out_u + 65536;

    TPack tp;
    const float* twsrc[NTW] = {
        lin_user_W, lin_item_W,
        c0_ui_Wl, c0_ui_Wr, c0_iu_Wl, c0_iu_Wr,
        c1_ui_Wl, c1_ui_Wr, c1_iu_Wl, c1_iu_Wr,
        out_user_W, out_item_W };
    float* twdst[NTW] = {
        w_lin_u, w_lin_i,
        w_c[0], w_c[1], w_c[2], w_c[3], w_c[4], w_c[5], w_c[6], w_c[7],
        w_out_u, w_out_i };
    int twK[NTW] = { DIN, DIN, HDIM, HDIM, HDIM, HDIM, HDIM, HDIM, HDIM, HDIM, HDIM, HDIM };
    for (int i = 0; i < NTW; i++) { tp.src[i] = twsrc[i]; tp.dst[i] = twdst[i]; tp.K[i] = twK[i]; }

    XPack xp;
    xp.src[0] = x_user; xp.dst[0] = xu; xp.n[0] = NNODE * DIN;
    xp.src[1] = x_item; xp.dst[1] = xi; xp.n[1] = NNODE * DIN;

    EdgePair ep;
    ep.src[0] = ei_ui_src; ep.src[1] = ei_iu_src;
    ep.dst[0] = ei_ui_dst; ep.dst[1] = ei_iu_dst;
    ep.deg[0] = deg0; ep.deg[1] = deg1;
    ep.off[0] = off0; ep.off[1] = off1;
    ep.cur[0] = cur0; ep.cur[1] = cur1;
    ep.csr[0] = csr0; ep.csr[1] = csr1;

    dim3 blk(256);
    dim3 grid_gemm(2, (M + BM - 1) / BM, 2);   // x = ncol (fast) for L2 A-reuse
    dim3 grid_edge((nE + 255) / 256, 2);
    dim3 grid_scan(NB, 2);
    dim3 grid_agg((M + 7) / 8, 2, 2);
    dim3 grid_ln((M + 7) / 8, 2);
    dim3 grid_cvx(2048, 2);
    dim3 grid_cvw(64, NTW);

    auto agg_pair = [&](const float* h0, const float* h1) {
        AggPair ap;
        ap.h[0] = h0;   ap.h[1] = h1;
        ap.csr[0] = csr0; ap.csr[1] = csr1;
        ap.off[0] = off0; ap.off[1] = off1;
        ap.deg[0] = deg0; ap.deg[1] = deg1;
        ap.agg[0] = agg0; ap.agg[1] = agg1;
        agg_pair_kernel<<<grid_agg, blk>>>(ap, M);
    };
    auto sage_pair = [&](const float* a1_0, const float* a2_0, float* wl0, float* wr0,
                         const float* bl0, float* c_0,
                         const float* a1_1, const float* a2_1, float* wl1, float* wr1,
                         const float* bl1, float* c_1) {
        GemmPair gp;
        gp.A1[0] = a1_0; gp.A2[0] = a2_0; gp.W1[0] = wl0; gp.W2[0] = wr0;
        gp.bias[0] = bl0; gp.C[0] = c_0;
        gp.A1[1] = a1_1; gp.A2[1] = a2_1; gp.W1[1] = wl1; gp.W2[1] = wr1;
        gp.bias[1] = bl1; gp.C[1] = c_1;
        gemm_pair<HDIM, true, 0><<<grid_gemm, blk>>>(gp, M);
    };

    /* memset  */ cudaMemsetAsync(deg, 0, 2 * M * sizeof(int));
    /* k1 */ cvt_x_kernel<<<grid_cvx, blk>>>(xp);
    /* k2 */ cvt_wT_kernel<<<grid_cvw, blk>>>(tp);
    /* k3 */ deg_pair_kernel<<<grid_edge, blk>>>(ep, nE);

    /* k4: input projections (pair) — PROFILED SLOT */
    {
        GemmPair gp;
        gp.A1[0] = xu; gp.A2[0] = nullptr; gp.W1[0] = w_lin_u; gp.W2[0] = nullptr;
        gp.bias[0] = lin_user_b; gp.C[0] = hu;
        gp.A1[1] = xi; gp.A2[1] = nullptr; gp.W1[1] = w_lin_i; gp.W2[1] = nullptr;
        gp.bias[1] = lin_item_b; gp.C[1] = hi;
        gemm_pair<DIN, false, 0><<<grid_gemm, blk>>>(gp, M);
    }

    /* k5-7: multi-block scan */
    bsum_pair_kernel<<<grid_scan, blk>>>(ep, M, bsum);
    bscan_kernel<<<1, 32>>>(bsum, bpre);
    addoff_pair_kernel<<<dim3(NB, 2), 1024>>>(ep, M, bpre);
    /* k8 */ csr_pair_kernel<<<grid_edge, blk>>>(ep, nE);

    /* k9: layer-0 aggregation (pair) */
    agg_pair(hu, hi);
    /* k10: layer-0 SAGE gemms (pair): ti, tu */
    sage_pair(agg0, hi, w_c[0], w_c[1], c0_ui_bl, ti,
              agg1, hu, w_c[2], w_c[3], c0_iu_bl, tu);

    /* k11: layer-1 aggregation (pair) */
    agg_pair(tu, ti);
    /* k12: layer-1 SAGE gemms (pair): hi, hu */
    sage_pair(agg0, ti, w_c[4], w_c[5], c1_ui_bl, hi,
              agg1, tu, w_c[6], w_c[7], c1_iu_bl, hu);

    /* k13: heads (pair) */
    {
        GemmPair gp;
        gp.A1[0] = hu; gp.A2[0] = nullptr; gp.W1[0] = w_out_u; gp.W2[0] = nullptr;
        gp.bias[0] = out_user_b; gp.C[0] = out;
        gp.A1[1] = hi; gp.A2[1] = nullptr; gp.W1[1] = w_out_i; gp.W2[1] = nullptr;
        gp.bias[1] = out_item_b; gp.C[1] = out + (size_t)M * HDIM;
        gemm_pair<HDIM, false, 1><<<grid_gemm, blk>>>(gp, M);
    }
    /* k14: LayerNorm (pair) */
    {
        LnPair lp;
        lp.x[0] = out;                     lp.x[1] = out + (size_t)M * HDIM;
        lp.g[0] = ln_user_g;               lp.g[1] = ln_item_g;
        lp.b[0] = ln_user_b2;              lp.b[1] = ln_item_b2;
        ln_pair_kernel<<<grid_ln, blk>>>(lp, M);
    }
}